// round 9
// baseline (speedup 1.0000x reference)
#include <cuda_runtime.h>
#include <cuda_fp16.h>
#include <math.h>
#include <stdint.h>

// ---------------------------------------------------------------------------
//   x: (2,16,1,128,128)
//   block0: 1->64,  128x128 -> pool -> 64x64   (SIMT)
//   block1: 64->128, 64x64  -> pool -> 32x32   (3xFP16 MMA GEMM)
//   block2: 128->256,32x32  -> pool -> 16x16   (3xFP16 MMA GEMM)
//   ConvLSTM x2: cin=512, cout=1024, 3x3, 16x16 (3xFP16 MMA GEMM,
//                B staged on the fly from plain [c][pos] fp16 hi/lo arrays)
//   out: z_seq (2,16,256,16,16) ++ z_last (2,256,16,16)
// 3xFP16 error-compensated mma.sync:  D += Ah*Bh + Ah*Bl + Al*Bh
// ---------------------------------------------------------------------------

#define CHW2 65536          // 256*16*16

typedef unsigned long long ull;

// ============================ PTX helpers ==================================
__device__ __forceinline__ uint32_t smem_u32(const void* p) {
    uint32_t a;
    asm("{ .reg .u64 t; cvta.to.shared.u64 t, %1; cvt.u32.u64 %0, t; }" : "=r"(a) : "l"(p));
    return a;
}
__device__ __forceinline__ void ldm_x4(uint32_t* r, uint32_t addr) {
    asm volatile("ldmatrix.sync.aligned.m8n8.x4.shared.b16 {%0,%1,%2,%3}, [%4];"
        : "=r"(r[0]), "=r"(r[1]), "=r"(r[2]), "=r"(r[3]) : "r"(addr));
}
__device__ __forceinline__ void ldm_x4t(uint32_t* r, uint32_t addr) {
    asm volatile("ldmatrix.sync.aligned.m8n8.x4.trans.shared.b16 {%0,%1,%2,%3}, [%4];"
        : "=r"(r[0]), "=r"(r[1]), "=r"(r[2]), "=r"(r[3]) : "r"(addr));
}
__device__ __forceinline__ void mma16816(float* d, const uint32_t* a, const uint32_t* b) {
    asm volatile(
        "mma.sync.aligned.m16n8k16.row.col.f32.f16.f16.f32 "
        "{%0,%1,%2,%3}, {%4,%5,%6,%7}, {%8,%9}, {%0,%1,%2,%3};"
        : "+f"(d[0]), "+f"(d[1]), "+f"(d[2]), "+f"(d[3])
        : "r"(a[0]), "r"(a[1]), "r"(a[2]), "r"(a[3]), "r"(b[0]), "r"(b[1]));
}
__device__ __forceinline__ void cp16(uint32_t sdst, const void* gsrc) {
    asm volatile("cp.async.cg.shared.global [%0], [%1], 16;" :: "r"(sdst), "l"(gsrc));
}
__device__ __forceinline__ void cp_commit() { asm volatile("cp.async.commit_group;"); }
template <int N> __device__ __forceinline__ void cp_wait() {
    asm volatile("cp.async.wait_group %0;" :: "n"(N));
}
__device__ __forceinline__ float sigmoidf_(float x) { return 1.0f / (1.0f + expf(-x)); }

// ---------------------------------------------------------------------------
// Scratch
// ---------------------------------------------------------------------------
__device__ __align__(256) float  g_f0[32 * 64 * 64 * 64];
__device__ __align__(256) float  g_f1[32 * 128 * 32 * 32];
__device__ __align__(256) float  g_f2[32 * 256 * 16 * 16];
__device__ __align__(256) float  g_pre[32 * 128 * 64 * 64];   // pre-pool conv output (reused)
__device__ __align__(256) __half g_wc1h[36 * 128 * 16];
__device__ __align__(256) __half g_wc1l[36 * 128 * 16];
__device__ __align__(256) __half g_wc2h[72 * 256 * 16];
__device__ __align__(256) __half g_wc2l[72 * 256 * 16];
__device__ __align__(256) __half g_wph[2 * 288 * 1024 * 16];  // lstm weights hi
__device__ __align__(256) __half g_wpl[2 * 288 * 1024 * 16];
// plain feature arrays, [slab][c][pos] with slab = frame index
__device__ __align__(256) __half g_x0h[32 * CHW2];            // L0 x, slab = b*16+t
__device__ __align__(256) __half g_x0l[32 * CHW2];
__device__ __align__(256) __half g_x1h[32 * CHW2];            // L1 x (=L0 h), slab = t*2+b
__device__ __align__(256) __half g_x1l[32 * CHW2];
__device__ __align__(256) __half g_hh[2 * CHW2];              // current h, slab = b
__device__ __align__(256) __half g_hl[2 * CHW2];
__device__ __align__(256) float  g_c[2 * CHW2];
__device__ __align__(256) float  g_zp[4 * 2 * 1024 * 256];

// ---------------------------------------------------------------------------
// LSTM weight prepack
// ---------------------------------------------------------------------------
__global__ void __launch_bounds__(256) prepack_w(const float* __restrict__ lw, int layer)
{
    int idx = blockIdx.x * 256 + threadIdx.x;  // 4718592
    int u  = idx & 15;
    int oc = (idx >> 4) & 1023;
    int G  = idx >> 14;
    int k  = G * 16 + u;
    int s  = k >> 9;
    int c  = k & 511;
    float w = lw[((size_t)oc * 512 + c) * 9 + s];
    __half hi = __float2half(w);
    size_t o = (size_t)layer * 4718592 + idx;
    g_wph[o] = hi;
    g_wpl[o] = __float2half(w - __half2float(hi));
}

// ---------------------------------------------------------------------------
// CNN conv weight prepack
// ---------------------------------------------------------------------------
template <int CIN, int OCTOT>
__global__ void __launch_bounds__(256) prepack_cw(
    const float* __restrict__ w, __half* __restrict__ outh, __half* __restrict__ outl)
{
    constexpr int CPG = CIN / 16;
    int idx = blockIdx.x * 256 + threadIdx.x;
    int u  = idx & 15;
    int oc = (idx >> 4) % OCTOT;
    int G  = (idx >> 4) / OCTOT;
    int s  = G / CPG;
    int c  = (G % CPG) * 16 + u;
    float val = w[((size_t)oc * CIN + c) * 9 + s];
    __half hi = __float2half(val);
    outh[idx] = hi;
    outl[idx] = __float2half(val - __half2float(hi));
}

// ---------------------------------------------------------------------------
// Convert CNN features fp32 -> plain fp16 hi/lo (2,097,152 elements)
// ---------------------------------------------------------------------------
__global__ void __launch_bounds__(256) cvt_f2()
{
    int idx = blockIdx.x * 256 + threadIdx.x;
    float val = g_f2[idx];
    __half hi = __float2half(val);
    g_x0h[idx] = hi;
    g_x0l[idx] = __float2half(val - __half2float(hi));
}

// ---------------------------------------------------------------------------
// Block 0: 1 input channel. One thread per pooled output.
// ---------------------------------------------------------------------------
__global__ void __launch_bounds__(256) conv0_pool(
    const float* __restrict__ x, const float* __restrict__ w,
    const float* __restrict__ bias, const float* __restrict__ g,
    const float* __restrict__ be, const float* __restrict__ m,
    const float* __restrict__ v)
{
    int idx = blockIdx.x * 256 + threadIdx.x;   // 8388608
    int pw = idx & 63;
    int ph = (idx >> 6) & 63;
    int oc = (idx >> 12) & 63;
    int n  = idx >> 18;

    float wr[9];
#pragma unroll
    for (int k = 0; k < 9; k++) wr[k] = w[oc * 9 + k];
    float s  = g[oc] * rsqrtf(v[oc] + 1e-5f);
    float cb = (bias[oc] - m[oc]) * s + be[oc];

    const float* xi = x + n * 16384;
    float mx = -1e30f;
#pragma unroll
    for (int dy0 = 0; dy0 < 2; dy0++) {
#pragma unroll
        for (int dx0 = 0; dx0 < 2; dx0++) {
            int oy = 2 * ph + dy0, ox = 2 * pw + dx0;
            float sum = 0.f;
#pragma unroll
            for (int ky = 0; ky < 3; ky++) {
                int iy = oy - 1 + ky;
                if (iy < 0 || iy >= 128) continue;
#pragma unroll
                for (int kx = 0; kx < 3; kx++) {
                    int ix = ox - 1 + kx;
                    if (ix < 0 || ix >= 128) continue;
                    sum = fmaf(xi[iy * 128 + ix], wr[ky * 3 + kx], sum);
                }
            }
            float y = fmaxf(fmaf(sum, s, cb), 0.f);
            mx = fmaxf(mx, y);
        }
    }
    g_f0[idx] = mx;
}

// ---------------------------------------------------------------------------
// CNN conv via 3xFP16 mma.sync GEMM, on-the-fly shifted im2col from fp32.
// ---------------------------------------------------------------------------
template <int CIN, int S, int OCTOT>
__global__ void __launch_bounds__(256) conv_mma(
    const float* __restrict__ in,
    const __half* __restrict__ wph, const __half* __restrict__ wpl,
    const float* __restrict__ bias, const float* __restrict__ g,
    const float* __restrict__ be, const float* __restrict__ m,
    const float* __restrict__ v, float* __restrict__ pre)
{
    constexpr int NPOS = S * S;
    constexpr int CPG  = CIN / 16;
    constexpr int NG   = 9 * CPG;
    constexpr int LOGS = (S == 64) ? 6 : 5;

    __shared__ __align__(16) __half Ah[2][128 * 24];
    __shared__ __align__(16) __half Al[2][128 * 24];
    __shared__ __align__(16) __half Bh[2][16 * 136];
    __shared__ __align__(16) __half Bl[2][16 * 136];
    __shared__ float ssc[128], sbi[128];

    int tid = threadIdx.x, lane = tid & 31, wid = tid >> 5;
    int wm = wid & 3, wn = wid >> 2;
    int ntile = blockIdx.x;
    int ocb   = blockIdx.y * 128;
    int frame = blockIdx.z;

    if (tid < 128) {
        int oc = ocb + tid;
        float s_ = g[oc] * rsqrtf(v[oc] + 1e-5f);
        ssc[tid] = s_;
        sbi[tid] = (bias[oc] - m[oc]) * s_ + be[oc];
    }

    int arow = tid >> 1, au = tid & 1;
    uint32_t ao = arow * 48 + au * 16;
    uint32_t ah_dst[2] = { smem_u32(&Ah[0][0]) + ao, smem_u32(&Ah[1][0]) + ao };
    uint32_t al_dst[2] = { smem_u32(&Al[0][0]) + ao, smem_u32(&Al[1][0]) + ao };
    size_t a_off_elem = (size_t)(ocb + arow) * 16 + au * 8;

    int bk = tid >> 4, bn = tid & 15;
    int nbase = ntile * 128 + bn * 8;

    float breg[8];
    auto prefetchB = [&](int G) {
        int s = G / CPG, q = G - s * CPG;
        int dy = s / 3 - 1, dx = s % 3 - 1;
        const float* src = in + ((size_t)frame * CIN + q * 16 + bk) * NPOS;
#pragma unroll
        for (int j = 0; j < 8; j++) {
            int pos = nbase + j;
            int y = pos >> LOGS, x = pos & (S - 1);
            int iy = y + dy, ix = x + dx;
            breg[j] = (iy >= 0 && iy < S && ix >= 0 && ix < S) ? src[iy * S + ix] : 0.f;
        }
    };
    auto stsB = [&](int buf) {
        __half hv[8], lv[8];
#pragma unroll
        for (int j = 0; j < 8; j++) {
            hv[j] = __float2half(breg[j]);
            lv[j] = __float2half(breg[j] - __half2float(hv[j]));
        }
        *(uint4*)&Bh[buf][bk * 136 + bn * 8] = *(uint4*)hv;
        *(uint4*)&Bl[buf][bk * 136 + bn * 8] = *(uint4*)lv;
    };
    auto cpA = [&](int G, int buf) {
        cp16(ah_dst[buf], wph + (size_t)G * (OCTOT * 16) + a_off_elem);
        cp16(al_dst[buf], wpl + (size_t)G * (OCTOT * 16) + a_off_elem);
        cp_commit();
    };

    int quad = lane >> 3, l7 = lane & 7;
    uint32_t a_off[2], b_off[4];
    {
        int rsub = ((quad & 1) << 3) + l7;
        int ksub = (quad >> 1) << 4;
#pragma unroll
        for (int mi = 0; mi < 2; mi++)
            a_off[mi] = (uint32_t)((wm * 32 + mi * 16 + rsub) * 48 + ksub);
        int krow = ((quad & 1) << 3) + l7;
        int nsub = (quad >> 1) << 3;
#pragma unroll
        for (int ni2 = 0; ni2 < 4; ni2++)
            b_off[ni2] = (uint32_t)(krow * 272 + (wn * 64 + ni2 * 16 + nsub) * 2);
    }
    uint32_t ahb[2] = { smem_u32(&Ah[0][0]), smem_u32(&Ah[1][0]) };
    uint32_t alb[2] = { smem_u32(&Al[0][0]), smem_u32(&Al[1][0]) };
    uint32_t bhb[2] = { smem_u32(&Bh[0][0]), smem_u32(&Bh[1][0]) };
    uint32_t blb[2] = { smem_u32(&Bl[0][0]), smem_u32(&Bl[1][0]) };

    float acc[2][8][4];
#pragma unroll
    for (int mi = 0; mi < 2; mi++)
#pragma unroll
        for (int ni = 0; ni < 8; ni++)
#pragma unroll
            for (int q = 0; q < 4; q++) acc[mi][ni][q] = 0.f;

    prefetchB(0); stsB(0); cpA(0, 0);
    prefetchB(1); stsB(1); cpA(1, 1);
    if (NG > 2) prefetchB(2);

    for (int j = 0; j < NG; j++) {
        if (j < NG - 1) cp_wait<1>(); else cp_wait<0>();
        __syncthreads();

        int buf = j & 1;
        uint32_t ah[2][4], al[2][4], bh_[4][4], bl_[4][4];
#pragma unroll
        for (int mi = 0; mi < 2; mi++) {
            ldm_x4(ah[mi], ahb[buf] + a_off[mi]);
            ldm_x4(al[mi], alb[buf] + a_off[mi]);
        }
#pragma unroll
        for (int ni2 = 0; ni2 < 4; ni2++) {
            ldm_x4t(bh_[ni2], bhb[buf] + b_off[ni2]);
            ldm_x4t(bl_[ni2], blb[buf] + b_off[ni2]);
        }
#pragma unroll
        for (int mi = 0; mi < 2; mi++)
#pragma unroll
            for (int ni = 0; ni < 8; ni++) {
                const uint32_t* bhf = &bh_[ni >> 1][(ni & 1) * 2];
                const uint32_t* blf = &bl_[ni >> 1][(ni & 1) * 2];
                mma16816(acc[mi][ni], ah[mi], bhf);
                mma16816(acc[mi][ni], ah[mi], blf);
                mma16816(acc[mi][ni], al[mi], bhf);
            }
        __syncthreads();

        if (j + 2 < NG) {
            stsB(buf);
            cpA(j + 2, buf);
            if (j + 3 < NG) prefetchB(j + 3);
        }
    }

    int gq = lane >> 2, tq = lane & 3;
    int row0 = wm * 32 + gq;
    int colb = ntile * 128 + wn * 64 + 2 * tq;
#pragma unroll
    for (int mi = 0; mi < 2; mi++)
#pragma unroll
        for (int ni = 0; ni < 8; ni++) {
            int r0 = row0 + mi * 16;
            int col = colb + ni * 8;
#pragma unroll
            for (int h = 0; h < 2; h++) {
                int r = r0 + h * 8;
                float sc = ssc[r], sh = sbi[r];
                float v0 = fmaxf(fmaf(acc[mi][ni][2 * h],     sc, sh), 0.f);
                float v1 = fmaxf(fmaf(acc[mi][ni][2 * h + 1], sc, sh), 0.f);
                *(float2*)(pre + ((size_t)frame * OCTOT + ocb + r) * NPOS + col)
                    = make_float2(v0, v1);
            }
        }
}

// ---------------------------------------------------------------------------
// 2x2 maxpool
// ---------------------------------------------------------------------------
template <int OC, int S>
__global__ void __launch_bounds__(256) pool2(const float* __restrict__ pre,
                                             float* __restrict__ out)
{
    constexpr int HP = S / 2;
    int idx = blockIdx.x * 256 + threadIdx.x;
    int pw = idx % HP;
    int t1 = idx / HP;
    int ph = t1 % HP;
    int t2 = t1 / HP;
    const float* p = pre + (size_t)t2 * S * S + (2 * ph) * S + 2 * pw;
    float a = p[0], b = p[1], c = p[S], d = p[S + 1];
    out[idx] = fmaxf(fmaxf(a, b), fmaxf(c, d));
}

// ---------------------------------------------------------------------------
// ConvLSTM gate conv via 3xFP16 mma.sync GEMM.
// B staged on the fly from plain fp16 hi/lo arrays with shift masking.
// Grid: (8 mtiles, 4 = ntile+2*b, 4 ksplits), 256 threads.
// ---------------------------------------------------------------------------
__global__ void __launch_bounds__(256) lstm_mma(
    const __half* __restrict__ wph, const __half* __restrict__ wpl,
    const __half* __restrict__ xh, const __half* __restrict__ xl,
    int xbstride)
{
    __shared__ __align__(16) __half Ah[2][128 * 24];
    __shared__ __align__(16) __half Al[2][128 * 24];
    __shared__ __align__(16) __half Bh[2][16 * 136];
    __shared__ __align__(16) __half Bl[2][16 * 136];

    int tid  = threadIdx.x;
    int lane = tid & 31;
    int wid  = tid >> 5;
    int wm = wid & 3, wn = wid >> 2;

    int mtile = blockIdx.x;
    int ntile = blockIdx.y & 1;
    int b     = blockIdx.y >> 1;
    int split = blockIdx.z;
    int ocb   = mtile * 128;

    const __half* xhb = xh + (size_t)b * xbstride;
    const __half* xlb = xl + (size_t)b * xbstride;
    const __half* hhb = g_hh + (size_t)b * CHW2;
    const __half* hlb = g_hl + (size_t)b * CHW2;

    int arow = tid >> 1, au = tid & 1;
    uint32_t ao = arow * 48 + au * 16;
    uint32_t ah_dst[2] = { smem_u32(&Ah[0][0]) + ao, smem_u32(&Ah[1][0]) + ao };
    uint32_t al_dst[2] = { smem_u32(&Al[0][0]) + ao, smem_u32(&Al[1][0]) + ao };
    size_t a_off_elem = (size_t)(arow + ocb) * 16 + au * 8;

    int bk = tid >> 4, bn = tid & 15;
    int pos0 = ntile * 128 + bn * 8;
    int py = pos0 >> 4, px0 = pos0 & 15;

    __half hv[8], lv[8];
    auto prefetchB = [&](int j) {
        int Gg = split * 72 + j;
        int s  = Gg >> 5;
        int c0 = (Gg & 31) << 4;
        int dy = s / 3 - 1, dx = s % 3 - 1;
        bool isx = (c0 < 256);
        int chl = (isx ? c0 : c0 - 256) + bk;
        const __half* sh = (isx ? xhb : hhb) + chl * 256;
        const __half* sl = (isx ? xlb : hlb) + chl * 256;
        int iy = py + dy;
        bool rowok = (iy >= 0 && iy < 16);
        const __half* shr = sh + iy * 16;
        const __half* slr = sl + iy * 16;
        __half z = __float2half(0.f);
#pragma unroll
        for (int j2 = 0; j2 < 8; j2++) {
            int ix = px0 + j2 + dx;
            bool ok = rowok && (ix >= 0) && (ix < 16);
            hv[j2] = ok ? shr[ix] : z;
            lv[j2] = ok ? slr[ix] : z;
        }
    };
    auto stsB = [&](int buf) {
        *(uint4*)&Bh[buf][bk * 136 + bn * 8] = *(uint4*)hv;
        *(uint4*)&Bl[buf][bk * 136 + bn * 8] = *(uint4*)lv;
    };
    auto cpA = [&](int j, int buf) {
        int Gg = split * 72 + j;
        cp16(ah_dst[buf], wph + (size_t)Gg * 16384 + a_off_elem);
        cp16(al_dst[buf], wpl + (size_t)Gg * 16384 + a_off_elem);
        cp_commit();
    };

    int quad = lane >> 3, l7 = lane & 7;
    uint32_t a_off[2], b_off[4];
    {
        int rsub = ((quad & 1) << 3) + l7;
        int ksub = (quad >> 1) << 4;
#pragma unroll
        for (int mi = 0; mi < 2; mi++)
            a_off[mi] = (uint32_t)((wm * 32 + mi * 16 + rsub) * 48 + ksub);
        int krow = ((quad & 1) << 3) + l7;
        int nsub = (quad >> 1) << 3;
#pragma unroll
        for (int ni2 = 0; ni2 < 4; ni2++)
            b_off[ni2] = (uint32_t)(krow * 272 + (wn * 64 + ni2 * 16 + nsub) * 2);
    }
    uint32_t ahb[2] = { smem_u32(&Ah[0][0]), smem_u32(&Ah[1][0]) };
    uint32_t alb[2] = { smem_u32(&Al[0][0]), smem_u32(&Al[1][0]) };
    uint32_t bhb[2] = { smem_u32(&Bh[0][0]), smem_u32(&Bh[1][0]) };
    uint32_t blb[2] = { smem_u32(&Bl[0][0]), smem_u32(&Bl[1][0]) };

    float acc[2][8][4];
#pragma unroll
    for (int mi = 0; mi < 2; mi++)
#pragma unroll
        for (int ni = 0; ni < 8; ni++)
#pragma unroll
            for (int q = 0; q < 4; q++) acc[mi][ni][q] = 0.f;

    prefetchB(0); stsB(0); cpA(0, 0);
    prefetchB(1); stsB(1); cpA(1, 1);
    prefetchB(2);

    for (int j = 0; j < 72; j++) {
        if (j < 71) cp_wait<1>(); else cp_wait<0>();
        __syncthreads();

        int buf = j & 1;
        uint32_t ah[2][4], al[2][4], bh_[4][4], bl_[4][4];
#pragma unroll
        for (int mi = 0; mi < 2; mi++) {
            ldm_x4(ah[mi], ahb[buf] + a_off[mi]);
            ldm_x4(al[mi], alb[buf] + a_off[mi]);
        }
#pragma unroll
        for (int ni2 = 0; ni2 < 4; ni2++) {
            ldm_x4t(bh_[ni2], bhb[buf] + b_off[ni2]);
            ldm_x4t(bl_[ni2], blb[buf] + b_off[ni2]);
        }
#pragma unroll
        for (int mi = 0; mi < 2; mi++)
#pragma unroll
            for (int ni = 0; ni < 8; ni++) {
                const uint32_t* bhf = &bh_[ni >> 1][(ni & 1) * 2];
                const uint32_t* blf = &bl_[ni >> 1][(ni & 1) * 2];
                mma16816(acc[mi][ni], ah[mi], bhf);
                mma16816(acc[mi][ni], ah[mi], blf);
                mma16816(acc[mi][ni], al[mi], bhf);
            }

        __syncthreads();
        if (j + 2 < 72) {
            stsB(buf);            // hv/lv hold chunk j+2
            cpA(j + 2, buf);
            if (j + 3 < 72) prefetchB(j + 3);
        }
    }

    int gq = lane >> 2, tq = lane & 3;
    float* zbase = g_zp + ((size_t)(split * 2 + b) * 1024) * 256;
    int row0 = ocb + wm * 32 + gq;
    int col0 = ntile * 128 + wn * 64 + 2 * tq;
#pragma unroll
    for (int mi = 0; mi < 2; mi++)
#pragma unroll
        for (int ni = 0; ni < 8; ni++) {
            int r = row0 + mi * 16;
            int cc = col0 + ni * 8;
            *(float2*)(zbase + (size_t)r * 256 + cc)       = make_float2(acc[mi][ni][0], acc[mi][ni][1]);
            *(float2*)(zbase + (size_t)(r + 8) * 256 + cc) = make_float2(acc[mi][ni][2], acc[mi][ni][3]);
        }
}

// ---------------------------------------------------------------------------
// Gates: sum 4 K-split partials + bias, nonlinearities, state update,
// plain contiguous writes of h hi/lo (+ L1 input slab for layer 0).
// ---------------------------------------------------------------------------
__global__ void __launch_bounds__(256) lstm_gates(int t, int layer,
                                                  const float* __restrict__ lb,
                                                  float* __restrict__ out)
{
    int idx = blockIdx.x * 256 + threadIdx.x;  // 131072
    int inner = idx & 65535;
    int b = idx >> 16;
    int c = inner >> 8;
    int pos = inner & 255;

    float zi = lb[c], zf = lb[c + 256], zo = lb[c + 512], zg = lb[c + 768];
#pragma unroll
    for (int s = 0; s < 4; s++) {
        const float* zb = g_zp + ((size_t)s * 2 + b) * 1024 * 256;
        zi += zb[(size_t)(c)       * 256 + pos];
        zf += zb[(size_t)(c + 256) * 256 + pos];
        zo += zb[(size_t)(c + 512) * 256 + pos];
        zg += zb[(size_t)(c + 768) * 256 + pos];
    }

    float cn = sigmoidf_(zf) * g_c[idx] + sigmoidf_(zi) * tanhf(zg);
    float hn = sigmoidf_(zo) * tanhf(cn);
    g_c[idx] = cn;

    __half hh = __float2half(hn);
    __half hl = __float2half(hn - __half2float(hh));
    size_t ho = (size_t)b * CHW2 + inner;
    g_hh[ho] = hh;
    g_hl[ho] = hl;
    if (layer == 0) {
        size_t xo = (size_t)(t * 2 + b) * CHW2 + inner;
        g_x1h[xo] = hh;
        g_x1l[xo] = hl;
    } else {
        out[(size_t)b * 16 * CHW2 + (size_t)t * CHW2 + inner] = hn;
    }
}

// zero c state and plain h arrays (131072 each)
__global__ void __launch_bounds__(256) zero_state()
{
    int idx = blockIdx.x * 256 + threadIdx.x;   // 131072
    g_c[idx] = 0.f;
    g_hh[idx] = __float2half(0.f);
    g_hl[idx] = __float2half(0.f);
}

__global__ void __launch_bounds__(256) copy_last(float* __restrict__ out)
{
    int idx = blockIdx.x * 256 + threadIdx.x;   // 131072
    int inner = idx & 65535;
    int b = idx >> 16;
    out[2097152 + idx] = out[(size_t)b * 16 * CHW2 + 15 * CHW2 + inner];
}

// ---------------------------------------------------------------------------
// Launch sequence (graph-capturable)
// ---------------------------------------------------------------------------
extern "C" void kernel_launch(void* const* d_in, const int* in_sizes, int n_in,
                              void* d_out, int out_size)
{
    const float* x   = (const float*)d_in[0];
    const float* w0  = (const float*)d_in[1];
    const float* b0  = (const float*)d_in[2];
    const float* g0  = (const float*)d_in[3];
    const float* be0 = (const float*)d_in[4];
    const float* m0  = (const float*)d_in[5];
    const float* v0  = (const float*)d_in[6];
    const float* w1  = (const float*)d_in[7];
    const float* b1  = (const float*)d_in[8];
    const float* g1  = (const float*)d_in[9];
    const float* be1 = (const float*)d_in[10];
    const float* m1  = (const float*)d_in[11];
    const float* v1  = (const float*)d_in[12];
    const float* w2  = (const float*)d_in[13];
    const float* b2  = (const float*)d_in[14];
    const float* g2  = (const float*)d_in[15];
    const float* be2 = (const float*)d_in[16];
    const float* m2  = (const float*)d_in[17];
    const float* v2  = (const float*)d_in[18];
    const float* lw0 = (const float*)d_in[19];
    const float* lb0 = (const float*)d_in[20];
    const float* lw1 = (const float*)d_in[21];
    const float* lb1 = (const float*)d_in[22];
    float* out = (float*)d_out;

    float* f0ptr;  cudaGetSymbolAddress((void**)&f0ptr, g_f0);
    float* f1ptr;  cudaGetSymbolAddress((void**)&f1ptr, g_f1);
    float* f2ptr;  cudaGetSymbolAddress((void**)&f2ptr, g_f2);
    float* preptr; cudaGetSymbolAddress((void**)&preptr, g_pre);
    __half* wc1h; cudaGetSymbolAddress((void**)&wc1h, g_wc1h);
    __half* wc1l; cudaGetSymbolAddress((void**)&wc1l, g_wc1l);
    __half* wc2h; cudaGetSymbolAddress((void**)&wc2h, g_wc2h);
    __half* wc2l; cudaGetSymbolAddress((void**)&wc2l, g_wc2l);
    __half* wphptr; cudaGetSymbolAddress((void**)&wphptr, g_wph);
    __half* wplptr; cudaGetSymbolAddress((void**)&wplptr, g_wpl);
    __half* x0hptr; cudaGetSymbolAddress((void**)&x0hptr, g_x0h);
    __half* x0lptr; cudaGetSymbolAddress((void**)&x0lptr, g_x0l);
    __half* x1hptr; cudaGetSymbolAddress((void**)&x1hptr, g_x1h);
    __half* x1lptr; cudaGetSymbolAddress((void**)&x1lptr, g_x1l);

    // weight prepacks
    prepack_w<<<18432, 256>>>(lw0, 0);
    prepack_w<<<18432, 256>>>(lw1, 1);
    prepack_cw<64, 128><<<288, 256>>>(w1, wc1h, wc1l);
    prepack_cw<128, 256><<<1152, 256>>>(w2, wc2h, wc2l);

    // CNN encoder
    conv0_pool<<<32768, 256>>>(x, w0, b0, g0, be0, m0, v0);
    conv_mma<64, 64, 128><<<dim3(32, 1, 32), 256>>>(f0ptr, wc1h, wc1l,
                                                    b1, g1, be1, m1, v1, preptr);
    pool2<128, 64><<<16384, 256>>>(preptr, f1ptr);
    conv_mma<128, 32, 256><<<dim3(8, 2, 32), 256>>>(f1ptr, wc2h, wc2l,
                                                    b2, g2, be2, m2, v2, preptr);
    pool2<256, 32><<<8192, 256>>>(preptr, f2ptr);

    // convert features to plain fp16 hi/lo
    cvt_f2<<<8192, 256>>>();

    // ConvLSTM layer 0: x slab = b*16+t  ->  base + t*CHW2, b-stride 16*CHW2
    zero_state<<<512, 256>>>();
    for (int t = 0; t < 16; t++) {
        lstm_mma<<<dim3(8, 4, 4), 256>>>(wphptr, wplptr,
                                         x0hptr + (size_t)t * CHW2,
                                         x0lptr + (size_t)t * CHW2, 16 * CHW2);
        lstm_gates<<<512, 256>>>(t, 0, lb0, out);
    }

    // ConvLSTM layer 1: x slab = t*2+b  ->  base + t*2*CHW2, b-stride CHW2
    zero_state<<<512, 256>>>();
    for (int t = 0; t < 16; t++) {
        lstm_mma<<<dim3(8, 4, 4), 256>>>(wphptr + (size_t)288 * 1024 * 16,
                                         wplptr + (size_t)288 * 1024 * 16,
                                         x1hptr + (size_t)t * 2 * CHW2,
                                         x1lptr + (size_t)t * 2 * CHW2, CHW2);
        lstm_gates<<<512, 256>>>(t, 1, lb1, out);
    }

    copy_last<<<512, 256>>>(out);
}

// round 10
// speedup vs baseline: 1.2371x; 1.2371x over previous
#include <cuda_runtime.h>
#include <cuda_fp16.h>
#include <math.h>
#include <stdint.h>

// ---------------------------------------------------------------------------
//   block0: 1->64 SIMT; block1/2 + ConvLSTM convs: 3xFP16 mma.sync GEMM
//   (D += Ah*Bh + Ah*Bl + Al*Bh), K staged in 32-wide chunks, double buffer.
// LSTM GEMM: Z_b[1024,256] = W[1024,4608] * B_b[4608,256], k = s*512+c
// ---------------------------------------------------------------------------

#define CHW2 65536          // 256*16*16
#define BHS  589824         // 9*256*256

typedef unsigned long long ull;

// dynamic smem byte offsets (per-kernel identical layout)
//  A bufs: 128 rows x 80B  -> 10240 B each (hi: 0/10240, lo: 20480/30720)
//  B bufs: 32 rows x 272B  ->  8704 B each (hi: 40960/49664, lo: 58368/67072)
#define SM_TOTAL 75776

// ============================ PTX helpers ==================================
__device__ __forceinline__ uint32_t smem_u32(const void* p) {
    uint32_t a;
    asm("{ .reg .u64 t; cvta.to.shared.u64 t, %1; cvt.u32.u64 %0, t; }" : "=r"(a) : "l"(p));
    return a;
}
__device__ __forceinline__ void ldm_x4(uint32_t* r, uint32_t addr) {
    asm volatile("ldmatrix.sync.aligned.m8n8.x4.shared.b16 {%0,%1,%2,%3}, [%4];"
        : "=r"(r[0]), "=r"(r[1]), "=r"(r[2]), "=r"(r[3]) : "r"(addr));
}
__device__ __forceinline__ void ldm_x4t(uint32_t* r, uint32_t addr) {
    asm volatile("ldmatrix.sync.aligned.m8n8.x4.trans.shared.b16 {%0,%1,%2,%3}, [%4];"
        : "=r"(r[0]), "=r"(r[1]), "=r"(r[2]), "=r"(r[3]) : "r"(addr));
}
__device__ __forceinline__ void mma16816(float* d, const uint32_t* a, const uint32_t* b) {
    asm volatile(
        "mma.sync.aligned.m16n8k16.row.col.f32.f16.f16.f32 "
        "{%0,%1,%2,%3}, {%4,%5,%6,%7}, {%8,%9}, {%0,%1,%2,%3};"
        : "+f"(d[0]), "+f"(d[1]), "+f"(d[2]), "+f"(d[3])
        : "r"(a[0]), "r"(a[1]), "r"(a[2]), "r"(a[3]), "r"(b[0]), "r"(b[1]));
}
__device__ __forceinline__ void cp16(uint32_t sdst, const void* gsrc) {
    asm volatile("cp.async.cg.shared.global [%0], [%1], 16;" :: "r"(sdst), "l"(gsrc));
}
__device__ __forceinline__ void cp_commit() { asm volatile("cp.async.commit_group;"); }
template <int N> __device__ __forceinline__ void cp_wait() {
    asm volatile("cp.async.wait_group %0;" :: "n"(N));
}
__device__ __forceinline__ float sigmoidf_(float x) { return 1.0f / (1.0f + expf(-x)); }

// ---------------------------------------------------------------------------
// Scratch
// ---------------------------------------------------------------------------
__device__ __align__(256) float  g_f0[32 * 64 * 64 * 64];
__device__ __align__(256) float  g_f1[32 * 128 * 32 * 32];
__device__ __align__(256) float  g_f2[32 * 256 * 16 * 16];
__device__ __align__(256) float  g_pre[32 * 128 * 64 * 64];
__device__ __align__(256) __half g_wc1h[18 * 128 * 32];       // block1 W hi [G32][oc][32]
__device__ __align__(256) __half g_wc1l[18 * 128 * 32];
__device__ __align__(256) __half g_wc2h[36 * 256 * 32];
__device__ __align__(256) __half g_wc2l[36 * 256 * 32];
__device__ __align__(256) __half g_wph[2 * 144 * 1024 * 32];  // lstm W hi [layer][G32][oc][32]
__device__ __align__(256) __half g_wpl[2 * 144 * 1024 * 32];
__device__ __align__(256) __half g_bx0h[32 * BHS];            // L0 x im2col hi [(t*2+b)][s][c][n]
__device__ __align__(256) __half g_bx0l[32 * BHS];
__device__ __align__(256) __half g_bx1h[32 * BHS];
__device__ __align__(256) __half g_bx1l[32 * BHS];
__device__ __align__(256) __half g_bhh[2 * BHS];              // h im2col hi [b][s][c][n]
__device__ __align__(256) __half g_bhl[2 * BHS];
__device__ __align__(256) float  g_c[2 * CHW2];
__device__ __align__(256) float  g_zp[4 * 2 * 1024 * 256];

// ---------------------------------------------------------------------------
// LSTM weight prepack: fp32 -> hi/lo fp16 in [layer][G32][oc][32]
// ---------------------------------------------------------------------------
__global__ void __launch_bounds__(256) prepack_w(const float* __restrict__ lw, int layer)
{
    int idx = blockIdx.x * 256 + threadIdx.x;  // 4718592
    int u  = idx & 31;
    int oc = (idx >> 5) & 1023;
    int G  = idx >> 15;
    int k  = G * 32 + u;
    int s  = k >> 9;
    int c  = k & 511;
    float w = lw[((size_t)oc * 512 + c) * 9 + s];
    __half hi = __float2half(w);
    size_t o = (size_t)layer * 4718592 + idx;
    g_wph[o] = hi;
    g_wpl[o] = __float2half(w - __half2float(hi));
}

// ---------------------------------------------------------------------------
// CNN conv weight prepack: [G32][oc][32]
// ---------------------------------------------------------------------------
template <int CIN, int OCTOT>
__global__ void __launch_bounds__(256) prepack_cw(
    const float* __restrict__ w, __half* __restrict__ outh, __half* __restrict__ outl)
{
    constexpr int CPG = CIN / 32;
    int idx = blockIdx.x * 256 + threadIdx.x;
    int u  = idx & 31;
    int oc = (idx >> 5) % OCTOT;
    int G  = (idx >> 5) / OCTOT;
    int s  = G / CPG;
    int c  = (G % CPG) * 32 + u;
    float val = w[((size_t)oc * CIN + c) * 9 + s];
    __half hi = __float2half(val);
    outh[idx] = hi;
    outl[idx] = __float2half(val - __half2float(hi));
}

// ---------------------------------------------------------------------------
// Build layer0 x im2col (hi/lo). 32*BHS elements.
// ---------------------------------------------------------------------------
__global__ void __launch_bounds__(256) build_bx0()
{
    int idx = blockIdx.x * 256 + threadIdx.x;
    int n   = idx & 255;
    int c   = (idx >> 8) & 255;
    int rem = idx >> 16;
    int s   = rem % 9;
    int tb  = rem / 9;
    int t   = tb >> 1, b = tb & 1;
    int dy  = s / 3 - 1, dx = s % 3 - 1;
    int iy  = (n >> 4) + dy, ix = (n & 15) + dx;
    float val = 0.f;
    if (iy >= 0 && iy < 16 && ix >= 0 && ix < 16)
        val = g_f2[(((size_t)(b * 16 + t) * 256 + c) << 8) + iy * 16 + ix];
    __half hi = __float2half(val);
    g_bx0h[idx] = hi;
    g_bx0l[idx] = __float2half(val - __half2float(hi));
}

// ---------------------------------------------------------------------------
// Block 0 SIMT conv+pool
// ---------------------------------------------------------------------------
__global__ void __launch_bounds__(256) conv0_pool(
    const float* __restrict__ x, const float* __restrict__ w,
    const float* __restrict__ bias, const float* __restrict__ g,
    const float* __restrict__ be, const float* __restrict__ m,
    const float* __restrict__ v)
{
    int idx = blockIdx.x * 256 + threadIdx.x;
    int pw = idx & 63;
    int ph = (idx >> 6) & 63;
    int oc = (idx >> 12) & 63;
    int n  = idx >> 18;

    float wr[9];
#pragma unroll
    for (int k = 0; k < 9; k++) wr[k] = w[oc * 9 + k];
    float s  = g[oc] * rsqrtf(v[oc] + 1e-5f);
    float cb = (bias[oc] - m[oc]) * s + be[oc];

    const float* xi = x + n * 16384;
    float mx = -1e30f;
#pragma unroll
    for (int dy0 = 0; dy0 < 2; dy0++) {
#pragma unroll
        for (int dx0 = 0; dx0 < 2; dx0++) {
            int oy = 2 * ph + dy0, ox = 2 * pw + dx0;
            float sum = 0.f;
#pragma unroll
            for (int ky = 0; ky < 3; ky++) {
                int iy = oy - 1 + ky;
                if (iy < 0 || iy >= 128) continue;
#pragma unroll
                for (int kx = 0; kx < 3; kx++) {
                    int ix = ox - 1 + kx;
                    if (ix < 0 || ix >= 128) continue;
                    sum = fmaf(xi[iy * 128 + ix], wr[ky * 3 + kx], sum);
                }
            }
            float y = fmaxf(fmaf(sum, s, cb), 0.f);
            mx = fmaxf(mx, y);
        }
    }
    g_f0[idx] = mx;
}

// ---------------------------------------------------------------------------
// CNN conv via 3xFP16 GEMM, K=32 chunks, on-the-fly shifted im2col from fp32.
// ---------------------------------------------------------------------------
template <int CIN, int S, int OCTOT>
__global__ void __launch_bounds__(256) conv_mma(
    const float* __restrict__ in,
    const __half* __restrict__ wph, const __half* __restrict__ wpl,
    const float* __restrict__ bias, const float* __restrict__ g,
    const float* __restrict__ be, const float* __restrict__ m,
    const float* __restrict__ v, float* __restrict__ pre)
{
    constexpr int NPOS = S * S;
    constexpr int CPG  = CIN / 32;
    constexpr int NG   = 9 * CPG;
    constexpr int LOGS = (S == 64) ? 6 : 5;

    extern __shared__ __half dsm[];
    __shared__ float ssc[128], sbi[128];

    int tid = threadIdx.x, lane = tid & 31, wid = tid >> 5;
    int wm = wid & 3, wn = wid >> 2;
    int ntile = blockIdx.x;
    int ocb   = blockIdx.y * 128;
    int frame = blockIdx.z;

    if (tid < 128) {
        int oc = ocb + tid;
        float s_ = g[oc] * rsqrtf(v[oc] + 1e-5f);
        ssc[tid] = s_;
        sbi[tid] = (bias[oc] - m[oc]) * s_ + be[oc];
    }

    uint32_t dbase = smem_u32(dsm);
    // buffer byte bases
    uint32_t AHB[2] = { dbase,          dbase + 10240 };
    uint32_t ALB[2] = { dbase + 20480,  dbase + 30720 };
    uint32_t BHB[2] = { dbase + 40960,  dbase + 49664 };
    uint32_t BLB[2] = { dbase + 58368,  dbase + 67072 };
    __half* BHp[2] = { dsm + 20480, dsm + 24832 };  // half indices
    __half* BLp[2] = { dsm + 29184, dsm + 33536 };

    // A staging: thread -> (row, 2 segs of 16B out of 4)
    int arow = tid & 127, aseg0 = tid >> 7;
    auto cpA = [&](int G, int buf) {
#pragma unroll
        for (int i = 0; i < 2; i++) {
            int seg = aseg0 + 2 * i;
            uint32_t d = AHB[buf] + arow * 80 + seg * 16;
            uint32_t dl = ALB[buf] + arow * 80 + seg * 16;
            size_t so = (size_t)G * (OCTOT * 32) + (size_t)(ocb + arow) * 32 + seg * 8;
            cp16(d,  wph + so);
            cp16(dl, wpl + so);
        }
        cp_commit();
    };

    // B staging: thread -> (row = channel-in-chunk, 16 consecutive positions)
    int brow = tid >> 3, bp0 = (tid & 7) * 16;
    int nbase = ntile * 128 + bp0;
    float breg[16];
    auto prefetchB = [&](int G) {
        int s = G / CPG, q = G - s * CPG;
        int dy = s / 3 - 1, dx = s % 3 - 1;
        const float* src = in + ((size_t)frame * CIN + q * 32 + brow) * NPOS;
#pragma unroll
        for (int jj = 0; jj < 16; jj++) {
            int pos = nbase + jj;
            int y = pos >> LOGS, x = pos & (S - 1);
            int iy = y + dy, ix = x + dx;
            breg[jj] = (iy >= 0 && iy < S && ix >= 0 && ix < S) ? src[iy * S + ix] : 0.f;
        }
    };
    auto stsB = [&](int buf) {
        __half hv[16], lv[16];
#pragma unroll
        for (int jj = 0; jj < 16; jj++) {
            hv[jj] = __float2half(breg[jj]);
            lv[jj] = __float2half(breg[jj] - __half2float(hv[jj]));
        }
        int o = brow * 136 + bp0;
        *(uint4*)&BHp[buf][o]     = *(uint4*)&hv[0];
        *(uint4*)&BHp[buf][o + 8] = *(uint4*)&hv[8];
        *(uint4*)&BLp[buf][o]     = *(uint4*)&lv[0];
        *(uint4*)&BLp[buf][o + 8] = *(uint4*)&lv[8];
    };

    // ldmatrix lane offsets, per k16-half kk
    int quad = lane >> 3, l7 = lane & 7;
    uint32_t a_off[2][2], b_off[2][4];
    {
        int rsub = ((quad & 1) << 3) + l7;
        int ksub = (quad >> 1) << 4;
        int krow8 = ((quad & 1) << 3) + l7;
        int nsub = (quad >> 1) << 3;
#pragma unroll
        for (int kk = 0; kk < 2; kk++) {
#pragma unroll
            for (int mi = 0; mi < 2; mi++)
                a_off[kk][mi] = (uint32_t)((wm * 32 + mi * 16 + rsub) * 80 + kk * 32 + ksub);
#pragma unroll
            for (int ni2 = 0; ni2 < 4; ni2++)
                b_off[kk][ni2] = (uint32_t)((kk * 16 + krow8) * 272 + (wn * 64 + ni2 * 16 + nsub) * 2);
        }
    }

    float acc[2][8][4];
#pragma unroll
    for (int mi = 0; mi < 2; mi++)
#pragma unroll
        for (int ni = 0; ni < 8; ni++)
#pragma unroll
            for (int q = 0; q < 4; q++) acc[mi][ni][q] = 0.f;

    prefetchB(0); stsB(0); cpA(0, 0);
    prefetchB(1); stsB(1); cpA(1, 1);
    prefetchB(2);

    for (int j = 0; j < NG; j++) {
        if (j < NG - 1) cp_wait<1>(); else cp_wait<0>();
        __syncthreads();

        int buf = j & 1;
#pragma unroll
        for (int kk = 0; kk < 2; kk++) {
            uint32_t ah[2][4], al[2][4], bh_[4][4], bl_[4][4];
#pragma unroll
            for (int mi = 0; mi < 2; mi++) {
                ldm_x4(ah[mi], AHB[buf] + a_off[kk][mi]);
                ldm_x4(al[mi], ALB[buf] + a_off[kk][mi]);
            }
#pragma unroll
            for (int ni2 = 0; ni2 < 4; ni2++) {
                ldm_x4t(bh_[ni2], BHB[buf] + b_off[kk][ni2]);
                ldm_x4t(bl_[ni2], BLB[buf] + b_off[kk][ni2]);
            }
#pragma unroll
            for (int mi = 0; mi < 2; mi++)
#pragma unroll
                for (int ni = 0; ni < 8; ni++) {
                    const uint32_t* bhf = &bh_[ni >> 1][(ni & 1) * 2];
                    const uint32_t* blf = &bl_[ni >> 1][(ni & 1) * 2];
                    mma16816(acc[mi][ni], ah[mi], bhf);
                    mma16816(acc[mi][ni], ah[mi], blf);
                    mma16816(acc[mi][ni], al[mi], bhf);
                }
        }
        __syncthreads();

        if (j + 2 < NG) {
            stsB(buf);
            cpA(j + 2, buf);
            if (j + 3 < NG) prefetchB(j + 3);
        }
    }

    // Epilogue: BN + ReLU -> pre-pool buffer
    int gq = lane >> 2, tq = lane & 3;
    int row0 = wm * 32 + gq;
    int colb = ntile * 128 + wn * 64 + 2 * tq;
#pragma unroll
    for (int mi = 0; mi < 2; mi++)
#pragma unroll
        for (int ni = 0; ni < 8; ni++) {
            int r0 = row0 + mi * 16;
            int col = colb + ni * 8;
#pragma unroll
            for (int h = 0; h < 2; h++) {
                int r = r0 + h * 8;
                float sc = ssc[r], sh = sbi[r];
                float v0 = fmaxf(fmaf(acc[mi][ni][2 * h],     sc, sh), 0.f);
                float v1 = fmaxf(fmaf(acc[mi][ni][2 * h + 1], sc, sh), 0.f);
                *(float2*)(pre + ((size_t)frame * OCTOT + ocb + r) * NPOS + col)
                    = make_float2(v0, v1);
            }
        }
}

// ---------------------------------------------------------------------------
// 2x2 maxpool
// ---------------------------------------------------------------------------
template <int OC, int S>
__global__ void __launch_bounds__(256) pool2(const float* __restrict__ pre,
                                             float* __restrict__ out)
{
    constexpr int HP = S / 2;
    int idx = blockIdx.x * 256 + threadIdx.x;
    int pw = idx % HP;
    int t1 = idx / HP;
    int ph = t1 % HP;
    int t2 = t1 / HP;
    const float* p = pre + (size_t)t2 * S * S + (2 * ph) * S + 2 * pw;
    float a = p[0], b = p[1], c = p[S], d = p[S + 1];
    out[idx] = fmaxf(fmaxf(a, b), fmaxf(c, d));
}

// ---------------------------------------------------------------------------
// ConvLSTM gate conv, K=32 chunks, B via cp.async from materialized im2col.
// Grid: (8 mtiles, 4 = ntile+2*b, 4 ksplits), 256 threads.
// ---------------------------------------------------------------------------
__global__ void __launch_bounds__(256) lstm_mma(
    const __half* __restrict__ wph, const __half* __restrict__ wpl,
    const __half* __restrict__ bxh_t, const __half* __restrict__ bxl_t)
{
    extern __shared__ __half dsm[];

    int tid  = threadIdx.x;
    int lane = tid & 31;
    int wid  = tid >> 5;
    int wm = wid & 3, wn = wid >> 2;

    int mtile = blockIdx.x;
    int ntile = blockIdx.y & 1;
    int b     = blockIdx.y >> 1;
    int split = blockIdx.z;
    int ocb   = mtile * 128;

    const __half* bxh = bxh_t + (size_t)b * BHS;
    const __half* bxl = bxl_t + (size_t)b * BHS;
    const __half* bhh = g_bhh + (size_t)b * BHS;
    const __half* bhl = g_bhl + (size_t)b * BHS;

    uint32_t dbase = smem_u32(dsm);
    uint32_t AHB[2] = { dbase,          dbase + 10240 };
    uint32_t ALB[2] = { dbase + 20480,  dbase + 30720 };
    uint32_t BHB[2] = { dbase + 40960,  dbase + 49664 };
    uint32_t BLB[2] = { dbase + 58368,  dbase + 67072 };

    // A staging: thread -> (row, 2 segs)
    int arow = tid & 127, aseg0 = tid >> 7;
    // B staging: idx = tid + 256*i -> (row 0..31, seg 0..15)
    int brow0 = tid >> 4, bseg0 = tid & 15;        // i = 0
    int brow1 = (tid + 256) >> 4, bseg1 = tid & 15; // i = 1
    int pos0 = ntile * 128;

    auto stage = [&](int j, int buf) {
        int G  = split * 36 + j;
        int s  = G >> 4;
        int c0 = (G & 15) << 5;
        bool isx = (c0 < 256);
        int cL = isx ? c0 : c0 - 256;
        const __half* sh = isx ? bxh : bhh;
        const __half* sl = isx ? bxl : bhl;
        size_t slab = (size_t)s * 65536;
#pragma unroll
        for (int i = 0; i < 2; i++) {
            int seg = aseg0 + 2 * i;
            uint32_t d  = AHB[buf] + arow * 80 + seg * 16;
            uint32_t dl = ALB[buf] + arow * 80 + seg * 16;
            size_t so = (size_t)G * 32768 + (size_t)(ocb + arow) * 32 + seg * 8;
            cp16(d,  wph + so);
            cp16(dl, wpl + so);
        }
        {
            size_t so0 = slab + (size_t)(cL + brow0) * 256 + pos0 + bseg0 * 8;
            size_t so1 = slab + (size_t)(cL + brow1) * 256 + pos0 + bseg1 * 8;
            cp16(BHB[buf] + brow0 * 272 + bseg0 * 16, sh + so0);
            cp16(BHB[buf] + brow1 * 272 + bseg1 * 16, sh + so1);
            cp16(BLB[buf] + brow0 * 272 + bseg0 * 16, sl + so0);
            cp16(BLB[buf] + brow1 * 272 + bseg1 * 16, sl + so1);
        }
        cp_commit();
    };

    int quad = lane >> 3, l7 = lane & 7;
    uint32_t a_off[2][2], b_off[2][4];
    {
        int rsub = ((quad & 1) << 3) + l7;
        int ksub = (quad >> 1) << 4;
        int krow8 = ((quad & 1) << 3) + l7;
        int nsub = (quad >> 1) << 3;
#pragma unroll
        for (int kk = 0; kk < 2; kk++) {
#pragma unroll
            for (int mi = 0; mi < 2; mi++)
                a_off[kk][mi] = (uint32_t)((wm * 32 + mi * 16 + rsub) * 80 + kk * 32 + ksub);
#pragma unroll
            for (int ni2 = 0; ni2 < 4; ni2++)
                b_off[kk][ni2] = (uint32_t)((kk * 16 + krow8) * 272 + (wn * 64 + ni2 * 16 + nsub) * 2);
        }
    }

    float acc[2][8][4];
#pragma unroll
    for (int mi = 0; mi < 2; mi++)
#pragma unroll
        for (int ni = 0; ni < 8; ni++)
#pragma unroll
            for (int q = 0; q < 4; q++) acc[mi][ni][q] = 0.f;

    stage(0, 0);
    stage(1, 1);

    for (int j = 0; j < 36; j++) {
        if (j < 35) cp_wait<1>(); else cp_wait<0>();
        __syncthreads();

        int buf = j & 1;
#pragma unroll
        for (int kk = 0; kk < 2; kk++) {
            uint32_t ah[2][4], al[2][4], bh_[4][4], bl_[4][4];
#pragma unroll
            for (int mi = 0; mi < 2; mi++) {
                ldm_x4(ah[mi], AHB[buf] + a_off[kk][mi]);
                ldm_x4(al[mi], ALB[buf] + a_off[kk][mi]);
            }
#pragma unroll
            for (int ni2 = 0; ni2 < 4; ni2++) {
                ldm_x4t(bh_[ni2], BHB[buf] + b_off[kk][ni2]);
                ldm_x4t(bl_[ni2], BLB[buf] + b_off[kk][ni2]);
            }
#pragma unroll
            for (int mi = 0; mi < 2; mi++)
#pragma unroll
                for (int ni = 0; ni < 8; ni++) {
                    const uint32_t* bhf = &bh_[ni >> 1][(ni & 1) * 2];
                    const uint32_t* blf = &bl_[ni >> 1][(ni & 1) * 2];
                    mma16816(acc[mi][ni], ah[mi], bhf);
                    mma16816(acc[mi][ni], ah[mi], blf);
                    mma16816(acc[mi][ni], al[mi], bhf);
                }
        }
        __syncthreads();
        if (j + 2 < 36) stage(j + 2, buf);
    }

    int gq = lane >> 2, tq = lane & 3;
    float* zbase = g_zp + ((size_t)(split * 2 + b) * 1024) * 256;
    int row0 = ocb + wm * 32 + gq;
    int col0 = ntile * 128 + wn * 64 + 2 * tq;
#pragma unroll
    for (int mi = 0; mi < 2; mi++)
#pragma unroll
        for (int ni = 0; ni < 8; ni++) {
            int r = row0 + mi * 16;
            int cc = col0 + ni * 8;
            *(float2*)(zbase + (size_t)r * 256 + cc)       = make_float2(acc[mi][ni][0], acc[mi][ni][1]);
            *(float2*)(zbase + (size_t)(r + 8) * 256 + cc) = make_float2(acc[mi][ni][2], acc[mi][ni][3]);
        }
}

// ---------------------------------------------------------------------------
// Gates (round-8 version: scatter h hi/lo into im2col buffers)
// ---------------------------------------------------------------------------
__global__ void __launch_bounds__(256) lstm_gates(int t, int layer,
                                                  const float* __restrict__ lb,
                                                  float* __restrict__ out)
{
    int idx = blockIdx.x * 256 + threadIdx.x;
    int inner = idx & 65535;
    int b = idx >> 16;
    int c = inner >> 8;
    int pos = inner & 255;

    float zi = lb[c], zf = lb[c + 256], zo = lb[c + 512], zg = lb[c + 768];
#pragma unroll
    for (int s = 0; s < 4; s++) {
        const float* zb = g_zp + ((size_t)s * 2 + b) * 1024 * 256;
        zi += zb[(size_t)(c)       * 256 + pos];
        zf += zb[(size_t)(c + 256) * 256 + pos];
        zo += zb[(size_t)(c + 512) * 256 + pos];
        zg += zb[(size_t)(c + 768) * 256 + pos];
    }

    float cn = sigmoidf_(zf) * g_c[idx] + sigmoidf_(zi) * tanhf(zg);
    float hn = sigmoidf_(zo) * tanhf(cn);
    g_c[idx] = cn;

    __half hh = __float2half(hn);
    __half hl = __float2half(hn - __half2float(hh));
    int y = pos >> 4, x = pos & 15;
    __half* bhhp = g_bhh + (size_t)b * BHS;
    __half* bhlp = g_bhl + (size_t)b * BHS;
    __half* bxhp = g_bx1h + (size_t)(t * 2 + b) * BHS;
    __half* bxlp = g_bx1l + (size_t)(t * 2 + b) * BHS;
#pragma unroll
    for (int s = 0; s < 9; s++) {
        int dy = s / 3 - 1, dx = s % 3 - 1;
        int ny = y - dy, nx = x - dx;
        if (ny >= 0 && ny < 16 && nx >= 0 && nx < 16) {
            int o = ((s * 256 + c) << 8) + ny * 16 + nx;
            bhhp[o] = hh;
            bhlp[o] = hl;
            if (layer == 0) { bxhp[o] = hh; bxlp[o] = hl; }
        }
    }

    if (layer == 1)
        out[(size_t)b * 16 * CHW2 + (size_t)t * CHW2 + inner] = hn;
}

__global__ void __launch_bounds__(256) zero_state()
{
    int idx = blockIdx.x * 256 + threadIdx.x;   // 1179648
    if (idx < 131072) g_c[idx] = 0.f;
    g_bhh[idx] = __float2half(0.f);
    g_bhl[idx] = __float2half(0.f);
}

__global__ void __launch_bounds__(256) copy_last(float* __restrict__ out)
{
    int idx = blockIdx.x * 256 + threadIdx.x;
    int inner = idx & 65535;
    int b = idx >> 16;
    out[2097152 + idx] = out[(size_t)b * 16 * CHW2 + 15 * CHW2 + inner];
}

// ---------------------------------------------------------------------------
// Launch sequence (graph-capturable)
// ---------------------------------------------------------------------------
extern "C" void kernel_launch(void* const* d_in, const int* in_sizes, int n_in,
                              void* d_out, int out_size)
{
    const float* x   = (const float*)d_in[0];
    const float* w0  = (const float*)d_in[1];
    const float* b0  = (const float*)d_in[2];
    const float* g0  = (const float*)d_in[3];
    const float* be0 = (const float*)d_in[4];
    const float* m0  = (const float*)d_in[5];
    const float* v0  = (const float*)d_in[6];
    const float* w1  = (const float*)d_in[7];
    const float* b1  = (const float*)d_in[8];
    const float* g1  = (const float*)d_in[9];
    const float* be1 = (const float*)d_in[10];
    const float* m1  = (const float*)d_in[11];
    const float* v1  = (const float*)d_in[12];
    const float* w2  = (const float*)d_in[13];
    const float* b2  = (const float*)d_in[14];
    const float* g2  = (const float*)d_in[15];
    const float* be2 = (const float*)d_in[16];
    const float* m2  = (const float*)d_in[17];
    const float* v2  = (const float*)d_in[18];
    const float* lw0 = (const float*)d_in[19];
    const float* lb0 = (const float*)d_in[20];
    const float* lw1 = (const float*)d_in[21];
    const float* lb1 = (const float*)d_in[22];
    float* out = (float*)d_out;

    cudaFuncSetAttribute(lstm_mma, cudaFuncAttributeMaxDynamicSharedMemorySize, SM_TOTAL);
    cudaFuncSetAttribute(conv_mma<64, 64, 128>, cudaFuncAttributeMaxDynamicSharedMemorySize, SM_TOTAL);
    cudaFuncSetAttribute(conv_mma<128, 32, 256>, cudaFuncAttributeMaxDynamicSharedMemorySize, SM_TOTAL);

    float* f0ptr;  cudaGetSymbolAddress((void**)&f0ptr, g_f0);
    float* f1ptr;  cudaGetSymbolAddress((void**)&f1ptr, g_f1);
    float* f2ptr;  cudaGetSymbolAddress((void**)&f2ptr, g_f2);
    float* preptr; cudaGetSymbolAddress((void**)&preptr, g_pre);
    __half* wc1h; cudaGetSymbolAddress((void**)&wc1h, g_wc1h);
    __half* wc1l; cudaGetSymbolAddress((void**)&wc1l, g_wc1l);
    __half* wc2h; cudaGetSymbolAddress((void**)&wc2h, g_wc2h);
    __half* wc2l; cudaGetSymbolAddress((void**)&wc2l, g_wc2l);
    __half* wphptr; cudaGetSymbolAddress((void**)&wphptr, g_wph);
    __half* wplptr; cudaGetSymbolAddress((void**)&wplptr, g_wpl);
    __half* bx0hptr; cudaGetSymbolAddress((void**)&bx0hptr, g_bx0h);
    __half* bx0lptr; cudaGetSymbolAddress((void**)&bx0lptr, g_bx0l);
    __half* bx1hptr; cudaGetSymbolAddress((void**)&bx1hptr, g_bx1h);
    __half* bx1lptr; cudaGetSymbolAddress((void**)&bx1lptr, g_bx1l);

    // weight prepacks (K32 layout)
    prepack_w<<<18432, 256>>>(lw0, 0);
    prepack_w<<<18432, 256>>>(lw1, 1);
    prepack_cw<64, 128><<<288, 256>>>(w1, wc1h, wc1l);
    prepack_cw<128, 256><<<1152, 256>>>(w2, wc2h, wc2l);

    // CNN encoder
    conv0_pool<<<32768, 256>>>(x, w0, b0, g0, be0, m0, v0);
    conv_mma<64, 64, 128><<<dim3(32, 1, 32), 256, SM_TOTAL>>>(f0ptr, wc1h, wc1l,
                                                              b1, g1, be1, m1, v1, preptr);
    pool2<128, 64><<<16384, 256>>>(preptr, f1ptr);
    conv_mma<128, 32, 256><<<dim3(8, 2, 32), 256, SM_TOTAL>>>(f1ptr, wc2h, wc2l,
                                                              b2, g2, be2, m2, v2, preptr);
    pool2<256, 32><<<8192, 256>>>(preptr, f2ptr);

    // hi/lo fp16 im2col of CNN features
    build_bx0<<<73728, 256>>>();

    // ConvLSTM layer 0
    zero_state<<<4608, 256>>>();
    for (int t = 0; t < 16; t++) {
        lstm_mma<<<dim3(8, 4, 4), 256, SM_TOTAL>>>(wphptr, wplptr,
                                                   bx0hptr + (size_t)t * 2 * BHS,
                                                   bx0lptr + (size_t)t * 2 * BHS);
        lstm_gates<<<512, 256>>>(t, 0, lb0, out);
    }

    // ConvLSTM layer 1
    zero_state<<<4608, 256>>>();
    for (int t = 0; t < 16; t++) {
        lstm_mma<<<dim3(8, 4, 4), 256, SM_TOTAL>>>(wphptr + (size_t)144 * 1024 * 32,
                                                   wplptr + (size_t)144 * 1024 * 32,
                                                   bx1hptr + (size_t)t * 2 * BHS,
                                                   bx1lptr + (size_t)t * 2 * BHS);
        lstm_gates<<<512, 256>>>(t, 1, lb1, out);
    }

    copy_last<<<512, 256>>>(out);
}

// round 11
// speedup vs baseline: 1.5740x; 1.2723x over previous
#include <cuda_runtime.h>
#include <cuda_fp16.h>
#include <math.h>
#include <stdint.h>

// ---------------------------------------------------------------------------
//   block0: 1->64 SIMT; block1/2 + ConvLSTM convs: 3xFP16 mma.sync GEMM
//   (D += Ah*Bh + Ah*Bl + Al*Bh), K=16 chunks, double buffer (round-8 config).
// ConvLSTM layers software-pipelined: step k runs L0(t=k) and L1(t=k-1)
// in ONE kernel pair (per-layer state buffers).
// ---------------------------------------------------------------------------

#define CHW2 65536          // 256*16*16
#define BHS  589824         // 9*256*256

typedef unsigned long long ull;

// ============================ PTX helpers ==================================
__device__ __forceinline__ uint32_t smem_u32(const void* p) {
    uint32_t a;
    asm("{ .reg .u64 t; cvta.to.shared.u64 t, %1; cvt.u32.u64 %0, t; }" : "=r"(a) : "l"(p));
    return a;
}
__device__ __forceinline__ void ldm_x4(uint32_t* r, uint32_t addr) {
    asm volatile("ldmatrix.sync.aligned.m8n8.x4.shared.b16 {%0,%1,%2,%3}, [%4];"
        : "=r"(r[0]), "=r"(r[1]), "=r"(r[2]), "=r"(r[3]) : "r"(addr));
}
__device__ __forceinline__ void ldm_x4t(uint32_t* r, uint32_t addr) {
    asm volatile("ldmatrix.sync.aligned.m8n8.x4.trans.shared.b16 {%0,%1,%2,%3}, [%4];"
        : "=r"(r[0]), "=r"(r[1]), "=r"(r[2]), "=r"(r[3]) : "r"(addr));
}
__device__ __forceinline__ void mma16816(float* d, const uint32_t* a, const uint32_t* b) {
    asm volatile(
        "mma.sync.aligned.m16n8k16.row.col.f32.f16.f16.f32 "
        "{%0,%1,%2,%3}, {%4,%5,%6,%7}, {%8,%9}, {%0,%1,%2,%3};"
        : "+f"(d[0]), "+f"(d[1]), "+f"(d[2]), "+f"(d[3])
        : "r"(a[0]), "r"(a[1]), "r"(a[2]), "r"(a[3]), "r"(b[0]), "r"(b[1]));
}
__device__ __forceinline__ void cp16(uint32_t sdst, const void* gsrc) {
    asm volatile("cp.async.cg.shared.global [%0], [%1], 16;" :: "r"(sdst), "l"(gsrc));
}
__device__ __forceinline__ void cp_commit() { asm volatile("cp.async.commit_group;"); }
template <int N> __device__ __forceinline__ void cp_wait() {
    asm volatile("cp.async.wait_group %0;" :: "n"(N));
}
__device__ __forceinline__ ull pack2(float lo, float hi) {
    ull r; asm("mov.b64 %0, {%1,%2};" : "=l"(r) : "f"(lo), "f"(hi)); return r;
}
__device__ __forceinline__ float sigmoidf_(float x) { return 1.0f / (1.0f + expf(-x)); }

// ---------------------------------------------------------------------------
// Scratch (per-layer LSTM state duplicated for pipelining)
// ---------------------------------------------------------------------------
__device__ __align__(256) float  g_f0[32 * 64 * 64 * 64];
__device__ __align__(256) float  g_f1[32 * 128 * 32 * 32];
__device__ __align__(256) float  g_f2[32 * 256 * 16 * 16];
__device__ __align__(256) float  g_pre[32 * 128 * 64 * 64];
__device__ __align__(256) __half g_wc1h[36 * 128 * 16];
__device__ __align__(256) __half g_wc1l[36 * 128 * 16];
__device__ __align__(256) __half g_wc2h[72 * 256 * 16];
__device__ __align__(256) __half g_wc2l[72 * 256 * 16];
__device__ __align__(256) __half g_wph[2 * 288 * 1024 * 16];  // [layer][G][oc][16]
__device__ __align__(256) __half g_wpl[2 * 288 * 1024 * 16];
__device__ __align__(256) __half g_bx0h[32 * BHS];            // L0 x im2col [(t*2+b)][s][c][n]
__device__ __align__(256) __half g_bx0l[32 * BHS];
__device__ __align__(256) __half g_bx1h[32 * BHS];            // L1 x im2col
__device__ __align__(256) __half g_bx1l[32 * BHS];
__device__ __align__(256) __half g_bhh[2 * 2 * BHS];          // h im2col [layer][b][s][c][n]
__device__ __align__(256) __half g_bhl[2 * 2 * BHS];
__device__ __align__(256) float  g_c[2 * 2 * CHW2];           // cell state [layer][b][...]
__device__ __align__(256) float  g_zp[2 * 4 * 2 * 1024 * 256];// partials [layer][split][b][oc][pos]

// ---------------------------------------------------------------------------
// LSTM weight prepack: fp32 -> hi/lo fp16 in [layer][G][oc][16]
// ---------------------------------------------------------------------------
__global__ void __launch_bounds__(256) prepack_w(const float* __restrict__ lw, int layer)
{
    int idx = blockIdx.x * 256 + threadIdx.x;  // 4718592
    int u  = idx & 15;
    int oc = (idx >> 4) & 1023;
    int G  = idx >> 14;
    int k  = G * 16 + u;
    int s  = k >> 9;
    int c  = k & 511;
    float w = lw[((size_t)oc * 512 + c) * 9 + s];
    __half hi = __float2half(w);
    size_t o = (size_t)layer * 4718592 + idx;
    g_wph[o] = hi;
    g_wpl[o] = __float2half(w - __half2float(hi));
}

// ---------------------------------------------------------------------------
// CNN conv weight prepack: [G][oc][16]
// ---------------------------------------------------------------------------
template <int CIN, int OCTOT>
__global__ void __launch_bounds__(256) prepack_cw(
    const float* __restrict__ w, __half* __restrict__ outh, __half* __restrict__ outl)
{
    constexpr int CPG = CIN / 16;
    int idx = blockIdx.x * 256 + threadIdx.x;
    int u  = idx & 15;
    int oc = (idx >> 4) % OCTOT;
    int G  = (idx >> 4) / OCTOT;
    int s  = G / CPG;
    int c  = (G % CPG) * 16 + u;
    float val = w[((size_t)oc * CIN + c) * 9 + s];
    __half hi = __float2half(val);
    outh[idx] = hi;
    outl[idx] = __float2half(val - __half2float(hi));
}

// ---------------------------------------------------------------------------
// Build layer0 x im2col (hi/lo). 32*BHS elements.
// ---------------------------------------------------------------------------
__global__ void __launch_bounds__(256) build_bx0()
{
    int idx = blockIdx.x * 256 + threadIdx.x;   // < 18874368
    int n   = idx & 255;
    int c   = (idx >> 8) & 255;
    int rem = idx >> 16;
    int s   = rem % 9;
    int tb  = rem / 9;
    int t   = tb >> 1, b = tb & 1;
    int dy  = s / 3 - 1, dx = s % 3 - 1;
    int iy  = (n >> 4) + dy, ix = (n & 15) + dx;
    float val = 0.f;
    if (iy >= 0 && iy < 16 && ix >= 0 && ix < 16)
        val = g_f2[(((size_t)(b * 16 + t) * 256 + c) << 8) + iy * 16 + ix];
    __half hi = __float2half(val);
    g_bx0h[idx] = hi;
    g_bx0l[idx] = __float2half(val - __half2float(hi));
}

// ---------------------------------------------------------------------------
// Block 0 SIMT conv+pool
// ---------------------------------------------------------------------------
__global__ void __launch_bounds__(256) conv0_pool(
    const float* __restrict__ x, const float* __restrict__ w,
    const float* __restrict__ bias, const float* __restrict__ g,
    const float* __restrict__ be, const float* __restrict__ m,
    const float* __restrict__ v)
{
    int idx = blockIdx.x * 256 + threadIdx.x;
    int pw = idx & 63;
    int ph = (idx >> 6) & 63;
    int oc = (idx >> 12) & 63;
    int n  = idx >> 18;

    float wr[9];
#pragma unroll
    for (int k = 0; k < 9; k++) wr[k] = w[oc * 9 + k];
    float s  = g[oc] * rsqrtf(v[oc] + 1e-5f);
    float cb = (bias[oc] - m[oc]) * s + be[oc];

    const float* xi = x + n * 16384;
    float mx = -1e30f;
#pragma unroll
    for (int dy0 = 0; dy0 < 2; dy0++) {
#pragma unroll
        for (int dx0 = 0; dx0 < 2; dx0++) {
            int oy = 2 * ph + dy0, ox = 2 * pw + dx0;
            float sum = 0.f;
#pragma unroll
            for (int ky = 0; ky < 3; ky++) {
                int iy = oy - 1 + ky;
                if (iy < 0 || iy >= 128) continue;
#pragma unroll
                for (int kx = 0; kx < 3; kx++) {
                    int ix = ox - 1 + kx;
                    if (ix < 0 || ix >= 128) continue;
                    sum = fmaf(xi[iy * 128 + ix], wr[ky * 3 + kx], sum);
                }
            }
            float y = fmaxf(fmaf(sum, s, cb), 0.f);
            mx = fmaxf(mx, y);
        }
    }
    g_f0[idx] = mx;
}

// ---------------------------------------------------------------------------
// CNN conv via 3xFP16 GEMM, K=16 chunks, on-the-fly shifted im2col (round 8).
// ---------------------------------------------------------------------------
template <int CIN, int S, int OCTOT>
__global__ void __launch_bounds__(256) conv_mma(
    const float* __restrict__ in,
    const __half* __restrict__ wph, const __half* __restrict__ wpl,
    const float* __restrict__ bias, const float* __restrict__ g,
    const float* __restrict__ be, const float* __restrict__ m,
    const float* __restrict__ v, float* __restrict__ pre)
{
    constexpr int NPOS = S * S;
    constexpr int CPG  = CIN / 16;
    constexpr int NG   = 9 * CPG;
    constexpr int LOGS = (S == 64) ? 6 : 5;

    __shared__ __align__(16) __half Ah[2][128 * 24];
    __shared__ __align__(16) __half Al[2][128 * 24];
    __shared__ __align__(16) __half Bh[2][16 * 136];
    __shared__ __align__(16) __half Bl[2][16 * 136];
    __shared__ float ssc[128], sbi[128];

    int tid = threadIdx.x, lane = tid & 31, wid = tid >> 5;
    int wm = wid & 3, wn = wid >> 2;
    int ntile = blockIdx.x;
    int ocb   = blockIdx.y * 128;
    int frame = blockIdx.z;

    if (tid < 128) {
        int oc = ocb + tid;
        float s_ = g[oc] * rsqrtf(v[oc] + 1e-5f);
        ssc[tid] = s_;
        sbi[tid] = (bias[oc] - m[oc]) * s_ + be[oc];
    }

    int arow = tid >> 1, au = tid & 1;
    uint32_t ao = arow * 48 + au * 16;
    uint32_t ah_dst[2] = { smem_u32(&Ah[0][0]) + ao, smem_u32(&Ah[1][0]) + ao };
    uint32_t al_dst[2] = { smem_u32(&Al[0][0]) + ao, smem_u32(&Al[1][0]) + ao };
    size_t a_off_elem = (size_t)(ocb + arow) * 16 + au * 8;

    int bk = tid >> 4, bn = tid & 15;
    int nbase = ntile * 128 + bn * 8;

    float breg[8];
    auto prefetchB = [&](int G) {
        int s = G / CPG, q = G - s * CPG;
        int dy = s / 3 - 1, dx = s % 3 - 1;
        const float* src = in + ((size_t)frame * CIN + q * 16 + bk) * NPOS;
#pragma unroll
        for (int j = 0; j < 8; j++) {
            int pos = nbase + j;
            int y = pos >> LOGS, x = pos & (S - 1);
            int iy = y + dy, ix = x + dx;
            breg[j] = (iy >= 0 && iy < S && ix >= 0 && ix < S) ? src[iy * S + ix] : 0.f;
        }
    };
    auto stsB = [&](int buf) {
        __half hv[8], lv[8];
#pragma unroll
        for (int j = 0; j < 8; j++) {
            hv[j] = __float2half(breg[j]);
            lv[j] = __float2half(breg[j] - __half2float(hv[j]));
        }
        *(uint4*)&Bh[buf][bk * 136 + bn * 8] = *(uint4*)hv;
        *(uint4*)&Bl[buf][bk * 136 + bn * 8] = *(uint4*)lv;
    };
    auto cpA = [&](int G, int buf) {
        cp16(ah_dst[buf], wph + (size_t)G * (OCTOT * 16) + a_off_elem);
        cp16(al_dst[buf], wpl + (size_t)G * (OCTOT * 16) + a_off_elem);
        cp_commit();
    };

    int quad = lane >> 3, l7 = lane & 7;
    uint32_t a_off[2], b_off[4];
    {
        int rsub = ((quad & 1) << 3) + l7;
        int ksub = (quad >> 1) << 4;
#pragma unroll
        for (int mi = 0; mi < 2; mi++)
            a_off[mi] = (uint32_t)((wm * 32 + mi * 16 + rsub) * 48 + ksub);
        int krow = ((quad & 1) << 3) + l7;
        int nsub = (quad >> 1) << 3;
#pragma unroll
        for (int ni2 = 0; ni2 < 4; ni2++)
            b_off[ni2] = (uint32_t)(krow * 272 + (wn * 64 + ni2 * 16 + nsub) * 2);
    }
    uint32_t ahb[2] = { smem_u32(&Ah[0][0]), smem_u32(&Ah[1][0]) };
    uint32_t alb[2] = { smem_u32(&Al[0][0]), smem_u32(&Al[1][0]) };
    uint32_t bhb[2] = { smem_u32(&Bh[0][0]), smem_u32(&Bh[1][0]) };
    uint32_t blb[2] = { smem_u32(&Bl[0][0]), smem_u32(&Bl[1][0]) };

    float acc[2][8][4];
#pragma unroll
    for (int mi = 0; mi < 2; mi++)
#pragma unroll
        for (int ni = 0; ni < 8; ni++)
#pragma unroll
            for (int q = 0; q < 4; q++) acc[mi][ni][q] = 0.f;

    prefetchB(0); stsB(0); cpA(0, 0);
    prefetchB(1); stsB(1); cpA(1, 1);
    if (NG > 2) prefetchB(2);

    for (int j = 0; j < NG; j++) {
        if (j < NG - 1) cp_wait<1>(); else cp_wait<0>();
        __syncthreads();

        int buf = j & 1;
        uint32_t ah[2][4], al[2][4], bh_[4][4], bl_[4][4];
#pragma unroll
        for (int mi = 0; mi < 2; mi++) {
            ldm_x4(ah[mi], ahb[buf] + a_off[mi]);
            ldm_x4(al[mi], alb[buf] + a_off[mi]);
        }
#pragma unroll
        for (int ni2 = 0; ni2 < 4; ni2++) {
            ldm_x4t(bh_[ni2], bhb[buf] + b_off[ni2]);
            ldm_x4t(bl_[ni2], blb[buf] + b_off[ni2]);
        }
#pragma unroll
        for (int mi = 0; mi < 2; mi++)
#pragma unroll
            for (int ni = 0; ni < 8; ni++) {
                const uint32_t* bhf = &bh_[ni >> 1][(ni & 1) * 2];
                const uint32_t* blf = &bl_[ni >> 1][(ni & 1) * 2];
                mma16816(acc[mi][ni], ah[mi], bhf);
                mma16816(acc[mi][ni], ah[mi], blf);
                mma16816(acc[mi][ni], al[mi], bhf);
            }
        __syncthreads();

        if (j + 2 < NG) {
            stsB(buf);
            cpA(j + 2, buf);
            if (j + 3 < NG) prefetchB(j + 3);
        }
    }

    int gq = lane >> 2, tq = lane & 3;
    int row0 = wm * 32 + gq;
    int colb = ntile * 128 + wn * 64 + 2 * tq;
#pragma unroll
    for (int mi = 0; mi < 2; mi++)
#pragma unroll
        for (int ni = 0; ni < 8; ni++) {
            int r0 = row0 + mi * 16;
            int col = colb + ni * 8;
#pragma unroll
            for (int h = 0; h < 2; h++) {
                int r = r0 + h * 8;
                float sc = ssc[r], sh = sbi[r];
                float v0 = fmaxf(fmaf(acc[mi][ni][2 * h],     sc, sh), 0.f);
                float v1 = fmaxf(fmaf(acc[mi][ni][2 * h + 1], sc, sh), 0.f);
                *(float2*)(pre + ((size_t)frame * OCTOT + ocb + r) * NPOS + col)
                    = make_float2(v0, v1);
            }
        }
}

// ---------------------------------------------------------------------------
// 2x2 maxpool
// ---------------------------------------------------------------------------
template <int OC, int S>
__global__ void __launch_bounds__(256) pool2(const float* __restrict__ pre,
                                             float* __restrict__ out)
{
    constexpr int HP = S / 2;
    int idx = blockIdx.x * 256 + threadIdx.x;
    int pw = idx % HP;
    int t1 = idx / HP;
    int ph = t1 % HP;
    int t2 = t1 / HP;
    const float* p = pre + (size_t)t2 * S * S + (2 * ph) * S + 2 * pw;
    float a = p[0], b = p[1], c = p[S], d = p[S + 1];
    out[idx] = fmaxf(fmaxf(a, b), fmaxf(c, d));
}

// ---------------------------------------------------------------------------
// Pipelined ConvLSTM MMA: step k runs L0(t=k) and L1(t=k-1).
// Grid (8 mtiles, 4 = ntile+2*b, 8 = split + 4*layer), 256 threads.
// ---------------------------------------------------------------------------
__global__ void __launch_bounds__(256) lstm_mma_pair(int k)
{
    int layer = blockIdx.z >> 2;
    int split = blockIdx.z & 3;
    int t = layer ? (k - 1) : k;
    if (t < 0 || t > 15) return;

    __shared__ __align__(16) __half Ah[2][128 * 24];
    __shared__ __align__(16) __half Al[2][128 * 24];
    __shared__ __align__(16) __half Bh[2][16 * 136];
    __shared__ __align__(16) __half Bl[2][16 * 136];

    int tid  = threadIdx.x;
    int lane = tid & 31;
    int wid  = tid >> 5;
    int wm = wid & 3, wn = wid >> 2;

    int mtile = blockIdx.x;
    int ntile = blockIdx.y & 1;
    int b     = blockIdx.y >> 1;
    int ocb   = mtile * 128;

    size_t slab = (size_t)(t * 2 + b) * BHS;
    const __half* bxh = (layer ? g_bx1h : g_bx0h) + slab;
    const __half* bxl = (layer ? g_bx1l : g_bx0l) + slab;
    const __half* bhh = g_bhh + (size_t)(layer * 2 + b) * BHS;
    const __half* bhl = g_bhl + (size_t)(layer * 2 + b) * BHS;
    const __half* wph = g_wph + (size_t)layer * 4718592;
    const __half* wpl = g_wpl + (size_t)layer * 4718592;

    int arow = tid >> 1, au = tid & 1;
    uint32_t ao = arow * 48 + au * 16;
    uint32_t ah_dst[2] = { smem_u32(&Ah[0][0]) + ao, smem_u32(&Ah[1][0]) + ao };
    uint32_t al_dst[2] = { smem_u32(&Al[0][0]) + ao, smem_u32(&Al[1][0]) + ao };
    uint32_t bo = (tid >> 4) * 272 + (tid & 15) * 16;
    uint32_t bh_dst[2] = { smem_u32(&Bh[0][0]) + bo, smem_u32(&Bh[1][0]) + bo };
    uint32_t bl_dst[2] = { smem_u32(&Bl[0][0]) + bo, smem_u32(&Bl[1][0]) + bo };
    size_t a_off_elem = (size_t)(arow + ocb) * 16 + au * 8;
    int b_src_off = (tid >> 4) * 256 + ntile * 128 + (tid & 15) * 8;

    int quad = lane >> 3, l7 = lane & 7;
    uint32_t a_off[2], b_off[4];
    {
        int rsub = ((quad & 1) << 3) + l7;
        int ksub = (quad >> 1) << 4;
#pragma unroll
        for (int mi = 0; mi < 2; mi++)
            a_off[mi] = (uint32_t)((wm * 32 + mi * 16 + rsub) * 48 + ksub);
        int krow = ((quad & 1) << 3) + l7;
        int nsub = (quad >> 1) << 3;
#pragma unroll
        for (int ni2 = 0; ni2 < 4; ni2++)
            b_off[ni2] = (uint32_t)(krow * 272 + (wn * 64 + ni2 * 16 + nsub) * 2);
    }
    uint32_t ahb[2] = { smem_u32(&Ah[0][0]), smem_u32(&Ah[1][0]) };
    uint32_t alb[2] = { smem_u32(&Al[0][0]), smem_u32(&Al[1][0]) };
    uint32_t bhb[2] = { smem_u32(&Bh[0][0]), smem_u32(&Bh[1][0]) };
    uint32_t blb[2] = { smem_u32(&Bl[0][0]), smem_u32(&Bl[1][0]) };

    float acc[2][8][4];
#pragma unroll
    for (int mi = 0; mi < 2; mi++)
#pragma unroll
        for (int ni = 0; ni < 8; ni++)
#pragma unroll
            for (int q = 0; q < 4; q++) acc[mi][ni][q] = 0.f;

    auto stage = [&](int j, int buf) {
        int G  = split * 72 + j;
        int s  = G >> 5;
        int c0 = (G & 31) << 4;
        bool xh = (c0 < 256);
        size_t srow = ((size_t)(s * 256 + (xh ? c0 : c0 - 256)) << 8);
        const __half* bsh = (xh ? bxh : bhh) + srow;
        const __half* bsl = (xh ? bxl : bhl) + srow;
        cp16(ah_dst[buf], wph + (size_t)G * 16384 + a_off_elem);
        cp16(al_dst[buf], wpl + (size_t)G * 16384 + a_off_elem);
        cp16(bh_dst[buf], bsh + b_src_off);
        cp16(bl_dst[buf], bsl + b_src_off);
        cp_commit();
    };

    stage(0, 0);
    stage(1, 1);

    for (int j = 0; j < 72; j++) {
        if (j < 71) cp_wait<1>(); else cp_wait<0>();
        __syncthreads();

        int buf = j & 1;
        uint32_t ah[2][4], al[2][4], bh_[4][4], bl_[4][4];
#pragma unroll
        for (int mi = 0; mi < 2; mi++) {
            ldm_x4(ah[mi], ahb[buf] + a_off[mi]);
            ldm_x4(al[mi], alb[buf] + a_off[mi]);
        }
#pragma unroll
        for (int ni2 = 0; ni2 < 4; ni2++) {
            ldm_x4t(bh_[ni2], bhb[buf] + b_off[ni2]);
            ldm_x4t(bl_[ni2], blb[buf] + b_off[ni2]);
        }
#pragma unroll
        for (int mi = 0; mi < 2; mi++)
#pragma unroll
            for (int ni = 0; ni < 8; ni++) {
                const uint32_t* bhf = &bh_[ni >> 1][(ni & 1) * 2];
                const uint32_t* blf = &bl_[ni >> 1][(ni & 1) * 2];
                mma16816(acc[mi][ni], ah[mi], bhf);
                mma16816(acc[mi][ni], ah[mi], blf);
                mma16816(acc[mi][ni], al[mi], bhf);
            }

        __syncthreads();
        if (j + 2 < 72) stage(j + 2, buf);
    }

    int gq = lane >> 2, tq = lane & 3;
    float* zbase = g_zp + ((size_t)((layer * 4 + split) * 2 + b) * 1024) * 256;
    int row0 = ocb + wm * 32 + gq;
    int col0 = ntile * 128 + wn * 64 + 2 * tq;
#pragma unroll
    for (int mi = 0; mi < 2; mi++)
#pragma unroll
        for (int ni = 0; ni < 8; ni++) {
            int r = row0 + mi * 16;
            int cc = col0 + ni * 8;
            *(float2*)(zbase + (size_t)r * 256 + cc)       = make_float2(acc[mi][ni][0], acc[mi][ni][1]);
            *(float2*)(zbase + (size_t)(r + 8) * 256 + cc) = make_float2(acc[mi][ni][2], acc[mi][ni][3]);
        }
}

// ---------------------------------------------------------------------------
// Pipelined gates: both layers in one launch (1024 CTAs).
// ---------------------------------------------------------------------------
__global__ void __launch_bounds__(256) lstm_gates_pair(int k,
                                                       const float* __restrict__ lb0,
                                                       const float* __restrict__ lb1,
                                                       float* __restrict__ out)
{
    int gid = blockIdx.x * 256 + threadIdx.x;  // 262144
    int layer = gid >> 17;
    int idx = gid & 131071;
    int t = layer ? (k - 1) : k;
    if (t < 0 || t > 15) return;

    int inner = idx & 65535;
    int b = idx >> 16;
    int c = inner >> 8;
    int pos = inner & 255;
    const float* lb = layer ? lb1 : lb0;

    float zi = lb[c], zf = lb[c + 256], zo = lb[c + 512], zg = lb[c + 768];
#pragma unroll
    for (int s = 0; s < 4; s++) {
        const float* zb = g_zp + ((size_t)((layer * 4 + s) * 2 + b)) * 1024 * 256;
        zi += zb[(size_t)(c)       * 256 + pos];
        zf += zb[(size_t)(c + 256) * 256 + pos];
        zo += zb[(size_t)(c + 512) * 256 + pos];
        zg += zb[(size_t)(c + 768) * 256 + pos];
    }

    size_t cidx = (size_t)layer * 131072 + idx;
    float cn = sigmoidf_(zf) * g_c[cidx] + sigmoidf_(zi) * tanhf(zg);
    float hn = sigmoidf_(zo) * tanhf(cn);
    g_c[cidx] = cn;

    __half hh = __float2half(hn);
    __half hl = __float2half(hn - __half2float(hh));
    int y = pos >> 4, x = pos & 15;
    __half* bhhp = g_bhh + (size_t)(layer * 2 + b) * BHS;
    __half* bhlp = g_bhl + (size_t)(layer * 2 + b) * BHS;
    __half* bxhp = g_bx1h + (size_t)(t * 2 + b) * BHS;
    __half* bxlp = g_bx1l + (size_t)(t * 2 + b) * BHS;
#pragma unroll
    for (int s = 0; s < 9; s++) {
        int dy = s / 3 - 1, dx = s % 3 - 1;
        int ny = y - dy, nx = x - dx;
        if (ny >= 0 && ny < 16 && nx >= 0 && nx < 16) {
            int o = ((s * 256 + c) << 8) + ny * 16 + nx;
            bhhp[o] = hh;
            bhlp[o] = hl;
            if (layer == 0) { bxhp[o] = hh; bxlp[o] = hl; }
        }
    }

    if (layer == 1)
        out[(size_t)b * 16 * CHW2 + (size_t)t * CHW2 + inner] = hn;
}

// zero c (both layers) and h im2col buffers (both layers)
__global__ void __launch_bounds__(256) zero_state()
{
    int idx = blockIdx.x * 256 + threadIdx.x;   // 2359296 = 2*2*BHS
    if (idx < 262144) g_c[idx] = 0.f;
    g_bhh[idx] = __float2half(0.f);
    g_bhl[idx] = __float2half(0.f);
}

__global__ void __launch_bounds__(256) copy_last(float* __restrict__ out)
{
    int idx = blockIdx.x * 256 + threadIdx.x;
    int inner = idx & 65535;
    int b = idx >> 16;
    out[2097152 + idx] = out[(size_t)b * 16 * CHW2 + 15 * CHW2 + inner];
}

// ---------------------------------------------------------------------------
// Launch sequence (graph-capturable)
// ---------------------------------------------------------------------------
extern "C" void kernel_launch(void* const* d_in, const int* in_sizes, int n_in,
                              void* d_out, int out_size)
{
    const float* x   = (const float*)d_in[0];
    const float* w0  = (const float*)d_in[1];
    const float* b0  = (const float*)d_in[2];
    const float* g0  = (const float*)d_in[3];
    const float* be0 = (const float*)d_in[4];
    const float* m0  = (const float*)d_in[5];
    const float* v0  = (const float*)d_in[6];
    const float* w1  = (const float*)d_in[7];
    const float* b1  = (const float*)d_in[8];
    const float* g1  = (const float*)d_in[9];
    const float* be1 = (const float*)d_in[10];
    const float* m1  = (const float*)d_in[11];
    const float* v1  = (const float*)d_in[12];
    const float* w2  = (const float*)d_in[13];
    const float* b2  = (const float*)d_in[14];
    const float* g2  = (const float*)d_in[15];
    const float* be2 = (const float*)d_in[16];
    const float* m2  = (const float*)d_in[17];
    const float* v2  = (const float*)d_in[18];
    const float* lw0 = (const float*)d_in[19];
    const float* lb0 = (const float*)d_in[20];
    const float* lw1 = (const float*)d_in[21];
    const float* lb1 = (const float*)d_in[22];
    float* out = (float*)d_out;

    float* f0ptr;  cudaGetSymbolAddress((void**)&f0ptr, g_f0);
    float* f1ptr;  cudaGetSymbolAddress((void**)&f1ptr, g_f1);
    float* f2ptr;  cudaGetSymbolAddress((void**)&f2ptr, g_f2);
    float* preptr; cudaGetSymbolAddress((void**)&preptr, g_pre);
    __half* wc1h; cudaGetSymbolAddress((void**)&wc1h, g_wc1h);
    __half* wc1l; cudaGetSymbolAddress((void**)&wc1l, g_wc1l);
    __half* wc2h; cudaGetSymbolAddress((void**)&wc2h, g_wc2h);
    __half* wc2l; cudaGetSymbolAddress((void**)&wc2l, g_wc2l);

    // weight prepacks (K16 layout)
    prepack_w<<<18432, 256>>>(lw0, 0);
    prepack_w<<<18432, 256>>>(lw1, 1);
    prepack_cw<64, 128><<<288, 256>>>(w1, wc1h, wc1l);
    prepack_cw<128, 256><<<1152, 256>>>(w2, wc2h, wc2l);

    // CNN encoder
    conv0_pool<<<32768, 256>>>(x, w0, b0, g0, be0, m0, v0);
    conv_mma<64, 64, 128><<<dim3(32, 1, 32), 256>>>(f0ptr, wc1h, wc1l,
                                                    b1, g1, be1, m1, v1, preptr);
    pool2<128, 64><<<16384, 256>>>(preptr, f1ptr);
    conv_mma<128, 32, 256><<<dim3(8, 2, 32), 256>>>(f1ptr, wc2h, wc2l,
                                                    b2, g2, be2, m2, v2, preptr);
    pool2<256, 32><<<8192, 256>>>(preptr, f2ptr);

    // hi/lo fp16 im2col of CNN features
    build_bx0<<<73728, 256>>>();

    // Pipelined ConvLSTM: step k = L0(t=k) + L1(t=k-1)
    zero_state<<<9216, 256>>>();
    for (int k = 0; k <= 16; k++) {
        lstm_mma_pair<<<dim3(8, 4, 8), 256>>>(k);
        lstm_gates_pair<<<1024, 256>>>(k, lb0, lb1, out);
    }

    copy_last<<<512, 256>>>(out);
}

// round 12
// speedup vs baseline: 1.6182x; 1.0281x over previous
#include <cuda_runtime.h>
#include <cuda_fp16.h>
#include <math.h>
#include <stdint.h>

// ---------------------------------------------------------------------------
//   block0: 1->64 SIMT; block1/2 + ConvLSTM convs: 3xFP16 mma.sync GEMM
//   (D += Ah*Bh + Ah*Bl + Al*Bh), K=16 chunks, double buffer.
// ConvLSTM layers software-pipelined: step k runs L0(t=k) and L1(t=k-1).
// MMA kernels forced to 2 CTAs/SM (launch_bounds(256,2)) with per-ni2
// B-fragment loading to stay under the 128-reg cap.
// ---------------------------------------------------------------------------

#define CHW2 65536          // 256*16*16
#define BHS  589824         // 9*256*256

typedef unsigned long long ull;

// ============================ PTX helpers ==================================
__device__ __forceinline__ uint32_t smem_u32(const void* p) {
    uint32_t a;
    asm("{ .reg .u64 t; cvta.to.shared.u64 t, %1; cvt.u32.u64 %0, t; }" : "=r"(a) : "l"(p));
    return a;
}
__device__ __forceinline__ void ldm_x4(uint32_t* r, uint32_t addr) {
    asm volatile("ldmatrix.sync.aligned.m8n8.x4.shared.b16 {%0,%1,%2,%3}, [%4];"
        : "=r"(r[0]), "=r"(r[1]), "=r"(r[2]), "=r"(r[3]) : "r"(addr));
}
__device__ __forceinline__ void ldm_x4t(uint32_t* r, uint32_t addr) {
    asm volatile("ldmatrix.sync.aligned.m8n8.x4.trans.shared.b16 {%0,%1,%2,%3}, [%4];"
        : "=r"(r[0]), "=r"(r[1]), "=r"(r[2]), "=r"(r[3]) : "r"(addr));
}
__device__ __forceinline__ void mma16816(float* d, const uint32_t* a, const uint32_t* b) {
    asm volatile(
        "mma.sync.aligned.m16n8k16.row.col.f32.f16.f16.f32 "
        "{%0,%1,%2,%3}, {%4,%5,%6,%7}, {%8,%9}, {%0,%1,%2,%3};"
        : "+f"(d[0]), "+f"(d[1]), "+f"(d[2]), "+f"(d[3])
        : "r"(a[0]), "r"(a[1]), "r"(a[2]), "r"(a[3]), "r"(b[0]), "r"(b[1]));
}
__device__ __forceinline__ void cp16(uint32_t sdst, const void* gsrc) {
    asm volatile("cp.async.cg.shared.global [%0], [%1], 16;" :: "r"(sdst), "l"(gsrc));
}
__device__ __forceinline__ void cp_commit() { asm volatile("cp.async.commit_group;"); }
template <int N> __device__ __forceinline__ void cp_wait() {
    asm volatile("cp.async.wait_group %0;" :: "n"(N));
}
__device__ __forceinline__ float sigmoidf_(float x) { return 1.0f / (1.0f + expf(-x)); }

// ---------------------------------------------------------------------------
// Scratch (per-layer LSTM state duplicated for pipelining)
// ---------------------------------------------------------------------------
__device__ __align__(256) float  g_f0[32 * 64 * 64 * 64];
__device__ __align__(256) float  g_f1[32 * 128 * 32 * 32];
__device__ __align__(256) float  g_f2[32 * 256 * 16 * 16];
__device__ __align__(256) float  g_pre[32 * 128 * 64 * 64];
__device__ __align__(256) __half g_wc1h[36 * 128 * 16];
__device__ __align__(256) __half g_wc1l[36 * 128 * 16];
__device__ __align__(256) __half g_wc2h[72 * 256 * 16];
__device__ __align__(256) __half g_wc2l[72 * 256 * 16];
__device__ __align__(256) __half g_wph[2 * 288 * 1024 * 16];  // [layer][G][oc][16]
__device__ __align__(256) __half g_wpl[2 * 288 * 1024 * 16];
__device__ __align__(256) __half g_bx0h[32 * BHS];            // L0 x im2col [(t*2+b)][s][c][n]
__device__ __align__(256) __half g_bx0l[32 * BHS];
__device__ __align__(256) __half g_bx1h[32 * BHS];            // L1 x im2col
__device__ __align__(256) __half g_bx1l[32 * BHS];
__device__ __align__(256) __half g_bhh[2 * 2 * BHS];          // h im2col [layer][b][s][c][n]
__device__ __align__(256) __half g_bhl[2 * 2 * BHS];
__device__ __align__(256) float  g_c[2 * 2 * CHW2];           // cell state [layer][b][...]
__device__ __align__(256) float  g_zp[2 * 4 * 2 * 1024 * 256];// partials [layer][split][b][oc][pos]

// ---------------------------------------------------------------------------
// LSTM weight prepack: fp32 -> hi/lo fp16 in [layer][G][oc][16]
// ---------------------------------------------------------------------------
__global__ void __launch_bounds__(256) prepack_w(const float* __restrict__ lw, int layer)
{
    int idx = blockIdx.x * 256 + threadIdx.x;  // 4718592
    int u  = idx & 15;
    int oc = (idx >> 4) & 1023;
    int G  = idx >> 14;
    int k  = G * 16 + u;
    int s  = k >> 9;
    int c  = k & 511;
    float w = lw[((size_t)oc * 512 + c) * 9 + s];
    __half hi = __float2half(w);
    size_t o = (size_t)layer * 4718592 + idx;
    g_wph[o] = hi;
    g_wpl[o] = __float2half(w - __half2float(hi));
}

// ---------------------------------------------------------------------------
// CNN conv weight prepack: [G][oc][16]
// ---------------------------------------------------------------------------
template <int CIN, int OCTOT>
__global__ void __launch_bounds__(256) prepack_cw(
    const float* __restrict__ w, __half* __restrict__ outh, __half* __restrict__ outl)
{
    constexpr int CPG = CIN / 16;
    int idx = blockIdx.x * 256 + threadIdx.x;
    int u  = idx & 15;
    int oc = (idx >> 4) % OCTOT;
    int G  = (idx >> 4) / OCTOT;
    int s  = G / CPG;
    int c  = (G % CPG) * 16 + u;
    float val = w[((size_t)oc * CIN + c) * 9 + s];
    __half hi = __float2half(val);
    outh[idx] = hi;
    outl[idx] = __float2half(val - __half2float(hi));
}

// ---------------------------------------------------------------------------
// Build layer0 x im2col (hi/lo). 32*BHS elements.
// ---------------------------------------------------------------------------
__global__ void __launch_bounds__(256) build_bx0()
{
    int idx = blockIdx.x * 256 + threadIdx.x;   // < 18874368
    int n   = idx & 255;
    int c   = (idx >> 8) & 255;
    int rem = idx >> 16;
    int s   = rem % 9;
    int tb  = rem / 9;
    int t   = tb >> 1, b = tb & 1;
    int dy  = s / 3 - 1, dx = s % 3 - 1;
    int iy  = (n >> 4) + dy, ix = (n & 15) + dx;
    float val = 0.f;
    if (iy >= 0 && iy < 16 && ix >= 0 && ix < 16)
        val = g_f2[(((size_t)(b * 16 + t) * 256 + c) << 8) + iy * 16 + ix];
    __half hi = __float2half(val);
    g_bx0h[idx] = hi;
    g_bx0l[idx] = __float2half(val - __half2float(hi));
}

// ---------------------------------------------------------------------------
// Block 0 SIMT conv+pool
// ---------------------------------------------------------------------------
__global__ void __launch_bounds__(256) conv0_pool(
    const float* __restrict__ x, const float* __restrict__ w,
    const float* __restrict__ bias, const float* __restrict__ g,
    const float* __restrict__ be, const float* __restrict__ m,
    const float* __restrict__ v)
{
    int idx = blockIdx.x * 256 + threadIdx.x;
    int pw = idx & 63;
    int ph = (idx >> 6) & 63;
    int oc = (idx >> 12) & 63;
    int n  = idx >> 18;

    float wr[9];
#pragma unroll
    for (int k = 0; k < 9; k++) wr[k] = w[oc * 9 + k];
    float s  = g[oc] * rsqrtf(v[oc] + 1e-5f);
    float cb = (bias[oc] - m[oc]) * s + be[oc];

    const float* xi = x + n * 16384;
    float mx = -1e30f;
#pragma unroll
    for (int dy0 = 0; dy0 < 2; dy0++) {
#pragma unroll
        for (int dx0 = 0; dx0 < 2; dx0++) {
            int oy = 2 * ph + dy0, ox = 2 * pw + dx0;
            float sum = 0.f;
#pragma unroll
            for (int ky = 0; ky < 3; ky++) {
                int iy = oy - 1 + ky;
                if (iy < 0 || iy >= 128) continue;
#pragma unroll
                for (int kx = 0; kx < 3; kx++) {
                    int ix = ox - 1 + kx;
                    if (ix < 0 || ix >= 128) continue;
                    sum = fmaf(xi[iy * 128 + ix], wr[ky * 3 + kx], sum);
                }
            }
            float y = fmaxf(fmaf(sum, s, cb), 0.f);
            mx = fmaxf(mx, y);
        }
    }
    g_f0[idx] = mx;
}

// ---------------------------------------------------------------------------
// CNN conv via 3xFP16 GEMM, K=16 chunks, on-the-fly shifted im2col.
// 2 CTAs/SM; B fragments loaded per-ni2 group (low reg pressure).
// ---------------------------------------------------------------------------
template <int CIN, int S, int OCTOT>
__global__ void __launch_bounds__(256, 2) conv_mma(
    const float* __restrict__ in,
    const __half* __restrict__ wph, const __half* __restrict__ wpl,
    const float* __restrict__ bias, const float* __restrict__ g,
    const float* __restrict__ be, const float* __restrict__ m,
    const float* __restrict__ v, float* __restrict__ pre)
{
    constexpr int NPOS = S * S;
    constexpr int CPG  = CIN / 16;
    constexpr int NG   = 9 * CPG;
    constexpr int LOGS = (S == 64) ? 6 : 5;

    __shared__ __align__(16) __half Ah[2][128 * 24];
    __shared__ __align__(16) __half Al[2][128 * 24];
    __shared__ __align__(16) __half Bh[2][16 * 136];
    __shared__ __align__(16) __half Bl[2][16 * 136];
    __shared__ float ssc[128], sbi[128];

    int tid = threadIdx.x, lane = tid & 31, wid = tid >> 5;
    int wm = wid & 3, wn = wid >> 2;
    int ntile = blockIdx.x;
    int ocb   = blockIdx.y * 128;
    int frame = blockIdx.z;

    if (tid < 128) {
        int oc = ocb + tid;
        float s_ = g[oc] * rsqrtf(v[oc] + 1e-5f);
        ssc[tid] = s_;
        sbi[tid] = (bias[oc] - m[oc]) * s_ + be[oc];
    }

    int arow = tid >> 1, au = tid & 1;
    uint32_t ao = arow * 48 + au * 16;
    uint32_t ah_dst[2] = { smem_u32(&Ah[0][0]) + ao, smem_u32(&Ah[1][0]) + ao };
    uint32_t al_dst[2] = { smem_u32(&Al[0][0]) + ao, smem_u32(&Al[1][0]) + ao };
    size_t a_off_elem = (size_t)(ocb + arow) * 16 + au * 8;

    int bk = tid >> 4, bn = tid & 15;
    int nbase = ntile * 128 + bn * 8;

    float breg[8];
    auto prefetchB = [&](int G) {
        int s = G / CPG, q = G - s * CPG;
        int dy = s / 3 - 1, dx = s % 3 - 1;
        const float* src = in + ((size_t)frame * CIN + q * 16 + bk) * NPOS;
#pragma unroll
        for (int j = 0; j < 8; j++) {
            int pos = nbase + j;
            int y = pos >> LOGS, x = pos & (S - 1);
            int iy = y + dy, ix = x + dx;
            breg[j] = (iy >= 0 && iy < S && ix >= 0 && ix < S) ? src[iy * S + ix] : 0.f;
        }
    };
    auto stsB = [&](int buf) {
        __half hv[8], lv[8];
#pragma unroll
        for (int j = 0; j < 8; j++) {
            hv[j] = __float2half(breg[j]);
            lv[j] = __float2half(breg[j] - __half2float(hv[j]));
        }
        *(uint4*)&Bh[buf][bk * 136 + bn * 8] = *(uint4*)hv;
        *(uint4*)&Bl[buf][bk * 136 + bn * 8] = *(uint4*)lv;
    };
    auto cpA = [&](int G, int buf) {
        cp16(ah_dst[buf], wph + (size_t)G * (OCTOT * 16) + a_off_elem);
        cp16(al_dst[buf], wpl + (size_t)G * (OCTOT * 16) + a_off_elem);
        cp_commit();
    };

    int quad = lane >> 3, l7 = lane & 7;
    uint32_t a_off[2], b_off[4];
    {
        int rsub = ((quad & 1) << 3) + l7;
        int ksub = (quad >> 1) << 4;
#pragma unroll
        for (int mi = 0; mi < 2; mi++)
            a_off[mi] = (uint32_t)((wm * 32 + mi * 16 + rsub) * 48 + ksub);
        int krow = ((quad & 1) << 3) + l7;
        int nsub = (quad >> 1) << 3;
#pragma unroll
        for (int ni2 = 0; ni2 < 4; ni2++)
            b_off[ni2] = (uint32_t)(krow * 272 + (wn * 64 + ni2 * 16 + nsub) * 2);
    }
    uint32_t ahb[2] = { smem_u32(&Ah[0][0]), smem_u32(&Ah[1][0]) };
    uint32_t alb[2] = { smem_u32(&Al[0][0]), smem_u32(&Al[1][0]) };
    uint32_t bhb[2] = { smem_u32(&Bh[0][0]), smem_u32(&Bh[1][0]) };
    uint32_t blb[2] = { smem_u32(&Bl[0][0]), smem_u32(&Bl[1][0]) };

    float acc[2][8][4];
#pragma unroll
    for (int mi = 0; mi < 2; mi++)
#pragma unroll
        for (int ni = 0; ni < 8; ni++)
#pragma unroll
            for (int q = 0; q < 4; q++) acc[mi][ni][q] = 0.f;

    prefetchB(0); stsB(0); cpA(0, 0);
    prefetchB(1); stsB(1); cpA(1, 1);
    if (NG > 2) prefetchB(2);

    for (int j = 0; j < NG; j++) {
        if (j < NG - 1) cp_wait<1>(); else cp_wait<0>();
        __syncthreads();

        int buf = j & 1;
        uint32_t ah[2][4], al[2][4];
#pragma unroll
        for (int mi = 0; mi < 2; mi++) {
            ldm_x4(ah[mi], ahb[buf] + a_off[mi]);
            ldm_x4(al[mi], alb[buf] + a_off[mi]);
        }
#pragma unroll
        for (int ni2 = 0; ni2 < 4; ni2++) {
            uint32_t bhf[4], blf[4];
            ldm_x4t(bhf, bhb[buf] + b_off[ni2]);
            ldm_x4t(blf, blb[buf] + b_off[ni2]);
#pragma unroll
            for (int mi = 0; mi < 2; mi++)
#pragma unroll
                for (int q = 0; q < 2; q++) {
                    float* a_ = acc[mi][ni2 * 2 + q];
                    mma16816(a_, ah[mi], &bhf[q * 2]);
                    mma16816(a_, ah[mi], &blf[q * 2]);
                    mma16816(a_, al[mi], &bhf[q * 2]);
                }
        }
        __syncthreads();

        if (j + 2 < NG) {
            stsB(buf);
            cpA(j + 2, buf);
            if (j + 3 < NG) prefetchB(j + 3);
        }
    }

    int gq = lane >> 2, tq = lane & 3;
    int row0 = wm * 32 + gq;
    int colb = ntile * 128 + wn * 64 + 2 * tq;
#pragma unroll
    for (int mi = 0; mi < 2; mi++)
#pragma unroll
        for (int ni = 0; ni < 8; ni++) {
            int r0 = row0 + mi * 16;
            int col = colb + ni * 8;
#pragma unroll
            for (int h = 0; h < 2; h++) {
                int r = r0 + h * 8;
                float sc = ssc[r], sh = sbi[r];
                float v0 = fmaxf(fmaf(acc[mi][ni][2 * h],     sc, sh), 0.f);
                float v1 = fmaxf(fmaf(acc[mi][ni][2 * h + 1], sc, sh), 0.f);
                *(float2*)(pre + ((size_t)frame * OCTOT + ocb + r) * NPOS + col)
                    = make_float2(v0, v1);
            }
        }
}

// ---------------------------------------------------------------------------
// 2x2 maxpool
// ---------------------------------------------------------------------------
template <int OC, int S>
__global__ void __launch_bounds__(256) pool2(const float* __restrict__ pre,
                                             float* __restrict__ out)
{
    constexpr int HP = S / 2;
    int idx = blockIdx.x * 256 + threadIdx.x;
    int pw = idx % HP;
    int t1 = idx / HP;
    int ph = t1 % HP;
    int t2 = t1 / HP;
    const float* p = pre + (size_t)t2 * S * S + (2 * ph) * S + 2 * pw;
    float a = p[0], b = p[1], c = p[S], d = p[S + 1];
    out[idx] = fmaxf(fmaxf(a, b), fmaxf(c, d));
}

// ---------------------------------------------------------------------------
// Pipelined ConvLSTM MMA: step k runs L0(t=k) and L1(t=k-1).
// Grid (8, 4, 8), 256 threads, 2 CTAs/SM.
// ---------------------------------------------------------------------------
__global__ void __launch_bounds__(256, 2) lstm_mma_pair(int k)
{
    int layer = blockIdx.z >> 2;
    int split = blockIdx.z & 3;
    int t = layer ? (k - 1) : k;
    if (t < 0 || t > 15) return;

    __shared__ __align__(16) __half Ah[2][128 * 24];
    __shared__ __align__(16) __half Al[2][128 * 24];
    __shared__ __align__(16) __half Bh[2][16 * 136];
    __shared__ __align__(16) __half Bl[2][16 * 136];

    int tid  = threadIdx.x;
    int lane = tid & 31;
    int wid  = tid >> 5;
    int wm = wid & 3, wn = wid >> 2;

    int mtile = blockIdx.x;
    int ntile = blockIdx.y & 1;
    int b     = blockIdx.y >> 1;
    int ocb   = mtile * 128;

    size_t slab = (size_t)(t * 2 + b) * BHS;
    const __half* bxh = (layer ? g_bx1h : g_bx0h) + slab;
    const __half* bxl = (layer ? g_bx1l : g_bx0l) + slab;
    const __half* bhh = g_bhh + (size_t)(layer * 2 + b) * BHS;
    const __half* bhl = g_bhl + (size_t)(layer * 2 + b) * BHS;
    const __half* wph = g_wph + (size_t)layer * 4718592;
    const __half* wpl = g_wpl + (size_t)layer * 4718592;

    int arow = tid >> 1, au = tid & 1;
    uint32_t ao = arow * 48 + au * 16;
    uint32_t ah_dst[2] = { smem_u32(&Ah[0][0]) + ao, smem_u32(&Ah[1][0]) + ao };
    uint32_t al_dst[2] = { smem_u32(&Al[0][0]) + ao, smem_u32(&Al[1][0]) + ao };
    uint32_t bo = (tid >> 4) * 272 + (tid & 15) * 16;
    uint32_t bh_dst[2] = { smem_u32(&Bh[0][0]) + bo, smem_u32(&Bh[1][0]) + bo };
    uint32_t bl_dst[2] = { smem_u32(&Bl[0][0]) + bo, smem_u32(&Bl[1][0]) + bo };
    size_t a_off_elem = (size_t)(arow + ocb) * 16 + au * 8;
    int b_src_off = (tid >> 4) * 256 + ntile * 128 + (tid & 15) * 8;

    int quad = lane >> 3, l7 = lane & 7;
    uint32_t a_off[2], b_off[4];
    {
        int rsub = ((quad & 1) << 3) + l7;
        int ksub = (quad >> 1) << 4;
#pragma unroll
        for (int mi = 0; mi < 2; mi++)
            a_off[mi] = (uint32_t)((wm * 32 + mi * 16 + rsub) * 48 + ksub);
        int krow = ((quad & 1) << 3) + l7;
        int nsub = (quad >> 1) << 3;
#pragma unroll
        for (int ni2 = 0; ni2 < 4; ni2++)
            b_off[ni2] = (uint32_t)(krow * 272 + (wn * 64 + ni2 * 16 + nsub) * 2);
    }
    uint32_t ahb[2] = { smem_u32(&Ah[0][0]), smem_u32(&Ah[1][0]) };
    uint32_t alb[2] = { smem_u32(&Al[0][0]), smem_u32(&Al[1][0]) };
    uint32_t bhb[2] = { smem_u32(&Bh[0][0]), smem_u32(&Bh[1][0]) };
    uint32_t blb[2] = { smem_u32(&Bl[0][0]), smem_u32(&Bl[1][0]) };

    float acc[2][8][4];
#pragma unroll
    for (int mi = 0; mi < 2; mi++)
#pragma unroll
        for (int ni = 0; ni < 8; ni++)
#pragma unroll
            for (int q = 0; q < 4; q++) acc[mi][ni][q] = 0.f;

    auto stage = [&](int j, int buf) {
        int G  = split * 72 + j;
        int s  = G >> 5;
        int c0 = (G & 31) << 4;
        bool xh = (c0 < 256);
        size_t srow = ((size_t)(s * 256 + (xh ? c0 : c0 - 256)) << 8);
        const __half* bsh = (xh ? bxh : bhh) + srow;
        const __half* bsl = (xh ? bxl : bhl) + srow;
        cp16(ah_dst[buf], wph + (size_t)G * 16384 + a_off_elem);
        cp16(al_dst[buf], wpl + (size_t)G * 16384 + a_off_elem);
        cp16(bh_dst[buf], bsh + b_src_off);
        cp16(bl_dst[buf], bsl + b_src_off);
        cp_commit();
    };

    stage(0, 0);
    stage(1, 1);

    for (int j = 0; j < 72; j++) {
        if (j < 71) cp_wait<1>(); else cp_wait<0>();
        __syncthreads();

        int buf = j & 1;
        uint32_t ah[2][4], al[2][4];
#pragma unroll
        for (int mi = 0; mi < 2; mi++) {
            ldm_x4(ah[mi], ahb[buf] + a_off[mi]);
            ldm_x4(al[mi], alb[buf] + a_off[mi]);
        }
#pragma unroll
        for (int ni2 = 0; ni2 < 4; ni2++) {
            uint32_t bhf[4], blf[4];
            ldm_x4t(bhf, bhb[buf] + b_off[ni2]);
            ldm_x4t(blf, blb[buf] + b_off[ni2]);
#pragma unroll
            for (int mi = 0; mi < 2; mi++)
#pragma unroll
                for (int q = 0; q < 2; q++) {
                    float* a_ = acc[mi][ni2 * 2 + q];
                    mma16816(a_, ah[mi], &bhf[q * 2]);
                    mma16816(a_, ah[mi], &blf[q * 2]);
                    mma16816(a_, al[mi], &bhf[q * 2]);
                }
        }

        __syncthreads();
        if (j + 2 < 72) stage(j + 2, buf);
    }

    int gq = lane >> 2, tq = lane & 3;
    float* zbase = g_zp + ((size_t)((layer * 4 + split) * 2 + b) * 1024) * 256;
    int row0 = ocb + wm * 32 + gq;
    int col0 = ntile * 128 + wn * 64 + 2 * tq;
#pragma unroll
    for (int mi = 0; mi < 2; mi++)
#pragma unroll
        for (int ni = 0; ni < 8; ni++) {
            int r = row0 + mi * 16;
            int cc = col0 + ni * 8;
            *(float2*)(zbase + (size_t)r * 256 + cc)       = make_float2(acc[mi][ni][0], acc[mi][ni][1]);
            *(float2*)(zbase + (size_t)(r + 8) * 256 + cc) = make_float2(acc[mi][ni][2], acc[mi][ni][3]);
        }
}

// ---------------------------------------------------------------------------
// Pipelined gates: both layers in one launch (1024 CTAs).
// ---------------------------------------------------------------------------
__global__ void __launch_bounds__(256) lstm_gates_pair(int k,
                                                       const float* __restrict__ lb0,
                                                       const float* __restrict__ lb1,
                                                       float* __restrict__ out)
{
    int gid = blockIdx.x * 256 + threadIdx.x;  // 262144
    int layer = gid >> 17;
    int idx = gid & 131071;
    int t = layer ? (k - 1) : k;
    if (t < 0 || t > 15) return;

    int inner = idx & 65535;
    int b = idx >> 16;
    int c = inner >> 8;
    int pos = inner & 255;
    const float* lb = layer ? lb1 : lb0;

    float zi = lb[c], zf = lb[c + 256], zo = lb[c + 512], zg = lb[c + 768];
#pragma unroll
    for (int s = 0; s < 4; s++) {
        const float* zb = g_zp + ((size_t)((layer * 4 + s) * 2 + b)) * 1024 * 256;
        zi += zb[(size_t)(c)       * 256 + pos];
        zf += zb[(size_t)(c + 256) * 256 + pos];
        zo += zb[(size_t)(c + 512) * 256 + pos];
        zg += zb[(size_t)(c + 768) * 256 + pos];
    }

    size_t cidx = (size_t)layer * 131072 + idx;
    float cn = sigmoidf_(zf) * g_c[cidx] + sigmoidf_(zi) * tanhf(zg);
    float hn = sigmoidf_(zo) * tanhf(cn);
    g_c[cidx] = cn;

    __half hh = __float2half(hn);
    __half hl = __float2half(hn - __half2float(hh));
    int y = pos >> 4, x = pos & 15;
    __half* bhhp = g_bhh + (size_t)(layer * 2 + b) * BHS;
    __half* bhlp = g_bhl + (size_t)(layer * 2 + b) * BHS;
    __half* bxhp = g_bx1h + (size_t)(t * 2 + b) * BHS;
    __half* bxlp = g_bx1l + (size_t)(t * 2 + b) * BHS;
#pragma unroll
    for (int s = 0; s < 9; s++) {
        int dy = s / 3 - 1, dx = s % 3 - 1;
        int ny = y - dy, nx = x - dx;
        if (ny >= 0 && ny < 16 && nx >= 0 && nx < 16) {
            int o = ((s * 256 + c) << 8) + ny * 16 + nx;
            bhhp[o] = hh;
            bhlp[o] = hl;
            if (layer == 0) { bxhp[o] = hh; bxlp[o] = hl; }
        }
    }

    if (layer == 1)
        out[(size_t)b * 16 * CHW2 + (size_t)t * CHW2 + inner] = hn;
}

// zero c (both layers) and h im2col buffers (both layers)
__global__ void __launch_bounds__(256) zero_state()
{
    int idx = blockIdx.x * 256 + threadIdx.x;   // 2359296 = 2*2*BHS
    if (idx < 262144) g_c[idx] = 0.f;
    g_bhh[idx] = __float2half(0.f);
    g_bhl[idx] = __float2half(0.f);
}

__global__ void __launch_bounds__(256) copy_last(float* __restrict__ out)
{
    int idx = blockIdx.x * 256 + threadIdx.x;
    int inner = idx & 65535;
    int b = idx >> 16;
    out[2097152 + idx] = out[(size_t)b * 16 * CHW2 + 15 * CHW2 + inner];
}

// ---------------------------------------------------------------------------
// Launch sequence (graph-capturable)
// ---------------------------------------------------------------------------
extern "C" void kernel_launch(void* const* d_in, const int* in_sizes, int n_in,
                              void* d_out, int out_size)
{
    const float* x   = (const float*)d_in[0];
    const float* w0  = (const float*)d_in[1];
    const float* b0  = (const float*)d_in[2];
    const float* g0  = (const float*)d_in[3];
    const float* be0 = (const float*)d_in[4];
    const float* m0  = (const float*)d_in[5];
    const float* v0  = (const float*)d_in[6];
    const float* w1  = (const float*)d_in[7];
    const float* b1  = (const float*)d_in[8];
    const float* g1  = (const float*)d_in[9];
    const float* be1 = (const float*)d_in[10];
    const float* m1  = (const float*)d_in[11];
    const float* v1  = (const float*)d_in[12];
    const float* w2  = (const float*)d_in[13];
    const float* b2  = (const float*)d_in[14];
    const float* g2  = (const float*)d_in[15];
    const float* be2 = (const float*)d_in[16];
    const float* m2  = (const float*)d_in[17];
    const float* v2  = (const float*)d_in[18];
    const float* lw0 = (const float*)d_in[19];
    const float* lb0 = (const float*)d_in[20];
    const float* lw1 = (const float*)d_in[21];
    const float* lb1 = (const float*)d_in[22];
    float* out = (float*)d_out;

    float* f0ptr;  cudaGetSymbolAddress((void**)&f0ptr, g_f0);
    float* f1ptr;  cudaGetSymbolAddress((void**)&f1ptr, g_f1);
    float* f2ptr;  cudaGetSymbolAddress((void**)&f2ptr, g_f2);
    float* preptr; cudaGetSymbolAddress((void**)&preptr, g_pre);
    __half* wc1h; cudaGetSymbolAddress((void**)&wc1h, g_wc1h);
    __half* wc1l; cudaGetSymbolAddress((void**)&wc1l, g_wc1l);
    __half* wc2h; cudaGetSymbolAddress((void**)&wc2h, g_wc2h);
    __half* wc2l; cudaGetSymbolAddress((void**)&wc2l, g_wc2l);

    // weight prepacks (K16 layout)
    prepack_w<<<18432, 256>>>(lw0, 0);
    prepack_w<<<18432, 256>>>(lw1, 1);
    prepack_cw<64, 128><<<288, 256>>>(w1, wc1h, wc1l);
    prepack_cw<128, 256><<<1152, 256>>>(w2, wc2h, wc2l);

    // CNN encoder
    conv0_pool<<<32768, 256>>>(x, w0, b0, g0, be0, m0, v0);
    conv_mma<64, 64, 128><<<dim3(32, 1, 32), 256>>>(f0ptr, wc1h, wc1l,
                                                    b1, g1, be1, m1, v1, preptr);
    pool2<128, 64><<<16384, 256>>>(preptr, f1ptr);
    conv_mma<128, 32, 256><<<dim3(8, 2, 32), 256>>>(f1ptr, wc2h, wc2l,
                                                    b2, g2, be2, m2, v2, preptr);
    pool2<256, 32><<<8192, 256>>>(preptr, f2ptr);

    // hi/lo fp16 im2col of CNN features
    build_bx0<<<73728, 256>>>();

    // Pipelined ConvLSTM: step k = L0(t=k) + L1(t=k-1)
    zero_state<<<9216, 256>>>();
    for (int k = 0; k <= 16; k++) {
        lstm_mma_pair<<<dim3(8, 4, 8), 256>>>(k);
        lstm_gates_pair<<<1024, 256>>>(k, lb0, lb1, out);
    }

    copy_last<<<512, 256>>>(out);
}

// round 13
// speedup vs baseline: 1.6233x; 1.0031x over previous
#include <cuda_runtime.h>
#include <cuda_fp16.h>
#include <math.h>
#include <stdint.h>

// ---------------------------------------------------------------------------
//   block0: 1->64 SIMT; block1/2 + ConvLSTM convs: 3xFP16 mma.sync GEMM
//   (D += Ah*Bh + Ah*Bl + Al*Bh), K=16 chunks, double buffer.
// ConvLSTM layers software-pipelined: step k runs L0(t=k) and L1(t=k-1).
// conv_mma has the 2x2 maxpool FUSED into its epilogue (no pre-pool buffer).
// ---------------------------------------------------------------------------

#define CHW2 65536          // 256*16*16
#define BHS  589824         // 9*256*256

typedef unsigned long long ull;

// ============================ PTX helpers ==================================
__device__ __forceinline__ uint32_t smem_u32(const void* p) {
    uint32_t a;
    asm("{ .reg .u64 t; cvta.to.shared.u64 t, %1; cvt.u32.u64 %0, t; }" : "=r"(a) : "l"(p));
    return a;
}
__device__ __forceinline__ void ldm_x4(uint32_t* r, uint32_t addr) {
    asm volatile("ldmatrix.sync.aligned.m8n8.x4.shared.b16 {%0,%1,%2,%3}, [%4];"
        : "=r"(r[0]), "=r"(r[1]), "=r"(r[2]), "=r"(r[3]) : "r"(addr));
}
__device__ __forceinline__ void ldm_x4t(uint32_t* r, uint32_t addr) {
    asm volatile("ldmatrix.sync.aligned.m8n8.x4.trans.shared.b16 {%0,%1,%2,%3}, [%4];"
        : "=r"(r[0]), "=r"(r[1]), "=r"(r[2]), "=r"(r[3]) : "r"(addr));
}
__device__ __forceinline__ void mma16816(float* d, const uint32_t* a, const uint32_t* b) {
    asm volatile(
        "mma.sync.aligned.m16n8k16.row.col.f32.f16.f16.f32 "
        "{%0,%1,%2,%3}, {%4,%5,%6,%7}, {%8,%9}, {%0,%1,%2,%3};"
        : "+f"(d[0]), "+f"(d[1]), "+f"(d[2]), "+f"(d[3])
        : "r"(a[0]), "r"(a[1]), "r"(a[2]), "r"(a[3]), "r"(b[0]), "r"(b[1]));
}
__device__ __forceinline__ void cp16(uint32_t sdst, const void* gsrc) {
    asm volatile("cp.async.cg.shared.global [%0], [%1], 16;" :: "r"(sdst), "l"(gsrc));
}
__device__ __forceinline__ void cp_commit() { asm volatile("cp.async.commit_group;"); }
template <int N> __device__ __forceinline__ void cp_wait() {
    asm volatile("cp.async.wait_group %0;" :: "n"(N));
}
__device__ __forceinline__ float sigmoidf_(float x) { return 1.0f / (1.0f + expf(-x)); }

// ---------------------------------------------------------------------------
// Scratch
// ---------------------------------------------------------------------------
__device__ __align__(256) float  g_f0[32 * 64 * 64 * 64];
__device__ __align__(256) float  g_f1[32 * 128 * 32 * 32];
__device__ __align__(256) float  g_f2[32 * 256 * 16 * 16];
__device__ __align__(256) __half g_wc1h[36 * 128 * 16];
__device__ __align__(256) __half g_wc1l[36 * 128 * 16];
__device__ __align__(256) __half g_wc2h[72 * 256 * 16];
__device__ __align__(256) __half g_wc2l[72 * 256 * 16];
__device__ __align__(256) __half g_wph[2 * 288 * 1024 * 16];  // [layer][G][oc][16]
__device__ __align__(256) __half g_wpl[2 * 288 * 1024 * 16];
__device__ __align__(256) __half g_bx0h[32 * BHS];            // L0 x im2col [(t*2+b)][s][c][n]
__device__ __align__(256) __half g_bx0l[32 * BHS];
__device__ __align__(256) __half g_bx1h[32 * BHS];            // L1 x im2col
__device__ __align__(256) __half g_bx1l[32 * BHS];
__device__ __align__(256) __half g_bhh[2 * 2 * BHS];          // h im2col [layer][b][s][c][n]
__device__ __align__(256) __half g_bhl[2 * 2 * BHS];
__device__ __align__(256) float  g_c[2 * 2 * CHW2];           // cell state [layer][b]
__device__ __align__(256) float  g_zp[2 * 4 * 2 * 1024 * 256];// partials [layer][split][b][oc][pos]

// ---------------------------------------------------------------------------
// LSTM weight prepack (coalesced transpose): one oc per CTA, both layers.
// lw[oc][c][s] (9 contiguous s) -> g_wp[layer][G][oc][16], k = s*512+c.
// ---------------------------------------------------------------------------
__global__ void __launch_bounds__(256) prepack_w2(const float* __restrict__ lw0,
                                                  const float* __restrict__ lw1)
{
    __shared__ float wbuf[4608];
    int oc = blockIdx.x;
    int layer = blockIdx.y;
    const float* lw = layer ? lw1 : lw0;
    int tid = threadIdx.x;

    for (int i = tid; i < 4608; i += 256)
        wbuf[i] = lw[(size_t)oc * 4608 + i];     // [c][s], c*9+s
    __syncthreads();

    size_t base = (size_t)layer * 4718592;
    for (int k = tid; k < 4608; k += 256) {
        int s = k >> 9, c = k & 511;
        float w = wbuf[c * 9 + s];
        __half hi = __float2half(w);
        size_t o = base + ((size_t)(k >> 4) * 1024 + oc) * 16 + (k & 15);
        g_wph[o] = hi;
        g_wpl[o] = __float2half(w - __half2float(hi));
    }
}

// ---------------------------------------------------------------------------
// CNN conv weight prepack: [G][oc][16]
// ---------------------------------------------------------------------------
template <int CIN, int OCTOT>
__global__ void __launch_bounds__(256) prepack_cw(
    const float* __restrict__ w, __half* __restrict__ outh, __half* __restrict__ outl)
{
    constexpr int CPG = CIN / 16;
    int idx = blockIdx.x * 256 + threadIdx.x;
    int u  = idx & 15;
    int oc = (idx >> 4) % OCTOT;
    int G  = (idx >> 4) / OCTOT;
    int s  = G / CPG;
    int c  = (G % CPG) * 16 + u;
    float val = w[((size_t)oc * CIN + c) * 9 + s];
    __half hi = __float2half(val);
    outh[idx] = hi;
    outl[idx] = __float2half(val - __half2float(hi));
}

// ---------------------------------------------------------------------------
// Build layer0 x im2col (hi/lo). 32*BHS elements.
// ---------------------------------------------------------------------------
__global__ void __launch_bounds__(256) build_bx0()
{
    int idx = blockIdx.x * 256 + threadIdx.x;   // < 18874368
    int n   = idx & 255;
    int c   = (idx >> 8) & 255;
    int rem = idx >> 16;
    int s   = rem % 9;
    int tb  = rem / 9;
    int t   = tb >> 1, b = tb & 1;
    int dy  = s / 3 - 1, dx = s % 3 - 1;
    int iy  = (n >> 4) + dy, ix = (n & 15) + dx;
    float val = 0.f;
    if (iy >= 0 && iy < 16 && ix >= 0 && ix < 16)
        val = g_f2[(((size_t)(b * 16 + t) * 256 + c) << 8) + iy * 16 + ix];
    __half hi = __float2half(val);
    g_bx0h[idx] = hi;
    g_bx0l[idx] = __float2half(val - __half2float(hi));
}

// ---------------------------------------------------------------------------
// Block 0 SIMT conv+pool
// ---------------------------------------------------------------------------
__global__ void __launch_bounds__(256) conv0_pool(
    const float* __restrict__ x, const float* __restrict__ w,
    const float* __restrict__ bias, const float* __restrict__ g,
    const float* __restrict__ be, const float* __restrict__ m,
    const float* __restrict__ v)
{
    int idx = blockIdx.x * 256 + threadIdx.x;
    int pw = idx & 63;
    int ph = (idx >> 6) & 63;
    int oc = (idx >> 12) & 63;
    int n  = idx >> 18;

    float wr[9];
#pragma unroll
    for (int k = 0; k < 9; k++) wr[k] = w[oc * 9 + k];
    float s  = g[oc] * rsqrtf(v[oc] + 1e-5f);
    float cb = (bias[oc] - m[oc]) * s + be[oc];

    const float* xi = x + n * 16384;
    float mx = -1e30f;
#pragma unroll
    for (int dy0 = 0; dy0 < 2; dy0++) {
#pragma unroll
        for (int dx0 = 0; dx0 < 2; dx0++) {
            int oy = 2 * ph + dy0, ox = 2 * pw + dx0;
            float sum = 0.f;
#pragma unroll
            for (int ky = 0; ky < 3; ky++) {
                int iy = oy - 1 + ky;
                if (iy < 0 || iy >= 128) continue;
#pragma unroll
                for (int kx = 0; kx < 3; kx++) {
                    int ix = ox - 1 + kx;
                    if (ix < 0 || ix >= 128) continue;
                    sum = fmaf(xi[iy * 128 + ix], wr[ky * 3 + kx], sum);
                }
            }
            float y = fmaxf(fmaf(sum, s, cb), 0.f);
            mx = fmaxf(mx, y);
        }
    }
    g_f0[idx] = mx;
}

// ---------------------------------------------------------------------------
// CNN conv via 3xFP16 GEMM, K=16 chunks, on-the-fly shifted im2col.
// 2x2 maxpool FUSED into epilogue; pooled output written directly.
//   S=64: N-tile = 128 pos = 2 image rows; vertical pool via smem exchange
//         (reuses the dead A/B staging buffers).
//   S=32: N-tile = 128 pos = 4 image rows; pool entirely in-thread.
// ---------------------------------------------------------------------------
template <int CIN, int S, int OCTOT>
__global__ void __launch_bounds__(256, 2) conv_mma(
    const float* __restrict__ in,
    const __half* __restrict__ wph, const __half* __restrict__ wpl,
    const float* __restrict__ bias, const float* __restrict__ g,
    const float* __restrict__ be, const float* __restrict__ m,
    const float* __restrict__ v, float* __restrict__ out)
{
    constexpr int NPOS = S * S;
    constexpr int CPG  = CIN / 16;
    constexpr int NG   = 9 * CPG;
    constexpr int LOGS = (S == 64) ? 6 : 5;

    // A/B staging buffers live in one aliasable byte arena (41984 B);
    // the S=64 epilogue reuses it as a 32 KB fp32 pool-exchange buffer.
    __shared__ __align__(16) char smbuf[41984];
    __half* Ah = (__half*)smbuf;                   // [2][128*24]
    __half* Al = (__half*)(smbuf + 12288);
    __half* Bh = (__half*)(smbuf + 24576);         // [2][16*136]
    __half* Bl = (__half*)(smbuf + 33280);
    __shared__ float ssc[128], sbi[128];

    int tid = threadIdx.x, lane = tid & 31, wid = tid >> 5;
    int wm = wid & 3, wn = wid >> 2;
    int ntile = blockIdx.x;
    int ocb   = blockIdx.y * 128;
    int frame = blockIdx.z;

    if (tid < 128) {
        int oc = ocb + tid;
        float s_ = g[oc] * rsqrtf(v[oc] + 1e-5f);
        ssc[tid] = s_;
        sbi[tid] = (bias[oc] - m[oc]) * s_ + be[oc];
    }

    int arow = tid >> 1, au = tid & 1;
    uint32_t ao = arow * 48 + au * 16;
    uint32_t ah_dst[2] = { smem_u32(Ah) + ao, smem_u32(Ah + 3072) + ao };
    uint32_t al_dst[2] = { smem_u32(Al) + ao, smem_u32(Al + 3072) + ao };
    size_t a_off_elem = (size_t)(ocb + arow) * 16 + au * 8;

    int bk = tid >> 4, bn = tid & 15;
    int nbase = ntile * 128 + bn * 8;

    float breg[8];
    auto prefetchB = [&](int G) {
        int s = G / CPG, q = G - s * CPG;
        int dy = s / 3 - 1, dx = s % 3 - 1;
        const float* src = in + ((size_t)frame * CIN + q * 16 + bk) * NPOS;
#pragma unroll
        for (int j = 0; j < 8; j++) {
            int pos = nbase + j;
            int y = pos >> LOGS, x = pos & (S - 1);
            int iy = y + dy, ix = x + dx;
            breg[j] = (iy >= 0 && iy < S && ix >= 0 && ix < S) ? src[iy * S + ix] : 0.f;
        }
    };
    auto stsB = [&](int buf) {
        __half hv[8], lv[8];
#pragma unroll
        for (int j = 0; j < 8; j++) {
            hv[j] = __float2half(breg[j]);
            lv[j] = __float2half(breg[j] - __half2float(hv[j]));
        }
        *(uint4*)&Bh[buf * 2176 + bk * 136 + bn * 8] = *(uint4*)hv;
        *(uint4*)&Bl[buf * 2176 + bk * 136 + bn * 8] = *(uint4*)lv;
    };
    auto cpA = [&](int G, int buf) {
        cp16(ah_dst[buf], wph + (size_t)G * (OCTOT * 16) + a_off_elem);
        cp16(al_dst[buf], wpl + (size_t)G * (OCTOT * 16) + a_off_elem);
        cp_commit();
    };

    int quad = lane >> 3, l7 = lane & 7;
    uint32_t a_off[2], b_off[4];
    {
        int rsub = ((quad & 1) << 3) + l7;
        int ksub = (quad >> 1) << 4;
#pragma unroll
        for (int mi = 0; mi < 2; mi++)
            a_off[mi] = (uint32_t)((wm * 32 + mi * 16 + rsub) * 48 + ksub);
        int krow = ((quad & 1) << 3) + l7;
        int nsub = (quad >> 1) << 3;
#pragma unroll
        for (int ni2 = 0; ni2 < 4; ni2++)
            b_off[ni2] = (uint32_t)(krow * 272 + (wn * 64 + ni2 * 16 + nsub) * 2);
    }
    uint32_t ahb[2] = { smem_u32(Ah), smem_u32(Ah + 3072) };
    uint32_t alb[2] = { smem_u32(Al), smem_u32(Al + 3072) };
    uint32_t bhb[2] = { smem_u32(Bh), smem_u32(Bh + 2176) };
    uint32_t blb[2] = { smem_u32(Bl), smem_u32(Bl + 2176) };

    float acc[2][8][4];
#pragma unroll
    for (int mi = 0; mi < 2; mi++)
#pragma unroll
        for (int ni = 0; ni < 8; ni++)
#pragma unroll
            for (int q = 0; q < 4; q++) acc[mi][ni][q] = 0.f;

    prefetchB(0); stsB(0); cpA(0, 0);
    prefetchB(1); stsB(1); cpA(1, 1);
    if (NG > 2) prefetchB(2);

    for (int j = 0; j < NG; j++) {
        if (j < NG - 1) cp_wait<1>(); else cp_wait<0>();
        __syncthreads();

        int buf = j & 1;
        uint32_t ah[2][4], al[2][4];
#pragma unroll
        for (int mi = 0; mi < 2; mi++) {
            ldm_x4(ah[mi], ahb[buf] + a_off[mi]);
            ldm_x4(al[mi], alb[buf] + a_off[mi]);
        }
#pragma unroll
        for (int ni2 = 0; ni2 < 4; ni2++) {
            uint32_t bhf[4], blf[4];
            ldm_x4t(bhf, bhb[buf] + b_off[ni2]);
            ldm_x4t(blf, blb[buf] + b_off[ni2]);
#pragma unroll
            for (int mi = 0; mi < 2; mi++)
#pragma unroll
                for (int q = 0; q < 2; q++) {
                    float* a_ = acc[mi][ni2 * 2 + q];
                    mma16816(a_, ah[mi], &bhf[q * 2]);
                    mma16816(a_, ah[mi], &blf[q * 2]);
                    mma16816(a_, al[mi], &bhf[q * 2]);
                }
        }
        __syncthreads();

        if (j + 2 < NG) {
            stsB(buf);
            cpA(j + 2, buf);
            if (j + 3 < NG) prefetchB(j + 3);
        }
    }

    // ---- fused epilogue: BN + ReLU + 2x2 maxpool -> pooled output ----
    int gq = lane >> 2, tq = lane & 3;
    if (S == 64) {
        // h-pool in registers, v-pool via smem (rows 2*ntile / 2*ntile+1 by wn)
        float* pbuf = (float*)smbuf;       // [128 oc][2 wn][32 xh] = 32 KB
#pragma unroll
        for (int mi = 0; mi < 2; mi++)
#pragma unroll
            for (int h = 0; h < 2; h++) {
                int r = wm * 32 + mi * 16 + h * 8 + gq;
                float sc = ssc[r], sh = sbi[r];
#pragma unroll
                for (int ni = 0; ni < 8; ni++) {
                    float v0 = fmaxf(fmaf(acc[mi][ni][2 * h],     sc, sh), 0.f);
                    float v1 = fmaxf(fmaf(acc[mi][ni][2 * h + 1], sc, sh), 0.f);
                    pbuf[r * 64 + wn * 32 + ni * 4 + tq] = fmaxf(v0, v1);
                }
            }
        __syncthreads();
        const int HP = 32;
        for (int i = tid; i < 128 * 32; i += 256) {
            int oc = i >> 5, xh = i & 31;
            float vv = fmaxf(pbuf[oc * 64 + xh], pbuf[oc * 64 + 32 + xh]);
            out[((size_t)(frame * OCTOT + ocb + oc) * HP + ntile) * HP + xh] = vv;
        }
    } else {
        // S==32: pool partners (ni, ni+4) live in the same thread
        const int HP = 16;
#pragma unroll
        for (int mi = 0; mi < 2; mi++)
#pragma unroll
            for (int h = 0; h < 2; h++) {
                int r = wm * 32 + mi * 16 + h * 8 + gq;
                float sc = ssc[r], sh = sbi[r];
#pragma unroll
                for (int n4 = 0; n4 < 4; n4++) {
                    float a0 = fmaxf(fmaf(acc[mi][n4][2 * h],         sc, sh), 0.f);
                    float a1 = fmaxf(fmaf(acc[mi][n4][2 * h + 1],     sc, sh), 0.f);
                    float b0 = fmaxf(fmaf(acc[mi][n4 + 4][2 * h],     sc, sh), 0.f);
                    float b1 = fmaxf(fmaf(acc[mi][n4 + 4][2 * h + 1], sc, sh), 0.f);
                    float mx = fmaxf(fmaxf(a0, a1), fmaxf(b0, b1));
                    int yq = ntile * 2 + wn;
                    int xq = n4 * 4 + tq;
                    out[((size_t)(frame * OCTOT + ocb + r) * HP + yq) * HP + xq] = mx;
                }
            }
    }
}

// ---------------------------------------------------------------------------
// Pipelined ConvLSTM MMA: step k runs L0(t=k) and L1(t=k-1).
// Grid (8, 4, 8), 256 threads, 2 CTAs/SM.
// ---------------------------------------------------------------------------
__global__ void __launch_bounds__(256, 2) lstm_mma_pair(int k)
{
    int layer = blockIdx.z >> 2;
    int split = blockIdx.z & 3;
    int t = layer ? (k - 1) : k;
    if (t < 0 || t > 15) return;

    __shared__ __align__(16) __half Ah[2][128 * 24];
    __shared__ __align__(16) __half Al[2][128 * 24];
    __shared__ __align__(16) __half Bh[2][16 * 136];
    __shared__ __align__(16) __half Bl[2][16 * 136];

    int tid  = threadIdx.x;
    int lane = tid & 31;
    int wid  = tid >> 5;
    int wm = wid & 3, wn = wid >> 2;

    int mtile = blockIdx.x;
    int ntile = blockIdx.y & 1;
    int b     = blockIdx.y >> 1;
    int ocb   = mtile * 128;

    size_t slab = (size_t)(t * 2 + b) * BHS;
    const __half* bxh = (layer ? g_bx1h : g_bx0h) + slab;
    const __half* bxl = (layer ? g_bx1l : g_bx0l) + slab;
    const __half* bhh = g_bhh + (size_t)(layer * 2 + b) * BHS;
    const __half* bhl = g_bhl + (size_t)(layer * 2 + b) * BHS;
    const __half* wph = g_wph + (size_t)layer * 4718592;
    const __half* wpl = g_wpl + (size_t)layer * 4718592;

    int arow = tid >> 1, au = tid & 1;
    uint32_t ao = arow * 48 + au * 16;
    uint32_t ah_dst[2] = { smem_u32(&Ah[0][0]) + ao, smem_u32(&Ah[1][0]) + ao };
    uint32_t al_dst[2] = { smem_u32(&Al[0][0]) + ao, smem_u32(&Al[1][0]) + ao };
    uint32_t bo = (tid >> 4) * 272 + (tid & 15) * 16;
    uint32_t bh_dst[2] = { smem_u32(&Bh[0][0]) + bo, smem_u32(&Bh[1][0]) + bo };
    uint32_t bl_dst[2] = { smem_u32(&Bl[0][0]) + bo, smem_u32(&Bl[1][0]) + bo };
    size_t a_off_elem = (size_t)(arow + ocb) * 16 + au * 8;
    int b_src_off = (tid >> 4) * 256 + ntile * 128 + (tid & 15) * 8;

    int quad = lane >> 3, l7 = lane & 7;
    uint32_t a_off[2], b_off[4];
    {
        int rsub = ((quad & 1) << 3) + l7;
        int ksub = (quad >> 1) << 4;
#pragma unroll
        for (int mi = 0; mi < 2; mi++)
            a_off[mi] = (uint32_t)((wm * 32 + mi * 16 + rsub) * 48 + ksub);
        int krow = ((quad & 1) << 3) + l7;
        int nsub = (quad >> 1) << 3;
#pragma unroll
        for (int ni2 = 0; ni2 < 4; ni2++)
            b_off[ni2] = (uint32_t)(krow * 272 + (wn * 64 + ni2 * 16 + nsub) * 2);
    }
    uint32_t ahb[2] = { smem_u32(&Ah[0][0]), smem_u32(&Ah[1][0]) };
    uint32_t alb[2] = { smem_u32(&Al[0][0]), smem_u32(&Al[1][0]) };
    uint32_t bhb[2] = { smem_u32(&Bh[0][0]), smem_u32(&Bh[1][0]) };
    uint32_t blb[2] = { smem_u32(&Bl[0][0]), smem_u32(&Bl[1][0]) };

    float acc[2][8][4];
#pragma unroll
    for (int mi = 0; mi < 2; mi++)
#pragma unroll
        for (int ni = 0; ni < 8; ni++)
#pragma unroll
            for (int q = 0; q < 4; q++) acc[mi][ni][q] = 0.f;

    auto stage = [&](int j, int buf) {
        int G  = split * 72 + j;
        int s  = G >> 5;
        int c0 = (G & 31) << 4;
        bool xh = (c0 < 256);
        size_t srow = ((size_t)(s * 256 + (xh ? c0 : c0 - 256)) << 8);
        const __half* bsh = (xh ? bxh : bhh) + srow;
        const __half* bsl = (xh ? bxl : bhl) + srow;
        cp16(ah_dst[buf], wph + (size_t)G * 16384 + a_off_elem);
        cp16(al_dst[buf], wpl + (size_t)G * 16384 + a_off_elem);
        cp16(bh_dst[buf], bsh + b_src_off);
        cp16(bl_dst[buf], bsl + b_src_off);
        cp_commit();
    };

    stage(0, 0);
    stage(1, 1);

    for (int j = 0; j < 72; j++) {
        if (j < 71) cp_wait<1>(); else cp_wait<0>();
        __syncthreads();

        int buf = j & 1;
        uint32_t ah[2][4], al[2][4];
#pragma unroll
        for (int mi = 0; mi < 2; mi++) {
            ldm_x4(ah[mi], ahb[buf] + a_off[mi]);
            ldm_x4(al[mi], alb[buf] + a_off[mi]);
        }
#pragma unroll
        for (int ni2 = 0; ni2 < 4; ni2++) {
            uint32_t bhf[4], blf[4];
            ldm_x4t(bhf, bhb[buf] + b_off[ni2]);
            ldm_x4t(blf, blb[buf] + b_off[ni2]);
#pragma unroll
            for (int mi = 0; mi < 2; mi++)
#pragma unroll
                for (int q = 0; q < 2; q++) {
                    float* a_ = acc[mi][ni2 * 2 + q];
                    mma16816(a_, ah[mi], &bhf[q * 2]);
                    mma16816(a_, ah[mi], &blf[q * 2]);
                    mma16816(a_, al[mi], &bhf[q * 2]);
                }
        }

        __syncthreads();
        if (j + 2 < 72) stage(j + 2, buf);
    }

    int gq = lane >> 2, tq = lane & 3;
    float* zbase = g_zp + ((size_t)((layer * 4 + split) * 2 + b) * 1024) * 256;
    int row0 = ocb + wm * 32 + gq;
    int col0 = ntile * 128 + wn * 64 + 2 * tq;
#pragma unroll
    for (int mi = 0; mi < 2; mi++)
#pragma unroll
        for (int ni = 0; ni < 8; ni++) {
            int r = row0 + mi * 16;
            int cc = col0 + ni * 8;
            *(float2*)(zbase + (size_t)r * 256 + cc)       = make_float2(acc[mi][ni][0], acc[mi][ni][1]);
            *(float2*)(zbase + (size_t)(r + 8) * 256 + cc) = make_float2(acc[mi][ni][2], acc[mi][ni][3]);
        }
}

// ---------------------------------------------------------------------------
// Pipelined gates: both layers in one launch (1024 CTAs).
// ---------------------------------------------------------------------------
__global__ void __launch_bounds__(256) lstm_gates_pair(int k,
                                                       const float* __restrict__ lb0,
                                                       const float* __restrict__ lb1,
                                                       float* __restrict__ out)
{
    int gid = blockIdx.x * 256 + threadIdx.x;  // 262144
    int layer = gid >> 17;
    int idx = gid & 131071;
    int t = layer ? (k - 1) : k;
    if (t < 0 || t > 15) return;

    int inner = idx & 65535;
    int b = idx >> 16;
    int c = inner >> 8;
    int pos = inner & 255;
    const float* lb = layer ? lb1 : lb0;

    float zi = lb[c], zf = lb[c + 256], zo = lb[c + 512], zg = lb[c + 768];
#pragma unroll
    for (int s = 0; s < 4; s++) {
        const float* zb = g_zp + ((size_t)((layer * 4 + s) * 2 + b)) * 1024 * 256;
        zi += zb[(size_t)(c)       * 256 + pos];
        zf += zb[(size_t)(c + 256) * 256 + pos];
        zo += zb[(size_t)(c + 512) * 256 + pos];
        zg += zb[(size_t)(c + 768) * 256 + pos];
    }

    size_t cidx = (size_t)layer * 131072 + idx;
    float cn = sigmoidf_(zf) * g_c[cidx] + sigmoidf_(zi) * tanhf(zg);
    float hn = sigmoidf_(zo) * tanhf(cn);
    g_c[cidx] = cn;

    __half hh = __float2half(hn);
    __half hl = __float2half(hn - __half2float(hh));
    int y = pos >> 4, x = pos & 15;
    __half* bhhp = g_bhh + (size_t)(layer * 2 + b) * BHS;
    __half* bhlp = g_bhl + (size_t)(layer * 2 + b) * BHS;
    __half* bxhp = g_bx1h + (size_t)(t * 2 + b) * BHS;
    __half* bxlp = g_bx1l + (size_t)(t * 2 + b) * BHS;
#pragma unroll
    for (int s = 0; s < 9; s++) {
        int dy = s / 3 - 1, dx = s % 3 - 1;
        int ny = y - dy, nx = x - dx;
        if (ny >= 0 && ny < 16 && nx >= 0 && nx < 16) {
            int o = ((s * 256 + c) << 8) + ny * 16 + nx;
            bhhp[o] = hh;
            bhlp[o] = hl;
            if (layer == 0) { bxhp[o] = hh; bxlp[o] = hl; }
        }
    }

    if (layer == 1)
        out[(size_t)b * 16 * CHW2 + (size_t)t * CHW2 + inner] = hn;
}

// zero c (both layers) and h im2col buffers (both layers)
__global__ void __launch_bounds__(256) zero_state()
{
    int idx = blockIdx.x * 256 + threadIdx.x;   // 2359296 = 2*2*BHS
    if (idx < 262144) g_c[idx] = 0.f;
    g_bhh[idx] = __float2half(0.f);
    g_bhl[idx] = __float2half(0.f);
}

__global__ void __launch_bounds__(256) copy_last(float* __restrict__ out)
{
    int idx = blockIdx.x * 256 + threadIdx.x;
    int inner = idx & 65535;
    int b = idx >> 16;
    out[2097152 + idx] = out[(size_t)b * 16 * CHW2 + 15 * CHW2 + inner];
}

// ---------------------------------------------------------------------------
// Launch sequence (graph-capturable)
// ---------------------------------------------------------------------------
extern "C" void kernel_launch(void* const* d_in, const int* in_sizes, int n_in,
                              void* d_out, int out_size)
{
    const float* x   = (const float*)d_in[0];
    const float* w0  = (const float*)d_in[1];
    const float* b0  = (const float*)d_in[2];
    const float* g0  = (const float*)d_in[3];
    const float* be0 = (const float*)d_in[4];
    const float* m0  = (const float*)d_in[5];
    const float* v0  = (const float*)d_in[6];
    const float* w1  = (const float*)d_in[7];
    const float* b1  = (const float*)d_in[8];
    const float* g1  = (const float*)d_in[9];
    const float* be1 = (const float*)d_in[10];
    const float* m1  = (const float*)d_in[11];
    const float* v1  = (const float*)d_in[12];
    const float* w2  = (const float*)d_in[13];
    const float* b2  = (const float*)d_in[14];
    const float* g2  = (const float*)d_in[15];
    const float* be2 = (const float*)d_in[16];
    const float* m2  = (const float*)d_in[17];
    const float* v2  = (const float*)d_in[18];
    const float* lw0 = (const float*)d_in[19];
    const float* lb0 = (const float*)d_in[20];
    const float* lw1 = (const float*)d_in[21];
    const float* lb1 = (const float*)d_in[22];
    float* out = (float*)d_out;

    float* f0ptr;  cudaGetSymbolAddress((void**)&f0ptr, g_f0);
    float* f1ptr;  cudaGetSymbolAddress((void**)&f1ptr, g_f1);
    float* f2ptr;  cudaGetSymbolAddress((void**)&f2ptr, g_f2);
    __half* wc1h; cudaGetSymbolAddress((void**)&wc1h, g_wc1h);
    __half* wc1l; cudaGetSymbolAddress((void**)&wc1l, g_wc1l);
    __half* wc2h; cudaGetSymbolAddress((void**)&wc2h, g_wc2h);
    __half* wc2l; cudaGetSymbolAddress((void**)&wc2l, g_wc2l);

    // weight prepacks
    prepack_w2<<<dim3(1024, 2), 256>>>(lw0, lw1);
    prepack_cw<64, 128><<<288, 256>>>(w1, wc1h, wc1l);
    prepack_cw<128, 256><<<1152, 256>>>(w2, wc2h, wc2l);

    // CNN encoder (pool fused into conv_mma epilogue)
    conv0_pool<<<32768, 256>>>(x, w0, b0, g0, be0, m0, v0);
    conv_mma<64, 64, 128><<<dim3(32, 1, 32), 256>>>(f0ptr, wc1h, wc1l,
                                                    b1, g1, be1, m1, v1, f1ptr);
    conv_mma<128, 32, 256><<<dim3(8, 2, 32), 256>>>(f1ptr, wc2h, wc2l,
                                                    b2, g2, be2, m2, v2, f2ptr);

    // hi/lo fp16 im2col of CNN features
    build_bx0<<<73728, 256>>>();

    // Pipelined ConvLSTM: step k = L0(t=k) + L1(t=k-1)
    zero_state<<<9216, 256>>>();
    for (int k = 0; k <= 16; k++) {
        lstm_mma_pair<<<dim3(8, 4, 8), 256>>>(k);
        lstm_gates_pair<<<1024, 256>>>(k, lb0, lb1, out);
    }

    copy_last<<<512, 256>>>(out);
}

// round 14
// speedup vs baseline: 1.7274x; 1.0641x over previous
#include <cuda_runtime.h>
#include <cuda_fp16.h>
#include <math.h>
#include <stdint.h>

// ---------------------------------------------------------------------------
//   block0: 1->64 SIMT; block1/2 + ConvLSTM convs: 3xFP16 mma.sync GEMM
//   (D += Ah*Bh + Ah*Bl + Al*Bh), K=16 chunks, double buffer.
// ConvLSTM layers software-pipelined: step k runs L0(t=k) and L1(t=k-1).
//   - L0's x-half GEMM hoisted out of the loop (Zx0 precompute, all 32 slabs)
//   - L1's x-input read directly from L0's bh buffer (no bx1 materialization)
//   - in-loop splits rebalanced: every CTA does 48 K-chunks (L0 3, L1 6)
// ---------------------------------------------------------------------------

#define CHW2 65536          // 256*16*16
#define BHS  589824         // 9*256*256

typedef unsigned long long ull;

// ============================ PTX helpers ==================================
__device__ __forceinline__ uint32_t smem_u32(const void* p) {
    uint32_t a;
    asm("{ .reg .u64 t; cvta.to.shared.u64 t, %1; cvt.u32.u64 %0, t; }" : "=r"(a) : "l"(p));
    return a;
}
__device__ __forceinline__ void ldm_x4(uint32_t* r, uint32_t addr) {
    asm volatile("ldmatrix.sync.aligned.m8n8.x4.shared.b16 {%0,%1,%2,%3}, [%4];"
        : "=r"(r[0]), "=r"(r[1]), "=r"(r[2]), "=r"(r[3]) : "r"(addr));
}
__device__ __forceinline__ void ldm_x4t(uint32_t* r, uint32_t addr) {
    asm volatile("ldmatrix.sync.aligned.m8n8.x4.trans.shared.b16 {%0,%1,%2,%3}, [%4];"
        : "=r"(r[0]), "=r"(r[1]), "=r"(r[2]), "=r"(r[3]) : "r"(addr));
}
__device__ __forceinline__ void mma16816(float* d, const uint32_t* a, const uint32_t* b) {
    asm volatile(
        "mma.sync.aligned.m16n8k16.row.col.f32.f16.f16.f32 "
        "{%0,%1,%2,%3}, {%4,%5,%6,%7}, {%8,%9}, {%0,%1,%2,%3};"
        : "+f"(d[0]), "+f"(d[1]), "+f"(d[2]), "+f"(d[3])
        : "r"(a[0]), "r"(a[1]), "r"(a[2]), "r"(a[3]), "r"(b[0]), "r"(b[1]));
}
__device__ __forceinline__ void cp16(uint32_t sdst, const void* gsrc) {
    asm volatile("cp.async.cg.shared.global [%0], [%1], 16;" :: "r"(sdst), "l"(gsrc));
}
__device__ __forceinline__ void cp_commit() { asm volatile("cp.async.commit_group;"); }
template <int N> __device__ __forceinline__ void cp_wait() {
    asm volatile("cp.async.wait_group %0;" :: "n"(N));
}
__device__ __forceinline__ float sigmoidf_(float x) { return 1.0f / (1.0f + expf(-x)); }

// ---------------------------------------------------------------------------
// Scratch
// ---------------------------------------------------------------------------
__device__ __align__(256) float  g_f0[32 * 64 * 64 * 64];
__device__ __align__(256) float  g_f1[32 * 128 * 32 * 32];
__device__ __align__(256) float  g_f2[32 * 256 * 16 * 16];
__device__ __align__(256) __half g_wc1h[36 * 128 * 16];
__device__ __align__(256) __half g_wc1l[36 * 128 * 16];
__device__ __align__(256) __half g_wc2h[72 * 256 * 16];
__device__ __align__(256) __half g_wc2l[72 * 256 * 16];
__device__ __align__(256) __half g_wph[2 * 288 * 1024 * 16];  // [layer][G][oc][16]
__device__ __align__(256) __half g_wpl[2 * 288 * 1024 * 16];
__device__ __align__(256) __half g_bx0h[32 * BHS];            // L0 x im2col [(t*2+b)][s][c][n]
__device__ __align__(256) __half g_bx0l[32 * BHS];
__device__ __align__(256) __half g_bhh[2 * 2 * BHS];          // h im2col [layer][b][s][c][n]
__device__ __align__(256) __half g_bhl[2 * 2 * BHS];
__device__ __align__(256) float  g_c[2 * 2 * CHW2];           // cell state [layer][b]
__device__ __align__(256) float  g_zx0[32 * 1024 * 256];      // hoisted L0 x-half GEMM
__device__ __align__(256) float  g_zp[9 * 2 * 1024 * 256];    // partials [slot][b][oc][pos]

// ---------------------------------------------------------------------------
// LSTM weight prepack (coalesced transpose): one oc per CTA, both layers.
// ---------------------------------------------------------------------------
__global__ void __launch_bounds__(256) prepack_w2(const float* __restrict__ lw0,
                                                  const float* __restrict__ lw1)
{
    __shared__ float wbuf[4608];
    int oc = blockIdx.x;
    int layer = blockIdx.y;
    const float* lw = layer ? lw1 : lw0;
    int tid = threadIdx.x;

    for (int i = tid; i < 4608; i += 256)
        wbuf[i] = lw[(size_t)oc * 4608 + i];     // [c][s]
    __syncthreads();

    size_t base = (size_t)layer * 4718592;
    for (int k = tid; k < 4608; k += 256) {
        int s = k >> 9, c = k & 511;
        float w = wbuf[c * 9 + s];
        __half hi = __float2half(w);
        size_t o = base + ((size_t)(k >> 4) * 1024 + oc) * 16 + (k & 15);
        g_wph[o] = hi;
        g_wpl[o] = __float2half(w - __half2float(hi));
    }
}

// ---------------------------------------------------------------------------
// CNN conv weight prepack: [G][oc][16]
// ---------------------------------------------------------------------------
template <int CIN, int OCTOT>
__global__ void __launch_bounds__(256) prepack_cw(
    const float* __restrict__ w, __half* __restrict__ outh, __half* __restrict__ outl)
{
    constexpr int CPG = CIN / 16;
    int idx = blockIdx.x * 256 + threadIdx.x;
    int u  = idx & 15;
    int oc = (idx >> 4) % OCTOT;
    int G  = (idx >> 4) / OCTOT;
    int s  = G / CPG;
    int c  = (G % CPG) * 16 + u;
    float val = w[((size_t)oc * CIN + c) * 9 + s];
    __half hi = __float2half(val);
    outh[idx] = hi;
    outl[idx] = __float2half(val - __half2float(hi));
}

// ---------------------------------------------------------------------------
// Build layer0 x im2col (hi/lo). 32*BHS elements.
// ---------------------------------------------------------------------------
__global__ void __launch_bounds__(256) build_bx0()
{
    int idx = blockIdx.x * 256 + threadIdx.x;   // < 18874368
    int n   = idx & 255;
    int c   = (idx >> 8) & 255;
    int rem = idx >> 16;
    int s   = rem % 9;
    int tb  = rem / 9;
    int t   = tb >> 1, b = tb & 1;
    int dy  = s / 3 - 1, dx = s % 3 - 1;
    int iy  = (n >> 4) + dy, ix = (n & 15) + dx;
    float val = 0.f;
    if (iy >= 0 && iy < 16 && ix >= 0 && ix < 16)
        val = g_f2[(((size_t)(b * 16 + t) * 256 + c) << 8) + iy * 16 + ix];
    __half hi = __float2half(val);
    g_bx0h[idx] = hi;
    g_bx0l[idx] = __float2half(val - __half2float(hi));
}

// ---------------------------------------------------------------------------
// Block 0 SIMT conv+pool
// ---------------------------------------------------------------------------
__global__ void __launch_bounds__(256) conv0_pool(
    const float* __restrict__ x, const float* __restrict__ w,
    const float* __restrict__ bias, const float* __restrict__ g,
    const float* __restrict__ be, const float* __restrict__ m,
    const float* __restrict__ v)
{
    int idx = blockIdx.x * 256 + threadIdx.x;
    int pw = idx & 63;
    int ph = (idx >> 6) & 63;
    int oc = (idx >> 12) & 63;
    int n  = idx >> 18;

    float wr[9];
#pragma unroll
    for (int k = 0; k < 9; k++) wr[k] = w[oc * 9 + k];
    float s  = g[oc] * rsqrtf(v[oc] + 1e-5f);
    float cb = (bias[oc] - m[oc]) * s + be[oc];

    const float* xi = x + n * 16384;
    float mx = -1e30f;
#pragma unroll
    for (int dy0 = 0; dy0 < 2; dy0++) {
#pragma unroll
        for (int dx0 = 0; dx0 < 2; dx0++) {
            int oy = 2 * ph + dy0, ox = 2 * pw + dx0;
            float sum = 0.f;
#pragma unroll
            for (int ky = 0; ky < 3; ky++) {
                int iy = oy - 1 + ky;
                if (iy < 0 || iy >= 128) continue;
#pragma unroll
                for (int kx = 0; kx < 3; kx++) {
                    int ix = ox - 1 + kx;
                    if (ix < 0 || ix >= 128) continue;
                    sum = fmaf(xi[iy * 128 + ix], wr[ky * 3 + kx], sum);
                }
            }
            float y = fmaxf(fmaf(sum, s, cb), 0.f);
            mx = fmaxf(mx, y);
        }
    }
    g_f0[idx] = mx;
}

// ---------------------------------------------------------------------------
// CNN conv via 3xFP16 GEMM + fused 2x2 maxpool (round-13 version).
// ---------------------------------------------------------------------------
template <int CIN, int S, int OCTOT>
__global__ void __launch_bounds__(256, 2) conv_mma(
    const float* __restrict__ in,
    const __half* __restrict__ wph, const __half* __restrict__ wpl,
    const float* __restrict__ bias, const float* __restrict__ g,
    const float* __restrict__ be, const float* __restrict__ m,
    const float* __restrict__ v, float* __restrict__ out)
{
    constexpr int NPOS = S * S;
    constexpr int CPG  = CIN / 16;
    constexpr int NG   = 9 * CPG;
    constexpr int LOGS = (S == 64) ? 6 : 5;

    __shared__ __align__(16) char smbuf[41984];
    __half* Ah = (__half*)smbuf;
    __half* Al = (__half*)(smbuf + 12288);
    __half* Bh = (__half*)(smbuf + 24576);
    __half* Bl = (__half*)(smbuf + 33280);
    __shared__ float ssc[128], sbi[128];

    int tid = threadIdx.x, lane = tid & 31, wid = tid >> 5;
    int wm = wid & 3, wn = wid >> 2;
    int ntile = blockIdx.x;
    int ocb   = blockIdx.y * 128;
    int frame = blockIdx.z;

    if (tid < 128) {
        int oc = ocb + tid;
        float s_ = g[oc] * rsqrtf(v[oc] + 1e-5f);
        ssc[tid] = s_;
        sbi[tid] = (bias[oc] - m[oc]) * s_ + be[oc];
    }

    int arow = tid >> 1, au = tid & 1;
    uint32_t ao = arow * 48 + au * 16;
    uint32_t ah_dst[2] = { smem_u32(Ah) + ao, smem_u32(Ah + 3072) + ao };
    uint32_t al_dst[2] = { smem_u32(Al) + ao, smem_u32(Al + 3072) + ao };
    size_t a_off_elem = (size_t)(ocb + arow) * 16 + au * 8;

    int bk = tid >> 4, bn = tid & 15;
    int nbase = ntile * 128 + bn * 8;

    float breg[8];
    auto prefetchB = [&](int G) {
        int s = G / CPG, q = G - s * CPG;
        int dy = s / 3 - 1, dx = s % 3 - 1;
        const float* src = in + ((size_t)frame * CIN + q * 16 + bk) * NPOS;
#pragma unroll
        for (int j = 0; j < 8; j++) {
            int pos = nbase + j;
            int y = pos >> LOGS, x = pos & (S - 1);
            int iy = y + dy, ix = x + dx;
            breg[j] = (iy >= 0 && iy < S && ix >= 0 && ix < S) ? src[iy * S + ix] : 0.f;
        }
    };
    auto stsB = [&](int buf) {
        __half hv[8], lv[8];
#pragma unroll
        for (int j = 0; j < 8; j++) {
            hv[j] = __float2half(breg[j]);
            lv[j] = __float2half(breg[j] - __half2float(hv[j]));
        }
        *(uint4*)&Bh[buf * 2176 + bk * 136 + bn * 8] = *(uint4*)hv;
        *(uint4*)&Bl[buf * 2176 + bk * 136 + bn * 8] = *(uint4*)lv;
    };
    auto cpA = [&](int G, int buf) {
        cp16(ah_dst[buf], wph + (size_t)G * (OCTOT * 16) + a_off_elem);
        cp16(al_dst[buf], wpl + (size_t)G * (OCTOT * 16) + a_off_elem);
        cp_commit();
    };

    int quad = lane >> 3, l7 = lane & 7;
    uint32_t a_off[2], b_off[4];
    {
        int rsub = ((quad & 1) << 3) + l7;
        int ksub = (quad >> 1) << 4;
#pragma unroll
        for (int mi = 0; mi < 2; mi++)
            a_off[mi] = (uint32_t)((wm * 32 + mi * 16 + rsub) * 48 + ksub);
        int krow = ((quad & 1) << 3) + l7;
        int nsub = (quad >> 1) << 3;
#pragma unroll
        for (int ni2 = 0; ni2 < 4; ni2++)
            b_off[ni2] = (uint32_t)(krow * 272 + (wn * 64 + ni2 * 16 + nsub) * 2);
    }
    uint32_t ahb[2] = { smem_u32(Ah), smem_u32(Ah + 3072) };
    uint32_t alb[2] = { smem_u32(Al), smem_u32(Al + 3072) };
    uint32_t bhb[2] = { smem_u32(Bh), smem_u32(Bh + 2176) };
    uint32_t blb[2] = { smem_u32(Bl), smem_u32(Bl + 2176) };

    float acc[2][8][4];
#pragma unroll
    for (int mi = 0; mi < 2; mi++)
#pragma unroll
        for (int ni = 0; ni < 8; ni++)
#pragma unroll
            for (int q = 0; q < 4; q++) acc[mi][ni][q] = 0.f;

    prefetchB(0); stsB(0); cpA(0, 0);
    prefetchB(1); stsB(1); cpA(1, 1);
    if (NG > 2) prefetchB(2);

    for (int j = 0; j < NG; j++) {
        if (j < NG - 1) cp_wait<1>(); else cp_wait<0>();
        __syncthreads();

        int buf = j & 1;
        uint32_t ah[2][4], al[2][4];
#pragma unroll
        for (int mi = 0; mi < 2; mi++) {
            ldm_x4(ah[mi], ahb[buf] + a_off[mi]);
            ldm_x4(al[mi], alb[buf] + a_off[mi]);
        }
#pragma unroll
        for (int ni2 = 0; ni2 < 4; ni2++) {
            uint32_t bhf[4], blf[4];
            ldm_x4t(bhf, bhb[buf] + b_off[ni2]);
            ldm_x4t(blf, blb[buf] + b_off[ni2]);
#pragma unroll
            for (int mi = 0; mi < 2; mi++)
#pragma unroll
                for (int q = 0; q < 2; q++) {
                    float* a_ = acc[mi][ni2 * 2 + q];
                    mma16816(a_, ah[mi], &bhf[q * 2]);
                    mma16816(a_, ah[mi], &blf[q * 2]);
                    mma16816(a_, al[mi], &bhf[q * 2]);
                }
        }
        __syncthreads();

        if (j + 2 < NG) {
            stsB(buf);
            cpA(j + 2, buf);
            if (j + 3 < NG) prefetchB(j + 3);
        }
    }

    // fused epilogue: BN + ReLU + 2x2 maxpool
    int gq = lane >> 2, tq = lane & 3;
    if (S == 64) {
        float* pbuf = (float*)smbuf;
#pragma unroll
        for (int mi = 0; mi < 2; mi++)
#pragma unroll
            for (int h = 0; h < 2; h++) {
                int r = wm * 32 + mi * 16 + h * 8 + gq;
                float sc = ssc[r], sh = sbi[r];
#pragma unroll
                for (int ni = 0; ni < 8; ni++) {
                    float v0 = fmaxf(fmaf(acc[mi][ni][2 * h],     sc, sh), 0.f);
                    float v1 = fmaxf(fmaf(acc[mi][ni][2 * h + 1], sc, sh), 0.f);
                    pbuf[r * 64 + wn * 32 + ni * 4 + tq] = fmaxf(v0, v1);
                }
            }
        __syncthreads();
        const int HP = 32;
        for (int i = tid; i < 128 * 32; i += 256) {
            int oc = i >> 5, xh = i & 31;
            float vv = fmaxf(pbuf[oc * 64 + xh], pbuf[oc * 64 + 32 + xh]);
            out[((size_t)(frame * OCTOT + ocb + oc) * HP + ntile) * HP + xh] = vv;
        }
    } else {
        const int HP = 16;
#pragma unroll
        for (int mi = 0; mi < 2; mi++)
#pragma unroll
            for (int h = 0; h < 2; h++) {
                int r = wm * 32 + mi * 16 + h * 8 + gq;
                float sc = ssc[r], sh = sbi[r];
#pragma unroll
                for (int n4 = 0; n4 < 4; n4++) {
                    float a0 = fmaxf(fmaf(acc[mi][n4][2 * h],         sc, sh), 0.f);
                    float a1 = fmaxf(fmaf(acc[mi][n4][2 * h + 1],     sc, sh), 0.f);
                    float b0 = fmaxf(fmaf(acc[mi][n4 + 4][2 * h],     sc, sh), 0.f);
                    float b1 = fmaxf(fmaf(acc[mi][n4 + 4][2 * h + 1], sc, sh), 0.f);
                    float mx = fmaxf(fmaxf(a0, a1), fmaxf(b0, b1));
                    int yq = ntile * 2 + wn;
                    int xq = n4 * 4 + tq;
                    out[((size_t)(frame * OCTOT + ocb + r) * HP + yq) * HP + xq] = mx;
                }
            }
    }
}

// ---------------------------------------------------------------------------
// Hoisted L0 x-half GEMM: Zx0[slab] = Wx0 * im2col(x0[slab]), all 32 slabs.
// Grid (8 mtiles, 2 ntiles, 32 slabs), 256 threads, K = 144 x-chunks.
// ---------------------------------------------------------------------------
__global__ void __launch_bounds__(256, 2) lstm_xgemm()
{
    __shared__ __align__(16) __half Ah[2][128 * 24];
    __shared__ __align__(16) __half Al[2][128 * 24];
    __shared__ __align__(16) __half Bh[2][16 * 136];
    __shared__ __align__(16) __half Bl[2][16 * 136];

    int tid  = threadIdx.x;
    int lane = tid & 31;
    int wid  = tid >> 5;
    int wm = wid & 3, wn = wid >> 2;

    int mtile = blockIdx.x;
    int ntile = blockIdx.y;
    int slab  = blockIdx.z;
    int ocb   = mtile * 128;

    const __half* bxh = g_bx0h + (size_t)slab * BHS;
    const __half* bxl = g_bx0l + (size_t)slab * BHS;

    int arow = tid >> 1, au = tid & 1;
    uint32_t ao = arow * 48 + au * 16;
    uint32_t ah_dst[2] = { smem_u32(&Ah[0][0]) + ao, smem_u32(&Ah[1][0]) + ao };
    uint32_t al_dst[2] = { smem_u32(&Al[0][0]) + ao, smem_u32(&Al[1][0]) + ao };
    uint32_t bo = (tid >> 4) * 272 + (tid & 15) * 16;
    uint32_t bh_dst[2] = { smem_u32(&Bh[0][0]) + bo, smem_u32(&Bh[1][0]) + bo };
    uint32_t bl_dst[2] = { smem_u32(&Bl[0][0]) + bo, smem_u32(&Bl[1][0]) + bo };
    size_t a_off_elem = (size_t)(arow + ocb) * 16 + au * 8;
    int b_src_off = (tid >> 4) * 256 + ntile * 128 + (tid & 15) * 8;

    int quad = lane >> 3, l7 = lane & 7;
    uint32_t a_off[2], b_off[4];
    {
        int rsub = ((quad & 1) << 3) + l7;
        int ksub = (quad >> 1) << 4;
#pragma unroll
        for (int mi = 0; mi < 2; mi++)
            a_off[mi] = (uint32_t)((wm * 32 + mi * 16 + rsub) * 48 + ksub);
        int krow = ((quad & 1) << 3) + l7;
        int nsub = (quad >> 1) << 3;
#pragma unroll
        for (int ni2 = 0; ni2 < 4; ni2++)
            b_off[ni2] = (uint32_t)(krow * 272 + (wn * 64 + ni2 * 16 + nsub) * 2);
    }
    uint32_t ahb[2] = { smem_u32(&Ah[0][0]), smem_u32(&Ah[1][0]) };
    uint32_t alb[2] = { smem_u32(&Al[0][0]), smem_u32(&Al[1][0]) };
    uint32_t bhb[2] = { smem_u32(&Bh[0][0]), smem_u32(&Bh[1][0]) };
    uint32_t blb[2] = { smem_u32(&Bl[0][0]), smem_u32(&Bl[1][0]) };

    float acc[2][8][4];
#pragma unroll
    for (int mi = 0; mi < 2; mi++)
#pragma unroll
        for (int ni = 0; ni < 8; ni++)
#pragma unroll
            for (int q = 0; q < 4; q++) acc[mi][ni][q] = 0.f;

    // x-chunk jx: shift = jx>>4, c16 = jx&15, G = shift*32 + c16
    auto stage = [&](int jx, int buf) {
        int shift = jx >> 4, c16 = jx & 15;
        int G = shift * 32 + c16;
        size_t srow = ((size_t)(shift * 256 + c16 * 16)) << 8;
        cp16(ah_dst[buf], g_wph + (size_t)G * 16384 + a_off_elem);
        cp16(al_dst[buf], g_wpl + (size_t)G * 16384 + a_off_elem);
        cp16(bh_dst[buf], bxh + srow + b_src_off);
        cp16(bl_dst[buf], bxl + srow + b_src_off);
        cp_commit();
    };

    stage(0, 0);
    stage(1, 1);

    for (int j = 0; j < 144; j++) {
        if (j < 143) cp_wait<1>(); else cp_wait<0>();
        __syncthreads();

        int buf = j & 1;
        uint32_t ah[2][4], al[2][4];
#pragma unroll
        for (int mi = 0; mi < 2; mi++) {
            ldm_x4(ah[mi], ahb[buf] + a_off[mi]);
            ldm_x4(al[mi], alb[buf] + a_off[mi]);
        }
#pragma unroll
        for (int ni2 = 0; ni2 < 4; ni2++) {
            uint32_t bhf[4], blf[4];
            ldm_x4t(bhf, bhb[buf] + b_off[ni2]);
            ldm_x4t(blf, blb[buf] + b_off[ni2]);
#pragma unroll
            for (int mi = 0; mi < 2; mi++)
#pragma unroll
                for (int q = 0; q < 2; q++) {
                    float* a_ = acc[mi][ni2 * 2 + q];
                    mma16816(a_, ah[mi], &bhf[q * 2]);
                    mma16816(a_, ah[mi], &blf[q * 2]);
                    mma16816(a_, al[mi], &bhf[q * 2]);
                }
        }
        __syncthreads();
        if (j + 2 < 144) stage(j + 2, buf);
    }

    int gq = lane >> 2, tq = lane & 3;
    float* zbase = g_zx0 + (size_t)slab * 262144;
    int row0 = ocb + wm * 32 + gq;
    int col0 = ntile * 128 + wn * 64 + 2 * tq;
#pragma unroll
    for (int mi = 0; mi < 2; mi++)
#pragma unroll
        for (int ni = 0; ni < 8; ni++) {
            int r = row0 + mi * 16;
            int cc = col0 + ni * 8;
            *(float2*)(zbase + (size_t)r * 256 + cc)       = make_float2(acc[mi][ni][0], acc[mi][ni][1]);
            *(float2*)(zbase + (size_t)(r + 8) * 256 + cc) = make_float2(acc[mi][ni][2], acc[mi][ni][3]);
        }
}

// ---------------------------------------------------------------------------
// Pipelined ConvLSTM MMA: step k runs L0(t=k) h-half and L1(t=k-1) full.
// Grid (8 mtiles, 4 = ntile+2*b, 9 = L0 splits 0..2 + L1 splits 3..8).
// Every CTA: 48 K-chunks.
// ---------------------------------------------------------------------------
__global__ void __launch_bounds__(256, 2) lstm_mma_pair(int k)
{
    int slot  = blockIdx.z;
    int layer = (slot >= 3);
    int t = layer ? (k - 1) : k;
    if (t < 0 || t > 15) return;

    __shared__ __align__(16) __half Ah[2][128 * 24];
    __shared__ __align__(16) __half Al[2][128 * 24];
    __shared__ __align__(16) __half Bh[2][16 * 136];
    __shared__ __align__(16) __half Bl[2][16 * 136];

    int tid  = threadIdx.x;
    int lane = tid & 31;
    int wid  = tid >> 5;
    int wm = wid & 3, wn = wid >> 2;

    int mtile = blockIdx.x;
    int ntile = blockIdx.y & 1;
    int b     = blockIdx.y >> 1;
    int ocb   = mtile * 128;

    const __half* bh0h = g_bhh + (size_t)b * BHS;               // layer0 h (L1's x)
    const __half* bh0l = g_bhl + (size_t)b * BHS;
    const __half* bh1h = g_bhh + (size_t)(2 + b) * BHS;         // layer1 h
    const __half* bh1l = g_bhl + (size_t)(2 + b) * BHS;
    const __half* wph = g_wph + (size_t)layer * 4718592;
    const __half* wpl = g_wpl + (size_t)layer * 4718592;

    int arow = tid >> 1, au = tid & 1;
    uint32_t ao = arow * 48 + au * 16;
    uint32_t ah_dst[2] = { smem_u32(&Ah[0][0]) + ao, smem_u32(&Ah[1][0]) + ao };
    uint32_t al_dst[2] = { smem_u32(&Al[0][0]) + ao, smem_u32(&Al[1][0]) + ao };
    uint32_t bo = (tid >> 4) * 272 + (tid & 15) * 16;
    uint32_t bh_dst[2] = { smem_u32(&Bh[0][0]) + bo, smem_u32(&Bh[1][0]) + bo };
    uint32_t bl_dst[2] = { smem_u32(&Bl[0][0]) + bo, smem_u32(&Bl[1][0]) + bo };
    size_t a_off_elem = (size_t)(arow + ocb) * 16 + au * 8;
    int b_src_off = (tid >> 4) * 256 + ntile * 128 + (tid & 15) * 8;

    int quad = lane >> 3, l7 = lane & 7;
    uint32_t a_off[2], b_off[4];
    {
        int rsub = ((quad & 1) << 3) + l7;
        int ksub = (quad >> 1) << 4;
#pragma unroll
        for (int mi = 0; mi < 2; mi++)
            a_off[mi] = (uint32_t)((wm * 32 + mi * 16 + rsub) * 48 + ksub);
        int krow = ((quad & 1) << 3) + l7;
        int nsub = (quad >> 1) << 3;
#pragma unroll
        for (int ni2 = 0; ni2 < 4; ni2++)
            b_off[ni2] = (uint32_t)(krow * 272 + (wn * 64 + ni2 * 16 + nsub) * 2);
    }
    uint32_t ahb[2] = { smem_u32(&Ah[0][0]), smem_u32(&Ah[1][0]) };
    uint32_t alb[2] = { smem_u32(&Al[0][0]), smem_u32(&Al[1][0]) };
    uint32_t bhb[2] = { smem_u32(&Bh[0][0]), smem_u32(&Bh[1][0]) };
    uint32_t blb[2] = { smem_u32(&Bl[0][0]), smem_u32(&Bl[1][0]) };

    float acc[2][8][4];
#pragma unroll
    for (int mi = 0; mi < 2; mi++)
#pragma unroll
        for (int ni = 0; ni < 8; ni++)
#pragma unroll
            for (int q = 0; q < 4; q++) acc[mi][ni][q] = 0.f;

    auto stage = [&](int j, int buf) {
        int G;
        const __half* bsh;
        const __half* bsl;
        size_t srow;
        if (slot < 3) {
            // L0 h-half: jh = slot*48+j in [0,144): shift=jh>>4, c16=jh&15
            int jh = slot * 48 + j;
            int shift = jh >> 4, c16 = jh & 15;
            G = shift * 32 + 16 + c16;                         // h channels: c>=256
            srow = ((size_t)(shift * 256 + c16 * 16)) << 8;
            bsh = bh0h; bsl = bh0l;
        } else {
            // L1 full K: jg = (slot-3)*48+j in [0,288)
            int jg = (slot - 3) * 48 + j;
            G = jg;
            int s9 = jg >> 5;
            int c0 = (jg & 31) << 4;
            bool isx = (c0 < 256);
            int cL = isx ? c0 : (c0 - 256);
            srow = ((size_t)(s9 * 256 + cL)) << 8;
            bsh = isx ? bh0h : bh1h;                           // L1's x = L0's bh
            bsl = isx ? bh0l : bh1l;
        }
        cp16(ah_dst[buf], wph + (size_t)G * 16384 + a_off_elem);
        cp16(al_dst[buf], wpl + (size_t)G * 16384 + a_off_elem);
        cp16(bh_dst[buf], bsh + srow + b_src_off);
        cp16(bl_dst[buf], bsl + srow + b_src_off);
        cp_commit();
    };

    stage(0, 0);
    stage(1, 1);

    for (int j = 0; j < 48; j++) {
        if (j < 47) cp_wait<1>(); else cp_wait<0>();
        __syncthreads();

        int buf = j & 1;
        uint32_t ah[2][4], al[2][4];
#pragma unroll
        for (int mi = 0; mi < 2; mi++) {
            ldm_x4(ah[mi], ahb[buf] + a_off[mi]);
            ldm_x4(al[mi], alb[buf] + a_off[mi]);
        }
#pragma unroll
        for (int ni2 = 0; ni2 < 4; ni2++) {
            uint32_t bhf[4], blf[4];
            ldm_x4t(bhf, bhb[buf] + b_off[ni2]);
            ldm_x4t(blf, blb[buf] + b_off[ni2]);
#pragma unroll
            for (int mi = 0; mi < 2; mi++)
#pragma unroll
                for (int q = 0; q < 2; q++) {
                    float* a_ = acc[mi][ni2 * 2 + q];
                    mma16816(a_, ah[mi], &bhf[q * 2]);
                    mma16816(a_, ah[mi], &blf[q * 2]);
                    mma16816(a_, al[mi], &bhf[q * 2]);
                }
        }

        __syncthreads();
        if (j + 2 < 48) stage(j + 2, buf);
    }

    int gq = lane >> 2, tq = lane & 3;
    float* zbase = g_zp + ((size_t)(slot * 2 + b) * 1024) * 256;
    int row0 = ocb + wm * 32 + gq;
    int col0 = ntile * 128 + wn * 64 + 2 * tq;
#pragma unroll
    for (int mi = 0; mi < 2; mi++)
#pragma unroll
        for (int ni = 0; ni < 8; ni++) {
            int r = row0 + mi * 16;
            int cc = col0 + ni * 8;
            *(float2*)(zbase + (size_t)r * 256 + cc)       = make_float2(acc[mi][ni][0], acc[mi][ni][1]);
            *(float2*)(zbase + (size_t)(r + 8) * 256 + cc) = make_float2(acc[mi][ni][2], acc[mi][ni][3]);
        }
}

// ---------------------------------------------------------------------------
// Pipelined gates: both layers in one launch (1024 CTAs).
// L0: bias + Zx0[slab] + slots 0..2;  L1: bias + slots 3..8.
// ---------------------------------------------------------------------------
__global__ void __launch_bounds__(256) lstm_gates_pair(int k,
                                                       const float* __restrict__ lb0,
                                                       const float* __restrict__ lb1,
                                                       float* __restrict__ out)
{
    int gid = blockIdx.x * 256 + threadIdx.x;  // 262144
    int layer = gid >> 17;
    int idx = gid & 131071;
    int t = layer ? (k - 1) : k;
    if (t < 0 || t > 15) return;

    int inner = idx & 65535;
    int b = idx >> 16;
    int c = inner >> 8;
    int pos = inner & 255;
    const float* lb = layer ? lb1 : lb0;

    float zi = lb[c], zf = lb[c + 256], zo = lb[c + 512], zg = lb[c + 768];

    if (layer == 0) {
        const float* zx = g_zx0 + (size_t)(t * 2 + b) * 262144;
        zi += zx[(size_t)(c)       * 256 + pos];
        zf += zx[(size_t)(c + 256) * 256 + pos];
        zo += zx[(size_t)(c + 512) * 256 + pos];
        zg += zx[(size_t)(c + 768) * 256 + pos];
#pragma unroll
        for (int s = 0; s < 3; s++) {
            const float* zb = g_zp + ((size_t)(s * 2 + b)) * 1024 * 256;
            zi += zb[(size_t)(c)       * 256 + pos];
            zf += zb[(size_t)(c + 256) * 256 + pos];
            zo += zb[(size_t)(c + 512) * 256 + pos];
            zg += zb[(size_t)(c + 768) * 256 + pos];
        }
    } else {
#pragma unroll
        for (int s = 3; s < 9; s++) {
            const float* zb = g_zp + ((size_t)(s * 2 + b)) * 1024 * 256;
            zi += zb[(size_t)(c)       * 256 + pos];
            zf += zb[(size_t)(c + 256) * 256 + pos];
            zo += zb[(size_t)(c + 512) * 256 + pos];
            zg += zb[(size_t)(c + 768) * 256 + pos];
        }
    }

    size_t cidx = (size_t)layer * 131072 + idx;
    float cn = sigmoidf_(zf) * g_c[cidx] + sigmoidf_(zi) * tanhf(zg);
    float hn = sigmoidf_(zo) * tanhf(cn);
    g_c[cidx] = cn;

    __half hh = __float2half(hn);
    __half hl = __float2half(hn - __half2float(hh));
    int y = pos >> 4, x = pos & 15;
    __half* bhhp = g_bhh + (size_t)(layer * 2 + b) * BHS;
    __half* bhlp = g_bhl + (size_t)(layer * 2 + b) * BHS;
#pragma unroll
    for (int s = 0; s < 9; s++) {
        int dy = s / 3 - 1, dx = s % 3 - 1;
        int ny = y - dy, nx = x - dx;
        if (ny >= 0 && ny < 16 && nx >= 0 && nx < 16) {
            int o = ((s * 256 + c) << 8) + ny * 16 + nx;
            bhhp[o] = hh;
            bhlp[o] = hl;
        }
    }

    if (layer == 1)
        out[(size_t)b * 16 * CHW2 + (size_t)t * CHW2 + inner] = hn;
}

// zero c (both layers) and h im2col buffers (both layers)
__global__ void __launch_bounds__(256) zero_state()
{
    int idx = blockIdx.x * 256 + threadIdx.x;   // 2359296 = 2*2*BHS
    if (idx < 262144) g_c[idx] = 0.f;
    g_bhh[idx] = __float2half(0.f);
    g_bhl[idx] = __float2half(0.f);
}

__global__ void __launch_bounds__(256) copy_last(float* __restrict__ out)
{
    int idx = blockIdx.x * 256 + threadIdx.x;
    int inner = idx & 65535;
    int b = idx >> 16;
    out[2097152 + idx] = out[(size_t)b * 16 * CHW2 + 15 * CHW2 + inner];
}

// ---------------------------------------------------------------------------
// Launch sequence (graph-capturable)
// ---------------------------------------------------------------------------
extern "C" void kernel_launch(void* const* d_in, const int* in_sizes, int n_in,
                              void* d_out, int out_size)
{
    const float* x   = (const float*)d_in[0];
    const float* w0  = (const float*)d_in[1];
    const float* b0  = (const float*)d_in[2];
    const float* g0  = (const float*)d_in[3];
    const float* be0 = (const float*)d_in[4];
    const float* m0  = (const float*)d_in[5];
    const float* v0  = (const float*)d_in[6];
    const float* w1  = (const float*)d_in[7];
    const float* b1  = (const float*)d_in[8];
    const float* g1  = (const float*)d_in[9];
    const float* be1 = (const float*)d_in[10];
    const float* m1  = (const float*)d_in[11];
    const float* v1  = (const float*)d_in[12];
    const float* w2  = (const float*)d_in[13];
    const float* b2  = (const float*)d_in[14];
    const float* g2  = (const float*)d_in[15];
    const float* be2 = (const float*)d_in[16];
    const float* m2  = (const float*)d_in[17];
    const float* v2  = (const float*)d_in[18];
    const float* lw0 = (const float*)d_in[19];
    const float* lb0 = (const float*)d_in[20];
    const float* lw1 = (const float*)d_in[21];
    const float* lb1 = (const float*)d_in[22];
    float* out = (float*)d_out;

    float* f0ptr;  cudaGetSymbolAddress((void**)&f0ptr, g_f0);
    float* f1ptr;  cudaGetSymbolAddress((void**)&f1ptr, g_f1);
    float* f2ptr;  cudaGetSymbolAddress((void**)&f2ptr, g_f2);
    __half* wc1h; cudaGetSymbolAddress((void**)&wc1h, g_wc1h);
    __half* wc1l; cudaGetSymbolAddress((void**)&wc1l, g_wc1l);
    __half* wc2h; cudaGetSymbolAddress((void**)&wc2h, g_wc2h);
    __half* wc2l; cudaGetSymbolAddress((void**)&wc2l, g_wc2l);

    // weight prepacks
    prepack_w2<<<dim3(1024, 2), 256>>>(lw0, lw1);
    prepack_cw<64, 128><<<288, 256>>>(w1, wc1h, wc1l);
    prepack_cw<128, 256><<<1152, 256>>>(w2, wc2h, wc2l);

    // CNN encoder (pool fused into conv_mma epilogue)
    conv0_pool<<<32768, 256>>>(x, w0, b0, g0, be0, m0, v0);
    conv_mma<64, 64, 128><<<dim3(32, 1, 32), 256>>>(f0ptr, wc1h, wc1l,
                                                    b1, g1, be1, m1, v1, f1ptr);
    conv_mma<128, 32, 256><<<dim3(8, 2, 32), 256>>>(f1ptr, wc2h, wc2l,
                                                    b2, g2, be2, m2, v2, f2ptr);

    // hi/lo fp16 im2col of CNN features
    build_bx0<<<73728, 256>>>();

    // hoisted L0 x-half GEMM for all 32 (t,b) slabs
    lstm_xgemm<<<dim3(8, 2, 32), 256>>>();

    // Pipelined ConvLSTM: step k = L0(t=k) h-half + L1(t=k-1) full
    zero_state<<<9216, 256>>>();
    for (int k = 0; k <= 16; k++) {
        lstm_mma_pair<<<dim3(8, 4, 9), 256>>>(k);
        lstm_gates_pair<<<1024, 256>>>(k, lb0, lb1, out);
    }

    copy_last<<<512, 256>>>(out);
}

// round 15
// speedup vs baseline: 1.9515x; 1.1298x over previous
#include <cuda_runtime.h>
#include <cuda_fp16.h>
#include <math.h>
#include <stdint.h>

// ---------------------------------------------------------------------------
//   block0: 1->64 SIMT; block1/2 + ConvLSTM convs: 3xFP16 mma.sync GEMM
//   (D += Ah*Bh + Ah*Bl + Al*Bh), K=16 chunks, TRIPLE buffer (1 barrier/chunk).
// ConvLSTM layers software-pipelined: step k runs L0(t=k) and L1(t=k-1).
//   - L0's x-half GEMM hoisted (Zx0 precompute, all 32 slabs)
//   - L1's x-input read directly from L0's bh buffer
//   - in-loop splits balanced: every CTA does 48 K-chunks (L0 3, L1 6 slots)
// Dynamic smem layout (bytes): Ah 3x6144 @0, Al 3x6144 @18432,
//   Bh 3x4352 @36864, Bl 3x4352 @49920; total 62976.
// ---------------------------------------------------------------------------

#define CHW2 65536          // 256*16*16
#define BHS  589824         // 9*256*256
#define DSM_BYTES 62976

typedef unsigned long long ull;

// ============================ PTX helpers ==================================
__device__ __forceinline__ uint32_t smem_u32(const void* p) {
    uint32_t a;
    asm("{ .reg .u64 t; cvta.to.shared.u64 t, %1; cvt.u32.u64 %0, t; }" : "=r"(a) : "l"(p));
    return a;
}
__device__ __forceinline__ void ldm_x4(uint32_t* r, uint32_t addr) {
    asm volatile("ldmatrix.sync.aligned.m8n8.x4.shared.b16 {%0,%1,%2,%3}, [%4];"
        : "=r"(r[0]), "=r"(r[1]), "=r"(r[2]), "=r"(r[3]) : "r"(addr));
}
__device__ __forceinline__ void ldm_x4t(uint32_t* r, uint32_t addr) {
    asm volatile("ldmatrix.sync.aligned.m8n8.x4.trans.shared.b16 {%0,%1,%2,%3}, [%4];"
        : "=r"(r[0]), "=r"(r[1]), "=r"(r[2]), "=r"(r[3]) : "r"(addr));
}
__device__ __forceinline__ void mma16816(float* d, const uint32_t* a, const uint32_t* b) {
    asm volatile(
        "mma.sync.aligned.m16n8k16.row.col.f32.f16.f16.f32 "
        "{%0,%1,%2,%3}, {%4,%5,%6,%7}, {%8,%9}, {%0,%1,%2,%3};"
        : "+f"(d[0]), "+f"(d[1]), "+f"(d[2]), "+f"(d[3])
        : "r"(a[0]), "r"(a[1]), "r"(a[2]), "r"(a[3]), "r"(b[0]), "r"(b[1]));
}
__device__ __forceinline__ void cp16(uint32_t sdst, const void* gsrc) {
    asm volatile("cp.async.cg.shared.global [%0], [%1], 16;" :: "r"(sdst), "l"(gsrc));
}
__device__ __forceinline__ void cp_commit() { asm volatile("cp.async.commit_group;"); }
template <int N> __device__ __forceinline__ void cp_wait() {
    asm volatile("cp.async.wait_group %0;" :: "n"(N));
}
__device__ __forceinline__ float sigmoidf_(float x) { return 1.0f / (1.0f + expf(-x)); }

// ---------------------------------------------------------------------------
// Scratch
// ---------------------------------------------------------------------------
__device__ __align__(256) float  g_f0[32 * 64 * 64 * 64];
__device__ __align__(256) float  g_f1[32 * 128 * 32 * 32];
__device__ __align__(256) float  g_f2[32 * 256 * 16 * 16];
__device__ __align__(256) __half g_wc1h[36 * 128 * 16];
__device__ __align__(256) __half g_wc1l[36 * 128 * 16];
__device__ __align__(256) __half g_wc2h[72 * 256 * 16];
__device__ __align__(256) __half g_wc2l[72 * 256 * 16];
__device__ __align__(256) __half g_wph[2 * 288 * 1024 * 16];  // [layer][G][oc][16]
__device__ __align__(256) __half g_wpl[2 * 288 * 1024 * 16];
__device__ __align__(256) __half g_bx0h[32 * BHS];            // L0 x im2col [(t*2+b)][s][c][n]
__device__ __align__(256) __half g_bx0l[32 * BHS];
__device__ __align__(256) __half g_bhh[2 * 2 * BHS];          // h im2col [layer][b][s][c][n]
__device__ __align__(256) __half g_bhl[2 * 2 * BHS];
__device__ __align__(256) float  g_c[2 * 2 * CHW2];           // cell state [layer][b]
__device__ __align__(256) float  g_zx0[32 * 1024 * 256];      // hoisted L0 x-half GEMM
__device__ __align__(256) float  g_zp[9 * 2 * 1024 * 256];    // partials [slot][b][oc][pos]

// ---------------------------------------------------------------------------
// LSTM weight prepack (coalesced transpose): one oc per CTA, both layers.
// ---------------------------------------------------------------------------
__global__ void __launch_bounds__(256) prepack_w2(const float* __restrict__ lw0,
                                                  const float* __restrict__ lw1)
{
    __shared__ float wbuf[4608];
    int oc = blockIdx.x;
    int layer = blockIdx.y;
    const float* lw = layer ? lw1 : lw0;
    int tid = threadIdx.x;

    for (int i = tid; i < 4608; i += 256)
        wbuf[i] = lw[(size_t)oc * 4608 + i];
    __syncthreads();

    size_t base = (size_t)layer * 4718592;
    for (int k = tid; k < 4608; k += 256) {
        int s = k >> 9, c = k & 511;
        float w = wbuf[c * 9 + s];
        __half hi = __float2half(w);
        size_t o = base + ((size_t)(k >> 4) * 1024 + oc) * 16 + (k & 15);
        g_wph[o] = hi;
        g_wpl[o] = __float2half(w - __half2float(hi));
    }
}

// ---------------------------------------------------------------------------
// CNN conv weight prepack: [G][oc][16]
// ---------------------------------------------------------------------------
template <int CIN, int OCTOT>
__global__ void __launch_bounds__(256) prepack_cw(
    const float* __restrict__ w, __half* __restrict__ outh, __half* __restrict__ outl)
{
    constexpr int CPG = CIN / 16;
    int idx = blockIdx.x * 256 + threadIdx.x;
    int u  = idx & 15;
    int oc = (idx >> 4) % OCTOT;
    int G  = (idx >> 4) / OCTOT;
    int s  = G / CPG;
    int c  = (G % CPG) * 16 + u;
    float val = w[((size_t)oc * CIN + c) * 9 + s];
    __half hi = __float2half(val);
    outh[idx] = hi;
    outl[idx] = __float2half(val - __half2float(hi));
}

// ---------------------------------------------------------------------------
// Build layer0 x im2col (hi/lo). 32*BHS elements.
// ---------------------------------------------------------------------------
__global__ void __launch_bounds__(256) build_bx0()
{
    int idx = blockIdx.x * 256 + threadIdx.x;
    int n   = idx & 255;
    int c   = (idx >> 8) & 255;
    int rem = idx >> 16;
    int s   = rem % 9;
    int tb  = rem / 9;
    int t   = tb >> 1, b = tb & 1;
    int dy  = s / 3 - 1, dx = s % 3 - 1;
    int iy  = (n >> 4) + dy, ix = (n & 15) + dx;
    float val = 0.f;
    if (iy >= 0 && iy < 16 && ix >= 0 && ix < 16)
        val = g_f2[(((size_t)(b * 16 + t) * 256 + c) << 8) + iy * 16 + ix];
    __half hi = __float2half(val);
    g_bx0h[idx] = hi;
    g_bx0l[idx] = __float2half(val - __half2float(hi));
}

// ---------------------------------------------------------------------------
// Block 0 SIMT conv+pool
// ---------------------------------------------------------------------------
__global__ void __launch_bounds__(256) conv0_pool(
    const float* __restrict__ x, const float* __restrict__ w,
    const float* __restrict__ bias, const float* __restrict__ g,
    const float* __restrict__ be, const float* __restrict__ m,
    const float* __restrict__ v)
{
    int idx = blockIdx.x * 256 + threadIdx.x;
    int pw = idx & 63;
    int ph = (idx >> 6) & 63;
    int oc = (idx >> 12) & 63;
    int n  = idx >> 18;

    float wr[9];
#pragma unroll
    for (int k = 0; k < 9; k++) wr[k] = w[oc * 9 + k];
    float s  = g[oc] * rsqrtf(v[oc] + 1e-5f);
    float cb = (bias[oc] - m[oc]) * s + be[oc];

    const float* xi = x + n * 16384;
    float mx = -1e30f;
#pragma unroll
    for (int dy0 = 0; dy0 < 2; dy0++) {
#pragma unroll
        for (int dx0 = 0; dx0 < 2; dx0++) {
            int oy = 2 * ph + dy0, ox = 2 * pw + dx0;
            float sum = 0.f;
#pragma unroll
            for (int ky = 0; ky < 3; ky++) {
                int iy = oy - 1 + ky;
                if (iy < 0 || iy >= 128) continue;
#pragma unroll
                for (int kx = 0; kx < 3; kx++) {
                    int ix = ox - 1 + kx;
                    if (ix < 0 || ix >= 128) continue;
                    sum = fmaf(xi[iy * 128 + ix], wr[ky * 3 + kx], sum);
                }
            }
            float y = fmaxf(fmaf(sum, s, cb), 0.f);
            mx = fmaxf(mx, y);
        }
    }
    g_f0[idx] = mx;
}

// ---------------------------------------------------------------------------
// CNN conv via 3xFP16 GEMM + fused 2x2 maxpool. Triple-buffered staging.
// ---------------------------------------------------------------------------
template <int CIN, int S, int OCTOT>
__global__ void __launch_bounds__(256, 2) conv_mma(
    const float* __restrict__ in,
    const __half* __restrict__ wph, const __half* __restrict__ wpl,
    const float* __restrict__ bias, const float* __restrict__ g,
    const float* __restrict__ be, const float* __restrict__ m,
    const float* __restrict__ v, float* __restrict__ out)
{
    constexpr int NPOS = S * S;
    constexpr int CPG  = CIN / 16;
    constexpr int NG   = 9 * CPG;
    constexpr int LOGS = (S == 64) ? 6 : 5;

    extern __shared__ __align__(16) char dsm[];
    __shared__ float ssc[128], sbi[128];

    int tid = threadIdx.x, lane = tid & 31, wid = tid >> 5;
    int wm = wid & 3, wn = wid >> 2;
    int ntile = blockIdx.x;
    int ocb   = blockIdx.y * 128;
    int frame = blockIdx.z;

    if (tid < 128) {
        int oc = ocb + tid;
        float s_ = g[oc] * rsqrtf(v[oc] + 1e-5f);
        ssc[tid] = s_;
        sbi[tid] = (bias[oc] - m[oc]) * s_ + be[oc];
    }

    uint32_t dbase = smem_u32(dsm);
    uint32_t ahb[3] = { dbase,         dbase + 6144,  dbase + 12288 };
    uint32_t alb[3] = { dbase + 18432, dbase + 24576, dbase + 30720 };
    uint32_t bhb[3] = { dbase + 36864, dbase + 41216, dbase + 45568 };
    uint32_t blb[3] = { dbase + 49920, dbase + 54272, dbase + 58624 };

    int arow = tid >> 1, au = tid & 1;
    uint32_t ao = arow * 48 + au * 16;
    size_t a_off_elem = (size_t)(ocb + arow) * 16 + au * 8;

    int bk = tid >> 4, bn = tid & 15;
    int nbase = ntile * 128 + bn * 8;
    uint32_t bo = bk * 272 + bn * 16;

    float breg[8];
    auto prefetchB = [&](int G) {
        int s = G / CPG, q = G - s * CPG;
        int dy = s / 3 - 1, dx = s % 3 - 1;
        const float* src = in + ((size_t)frame * CIN + q * 16 + bk) * NPOS;
#pragma unroll
        for (int j = 0; j < 8; j++) {
            int pos = nbase + j;
            int y = pos >> LOGS, x = pos & (S - 1);
            int iy = y + dy, ix = x + dx;
            breg[j] = (iy >= 0 && iy < S && ix >= 0 && ix < S) ? src[iy * S + ix] : 0.f;
        }
    };
    auto stsB = [&](int buf) {
        __half hv[8], lv[8];
#pragma unroll
        for (int j = 0; j < 8; j++) {
            hv[j] = __float2half(breg[j]);
            lv[j] = __float2half(breg[j] - __half2float(hv[j]));
        }
        *(uint4*)(dsm + 36864 + buf * 4352 + bo) = *(uint4*)hv;
        *(uint4*)(dsm + 49920 + buf * 4352 + bo) = *(uint4*)lv;
    };
    auto cpA = [&](int G, int buf) {
        cp16(ahb[buf] + ao, wph + (size_t)G * (OCTOT * 16) + a_off_elem);
        cp16(alb[buf] + ao, wpl + (size_t)G * (OCTOT * 16) + a_off_elem);
        cp_commit();
    };

    int quad = lane >> 3, l7 = lane & 7;
    uint32_t a_off[2], b_off[4];
    {
        int rsub = ((quad & 1) << 3) + l7;
        int ksub = (quad >> 1) << 4;
#pragma unroll
        for (int mi = 0; mi < 2; mi++)
            a_off[mi] = (uint32_t)((wm * 32 + mi * 16 + rsub) * 48 + ksub);
        int krow = ((quad & 1) << 3) + l7;
        int nsub = (quad >> 1) << 3;
#pragma unroll
        for (int ni2 = 0; ni2 < 4; ni2++)
            b_off[ni2] = (uint32_t)(krow * 272 + (wn * 64 + ni2 * 16 + nsub) * 2);
    }

    float acc[2][8][4];
#pragma unroll
    for (int mi = 0; mi < 2; mi++)
#pragma unroll
        for (int ni = 0; ni < 8; ni++)
#pragma unroll
            for (int q = 0; q < 4; q++) acc[mi][ni][q] = 0.f;

    prefetchB(0); stsB(0); cpA(0, 0);
    prefetchB(1); stsB(1); cpA(1, 1);
    if (NG > 2) prefetchB(2);

    int buf = 0;
    for (int j = 0; j < NG; j++) {
        if (j < NG - 1) cp_wait<1>(); else cp_wait<0>();
        __syncthreads();

        uint32_t ah[2][4], al[2][4];
#pragma unroll
        for (int mi = 0; mi < 2; mi++) {
            ldm_x4(ah[mi], ahb[buf] + a_off[mi]);
            ldm_x4(al[mi], alb[buf] + a_off[mi]);
        }
#pragma unroll
        for (int ni2 = 0; ni2 < 4; ni2++) {
            uint32_t bhf[4], blf[4];
            ldm_x4t(bhf, bhb[buf] + b_off[ni2]);
            ldm_x4t(blf, blb[buf] + b_off[ni2]);
#pragma unroll
            for (int mi = 0; mi < 2; mi++)
#pragma unroll
                for (int q = 0; q < 2; q++) {
                    float* a_ = acc[mi][ni2 * 2 + q];
                    mma16816(a_, ah[mi], &bhf[q * 2]);
                    mma16816(a_, ah[mi], &blf[q * 2]);
                    mma16816(a_, al[mi], &bhf[q * 2]);
                }
        }

        // stage chunk j+2 into buffer (j+2)%3 (last read at iter j-1,
        // protected by the barrier at the top of this iteration)
        if (j + 2 < NG) {
            int nb = buf + 2; if (nb >= 3) nb -= 3;
            stsB(nb);
            cpA(j + 2, nb);
            if (j + 3 < NG) prefetchB(j + 3);
        }
        if (++buf == 3) buf = 0;
    }
    __syncthreads();   // protect epilogue pbuf reuse of staging arena

    // fused epilogue: BN + ReLU + 2x2 maxpool
    int gq = lane >> 2, tq = lane & 3;
    if (S == 64) {
        float* pbuf = (float*)dsm;
#pragma unroll
        for (int mi = 0; mi < 2; mi++)
#pragma unroll
            for (int h = 0; h < 2; h++) {
                int r = wm * 32 + mi * 16 + h * 8 + gq;
                float sc = ssc[r], sh = sbi[r];
#pragma unroll
                for (int ni = 0; ni < 8; ni++) {
                    float v0 = fmaxf(fmaf(acc[mi][ni][2 * h],     sc, sh), 0.f);
                    float v1 = fmaxf(fmaf(acc[mi][ni][2 * h + 1], sc, sh), 0.f);
                    pbuf[r * 64 + wn * 32 + ni * 4 + tq] = fmaxf(v0, v1);
                }
            }
        __syncthreads();
        const int HP = 32;
        for (int i = tid; i < 128 * 32; i += 256) {
            int oc = i >> 5, xh = i & 31;
            float vv = fmaxf(pbuf[oc * 64 + xh], pbuf[oc * 64 + 32 + xh]);
            out[((size_t)(frame * OCTOT + ocb + oc) * HP + ntile) * HP + xh] = vv;
        }
    } else {
        const int HP = 16;
#pragma unroll
        for (int mi = 0; mi < 2; mi++)
#pragma unroll
            for (int h = 0; h < 2; h++) {
                int r = wm * 32 + mi * 16 + h * 8 + gq;
                float sc = ssc[r], sh = sbi[r];
#pragma unroll
                for (int n4 = 0; n4 < 4; n4++) {
                    float a0 = fmaxf(fmaf(acc[mi][n4][2 * h],         sc, sh), 0.f);
                    float a1 = fmaxf(fmaf(acc[mi][n4][2 * h + 1],     sc, sh), 0.f);
                    float b0 = fmaxf(fmaf(acc[mi][n4 + 4][2 * h],     sc, sh), 0.f);
                    float b1 = fmaxf(fmaf(acc[mi][n4 + 4][2 * h + 1], sc, sh), 0.f);
                    float mx = fmaxf(fmaxf(a0, a1), fmaxf(b0, b1));
                    int yq = ntile * 2 + wn;
                    int xq = n4 * 4 + tq;
                    out[((size_t)(frame * OCTOT + ocb + r) * HP + yq) * HP + xq] = mx;
                }
            }
    }
}

// ---------------------------------------------------------------------------
// Hoisted L0 x-half GEMM: Zx0[slab] = Wx0 * im2col(x0[slab]). Triple buffer.
// Grid (8, 2, 32), 256 threads, K = 144 x-chunks.
// ---------------------------------------------------------------------------
__global__ void __launch_bounds__(256, 2) lstm_xgemm()
{
    extern __shared__ __align__(16) char dsm[];

    int tid  = threadIdx.x;
    int lane = tid & 31;
    int wid  = tid >> 5;
    int wm = wid & 3, wn = wid >> 2;

    int mtile = blockIdx.x;
    int ntile = blockIdx.y;
    int slab  = blockIdx.z;
    int ocb   = mtile * 128;

    const __half* bxh = g_bx0h + (size_t)slab * BHS;
    const __half* bxl = g_bx0l + (size_t)slab * BHS;

    uint32_t dbase = smem_u32(dsm);
    uint32_t ahb[3] = { dbase,         dbase + 6144,  dbase + 12288 };
    uint32_t alb[3] = { dbase + 18432, dbase + 24576, dbase + 30720 };
    uint32_t bhb[3] = { dbase + 36864, dbase + 41216, dbase + 45568 };
    uint32_t blb[3] = { dbase + 49920, dbase + 54272, dbase + 58624 };

    int arow = tid >> 1, au = tid & 1;
    uint32_t ao = arow * 48 + au * 16;
    uint32_t bo = (tid >> 4) * 272 + (tid & 15) * 16;
    size_t a_off_elem = (size_t)(arow + ocb) * 16 + au * 8;
    int b_src_off = (tid >> 4) * 256 + ntile * 128 + (tid & 15) * 8;

    int quad = lane >> 3, l7 = lane & 7;
    uint32_t a_off[2], b_off[4];
    {
        int rsub = ((quad & 1) << 3) + l7;
        int ksub = (quad >> 1) << 4;
#pragma unroll
        for (int mi = 0; mi < 2; mi++)
            a_off[mi] = (uint32_t)((wm * 32 + mi * 16 + rsub) * 48 + ksub);
        int krow = ((quad & 1) << 3) + l7;
        int nsub = (quad >> 1) << 3;
#pragma unroll
        for (int ni2 = 0; ni2 < 4; ni2++)
            b_off[ni2] = (uint32_t)(krow * 272 + (wn * 64 + ni2 * 16 + nsub) * 2);
    }

    float acc[2][8][4];
#pragma unroll
    for (int mi = 0; mi < 2; mi++)
#pragma unroll
        for (int ni = 0; ni < 8; ni++)
#pragma unroll
            for (int q = 0; q < 4; q++) acc[mi][ni][q] = 0.f;

    auto stage = [&](int jx, int buf) {
        int shift = jx >> 4, c16 = jx & 15;
        int G = shift * 32 + c16;
        size_t srow = ((size_t)(shift * 256 + c16 * 16)) << 8;
        cp16(ahb[buf] + ao, g_wph + (size_t)G * 16384 + a_off_elem);
        cp16(alb[buf] + ao, g_wpl + (size_t)G * 16384 + a_off_elem);
        cp16(bhb[buf] + bo, bxh + srow + b_src_off);
        cp16(blb[buf] + bo, bxl + srow + b_src_off);
        cp_commit();
    };

    stage(0, 0);
    stage(1, 1);

    int buf = 0;
    for (int j = 0; j < 144; j++) {
        if (j < 143) cp_wait<1>(); else cp_wait<0>();
        __syncthreads();

        uint32_t ah[2][4], al[2][4];
#pragma unroll
        for (int mi = 0; mi < 2; mi++) {
            ldm_x4(ah[mi], ahb[buf] + a_off[mi]);
            ldm_x4(al[mi], alb[buf] + a_off[mi]);
        }
#pragma unroll
        for (int ni2 = 0; ni2 < 4; ni2++) {
            uint32_t bhf[4], blf[4];
            ldm_x4t(bhf, bhb[buf] + b_off[ni2]);
            ldm_x4t(blf, blb[buf] + b_off[ni2]);
#pragma unroll
            for (int mi = 0; mi < 2; mi++)
#pragma unroll
                for (int q = 0; q < 2; q++) {
                    float* a_ = acc[mi][ni2 * 2 + q];
                    mma16816(a_, ah[mi], &bhf[q * 2]);
                    mma16816(a_, ah[mi], &blf[q * 2]);
                    mma16816(a_, al[mi], &bhf[q * 2]);
                }
        }

        if (j + 2 < 144) {
            int nb = buf + 2; if (nb >= 3) nb -= 3;
            stage(j + 2, nb);
        }
        if (++buf == 3) buf = 0;
    }

    int gq = lane >> 2, tq = lane & 3;
    float* zbase = g_zx0 + (size_t)slab * 262144;
    int row0 = ocb + wm * 32 + gq;
    int col0 = ntile * 128 + wn * 64 + 2 * tq;
#pragma unroll
    for (int mi = 0; mi < 2; mi++)
#pragma unroll
        for (int ni = 0; ni < 8; ni++) {
            int r = row0 + mi * 16;
            int cc = col0 + ni * 8;
            *(float2*)(zbase + (size_t)r * 256 + cc)       = make_float2(acc[mi][ni][0], acc[mi][ni][1]);
            *(float2*)(zbase + (size_t)(r + 8) * 256 + cc) = make_float2(acc[mi][ni][2], acc[mi][ni][3]);
        }
}

// ---------------------------------------------------------------------------
// Pipelined ConvLSTM MMA: step k runs L0(t=k) h-half and L1(t=k-1) full.
// Grid (8, 4, 9 slots). Triple buffer, 48 K-chunks per CTA.
// ---------------------------------------------------------------------------
__global__ void __launch_bounds__(256, 2) lstm_mma_pair(int k)
{
    int slot  = blockIdx.z;
    int layer = (slot >= 3);
    int t = layer ? (k - 1) : k;
    if (t < 0 || t > 15) return;

    extern __shared__ __align__(16) char dsm[];

    int tid  = threadIdx.x;
    int lane = tid & 31;
    int wid  = tid >> 5;
    int wm = wid & 3, wn = wid >> 2;

    int mtile = blockIdx.x;
    int ntile = blockIdx.y & 1;
    int b     = blockIdx.y >> 1;
    int ocb   = mtile * 128;

    const __half* bh0h = g_bhh + (size_t)b * BHS;
    const __half* bh0l = g_bhl + (size_t)b * BHS;
    const __half* bh1h = g_bhh + (size_t)(2 + b) * BHS;
    const __half* bh1l = g_bhl + (size_t)(2 + b) * BHS;
    const __half* wph = g_wph + (size_t)layer * 4718592;
    const __half* wpl = g_wpl + (size_t)layer * 4718592;

    uint32_t dbase = smem_u32(dsm);
    uint32_t ahb[3] = { dbase,         dbase + 6144,  dbase + 12288 };
    uint32_t alb[3] = { dbase + 18432, dbase + 24576, dbase + 30720 };
    uint32_t bhb[3] = { dbase + 36864, dbase + 41216, dbase + 45568 };
    uint32_t blb[3] = { dbase + 49920, dbase + 54272, dbase + 58624 };

    int arow = tid >> 1, au = tid & 1;
    uint32_t ao = arow * 48 + au * 16;
    uint32_t bo = (tid >> 4) * 272 + (tid & 15) * 16;
    size_t a_off_elem = (size_t)(arow + ocb) * 16 + au * 8;
    int b_src_off = (tid >> 4) * 256 + ntile * 128 + (tid & 15) * 8;

    int quad = lane >> 3, l7 = lane & 7;
    uint32_t a_off[2], b_off[4];
    {
        int rsub = ((quad & 1) << 3) + l7;
        int ksub = (quad >> 1) << 4;
#pragma unroll
        for (int mi = 0; mi < 2; mi++)
            a_off[mi] = (uint32_t)((wm * 32 + mi * 16 + rsub) * 48 + ksub);
        int krow = ((quad & 1) << 3) + l7;
        int nsub = (quad >> 1) << 3;
#pragma unroll
        for (int ni2 = 0; ni2 < 4; ni2++)
            b_off[ni2] = (uint32_t)(krow * 272 + (wn * 64 + ni2 * 16 + nsub) * 2);
    }

    float acc[2][8][4];
#pragma unroll
    for (int mi = 0; mi < 2; mi++)
#pragma unroll
        for (int ni = 0; ni < 8; ni++)
#pragma unroll
            for (int q = 0; q < 4; q++) acc[mi][ni][q] = 0.f;

    auto stage = [&](int j, int buf) {
        int G;
        const __half* bsh;
        const __half* bsl;
        size_t srow;
        if (slot < 3) {
            int jh = slot * 48 + j;
            int shift = jh >> 4, c16 = jh & 15;
            G = shift * 32 + 16 + c16;
            srow = ((size_t)(shift * 256 + c16 * 16)) << 8;
            bsh = bh0h; bsl = bh0l;
        } else {
            int jg = (slot - 3) * 48 + j;
            G = jg;
            int s9 = jg >> 5;
            int c0 = (jg & 31) << 4;
            bool isx = (c0 < 256);
            int cL = isx ? c0 : (c0 - 256);
            srow = ((size_t)(s9 * 256 + cL)) << 8;
            bsh = isx ? bh0h : bh1h;
            bsl = isx ? bh0l : bh1l;
        }
        cp16(ahb[buf] + ao, wph + (size_t)G * 16384 + a_off_elem);
        cp16(alb[buf] + ao, wpl + (size_t)G * 16384 + a_off_elem);
        cp16(bhb[buf] + bo, bsh + srow + b_src_off);
        cp16(blb[buf] + bo, bsl + srow + b_src_off);
        cp_commit();
    };

    stage(0, 0);
    stage(1, 1);

    int buf = 0;
    for (int j = 0; j < 48; j++) {
        if (j < 47) cp_wait<1>(); else cp_wait<0>();
        __syncthreads();

        uint32_t ah[2][4], al[2][4];
#pragma unroll
        for (int mi = 0; mi < 2; mi++) {
            ldm_x4(ah[mi], ahb[buf] + a_off[mi]);
            ldm_x4(al[mi], alb[buf] + a_off[mi]);
        }
#pragma unroll
        for (int ni2 = 0; ni2 < 4; ni2++) {
            uint32_t bhf[4], blf[4];
            ldm_x4t(bhf, bhb[buf] + b_off[ni2]);
            ldm_x4t(blf, blb[buf] + b_off[ni2]);
#pragma unroll
            for (int mi = 0; mi < 2; mi++)
#pragma unroll
                for (int q = 0; q < 2; q++) {
                    float* a_ = acc[mi][ni2 * 2 + q];
                    mma16816(a_, ah[mi], &bhf[q * 2]);
                    mma16816(a_, ah[mi], &blf[q * 2]);
                    mma16816(a_, al[mi], &bhf[q * 2]);
                }
        }

        if (j + 2 < 48) {
            int nb = buf + 2; if (nb >= 3) nb -= 3;
            stage(j + 2, nb);
        }
        if (++buf == 3) buf = 0;
    }

    int gq = lane >> 2, tq = lane & 3;
    float* zbase = g_zp + ((size_t)(slot * 2 + b) * 1024) * 256;
    int row0 = ocb + wm * 32 + gq;
    int col0 = ntile * 128 + wn * 64 + 2 * tq;
#pragma unroll
    for (int mi = 0; mi < 2; mi++)
#pragma unroll
        for (int ni = 0; ni < 8; ni++) {
            int r = row0 + mi * 16;
            int cc = col0 + ni * 8;
            *(float2*)(zbase + (size_t)r * 256 + cc)       = make_float2(acc[mi][ni][0], acc[mi][ni][1]);
            *(float2*)(zbase + (size_t)(r + 8) * 256 + cc) = make_float2(acc[mi][ni][2], acc[mi][ni][3]);
        }
}

// ---------------------------------------------------------------------------
// Pipelined gates: both layers in one launch (1024 CTAs).
// ---------------------------------------------------------------------------
__global__ void __launch_bounds__(256) lstm_gates_pair(int k,
                                                       const float* __restrict__ lb0,
                                                       const float* __restrict__ lb1,
                                                       float* __restrict__ out)
{
    int gid = blockIdx.x * 256 + threadIdx.x;
    int layer = gid >> 17;
    int idx = gid & 131071;
    int t = layer ? (k - 1) : k;
    if (t < 0 || t > 15) return;

    int inner = idx & 65535;
    int b = idx >> 16;
    int c = inner >> 8;
    int pos = inner & 255;
    const float* lb = layer ? lb1 : lb0;

    float zi = lb[c], zf = lb[c + 256], zo = lb[c + 512], zg = lb[c + 768];

    if (layer == 0) {
        const float* zx = g_zx0 + (size_t)(t * 2 + b) * 262144;
        zi += zx[(size_t)(c)       * 256 + pos];
        zf += zx[(size_t)(c + 256) * 256 + pos];
        zo += zx[(size_t)(c + 512) * 256 + pos];
        zg += zx[(size_t)(c + 768) * 256 + pos];
#pragma unroll
        for (int s = 0; s < 3; s++) {
            const float* zb = g_zp + ((size_t)(s * 2 + b)) * 1024 * 256;
            zi += zb[(size_t)(c)       * 256 + pos];
            zf += zb[(size_t)(c + 256) * 256 + pos];
            zo += zb[(size_t)(c + 512) * 256 + pos];
            zg += zb[(size_t)(c + 768) * 256 + pos];
        }
    } else {
#pragma unroll
        for (int s = 3; s < 9; s++) {
            const float* zb = g_zp + ((size_t)(s * 2 + b)) * 1024 * 256;
            zi += zb[(size_t)(c)       * 256 + pos];
            zf += zb[(size_t)(c + 256) * 256 + pos];
            zo += zb[(size_t)(c + 512) * 256 + pos];
            zg += zb[(size_t)(c + 768) * 256 + pos];
        }
    }

    size_t cidx = (size_t)layer * 131072 + idx;
    float cn = sigmoidf_(zf) * g_c[cidx] + sigmoidf_(zi) * tanhf(zg);
    float hn = sigmoidf_(zo) * tanhf(cn);
    g_c[cidx] = cn;

    __half hh = __float2half(hn);
    __half hl = __float2half(hn - __half2float(hh));
    int y = pos >> 4, x = pos & 15;
    __half* bhhp = g_bhh + (size_t)(layer * 2 + b) * BHS;
    __half* bhlp = g_bhl + (size_t)(layer * 2 + b) * BHS;
#pragma unroll
    for (int s = 0; s < 9; s++) {
        int dy = s / 3 - 1, dx = s % 3 - 1;
        int ny = y - dy, nx = x - dx;
        if (ny >= 0 && ny < 16 && nx >= 0 && nx < 16) {
            int o = ((s * 256 + c) << 8) + ny * 16 + nx;
            bhhp[o] = hh;
            bhlp[o] = hl;
        }
    }

    if (layer == 1)
        out[(size_t)b * 16 * CHW2 + (size_t)t * CHW2 + inner] = hn;
}

// zero c (both layers) and h im2col buffers (both layers)
__global__ void __launch_bounds__(256) zero_state()
{
    int idx = blockIdx.x * 256 + threadIdx.x;   // 2359296
    if (idx < 262144) g_c[idx] = 0.f;
    g_bhh[idx] = __float2half(0.f);
    g_bhl[idx] = __float2half(0.f);
}

__global__ void __launch_bounds__(256) copy_last(float* __restrict__ out)
{
    int idx = blockIdx.x * 256 + threadIdx.x;
    int inner = idx & 65535;
    int b = idx >> 16;
    out[2097152 + idx] = out[(size_t)b * 16 * CHW2 + 15 * CHW2 + inner];
}

// ---------------------------------------------------------------------------
// Launch sequence (graph-capturable)
// ---------------------------------------------------------------------------
extern "C" void kernel_launch(void* const* d_in, const int* in_sizes, int n_in,
                              void* d_out, int out_size)
{
    const float* x   = (const float*)d_in[0];
    const float* w0  = (const float*)d_in[1];
    const float* b0  = (const float*)d_in[2];
    const float* g0  = (const float*)d_in[3];
    const float* be0 = (const float*)d_in[4];
    const float* m0  = (const float*)d_in[5];
    const float* v0  = (const float*)d_in[6];
    const float* w1  = (const float*)d_in[7];
    const float* b1  = (const float*)d_in[8];
    const float* g1  = (const float*)d_in[9];
    const float* be1 = (const float*)d_in[10];
    const float* m1  = (const float*)d_in[11];
    const float* v1  = (const float*)d_in[12];
    const float* w2  = (const float*)d_in[13];
    const float* b2  = (const float*)d_in[14];
    const float* g2  = (const float*)d_in[15];
    const float* be2 = (const float*)d_in[16];
    const float* m2  = (const float*)d_in[17];
    const float* v2  = (const float*)d_in[18];
    const float* lw0 = (const float*)d_in[19];
    const float* lb0 = (const float*)d_in[20];
    const float* lw1 = (const float*)d_in[21];
    const float* lb1 = (const float*)d_in[22];
    float* out = (float*)d_out;

    static bool attr = false;
    if (!attr) {
        cudaFuncSetAttribute(lstm_mma_pair, cudaFuncAttributeMaxDynamicSharedMemorySize, DSM_BYTES);
        cudaFuncSetAttribute(lstm_xgemm, cudaFuncAttributeMaxDynamicSharedMemorySize, DSM_BYTES);
        cudaFuncSetAttribute(conv_mma<64, 64, 128>, cudaFuncAttributeMaxDynamicSharedMemorySize, DSM_BYTES);
        cudaFuncSetAttribute(conv_mma<128, 32, 256>, cudaFuncAttributeMaxDynamicSharedMemorySize, DSM_BYTES);
        attr = true;
    }

    float* f0ptr;  cudaGetSymbolAddress((void**)&f0ptr, g_f0);
    float* f1ptr;  cudaGetSymbolAddress((void**)&f1ptr, g_f1);
    float* f2ptr;  cudaGetSymbolAddress((void**)&f2ptr, g_f2);
    __half* wc1h; cudaGetSymbolAddress((void**)&wc1h, g_wc1h);
    __half* wc1l; cudaGetSymbolAddress((void**)&wc1l, g_wc1l);
    __half* wc2h; cudaGetSymbolAddress((void**)&wc2h, g_wc2h);
    __half* wc2l; cudaGetSymbolAddress((void**)&wc2l, g_wc2l);

    // weight prepacks
    prepack_w2<<<dim3(1024, 2), 256>>>(lw0, lw1);
    prepack_cw<64, 128><<<288, 256>>>(w1, wc1h, wc1l);
    prepack_cw<128, 256><<<1152, 256>>>(w2, wc2h, wc2l);

    // CNN encoder (pool fused into conv_mma epilogue)
    conv0_pool<<<32768, 256>>>(x, w0, b0, g0, be0, m0, v0);
    conv_mma<64, 64, 128><<<dim3(32, 1, 32), 256, DSM_BYTES>>>(f0ptr, wc1h, wc1l,
                                                               b1, g1, be1, m1, v1, f1ptr);
    conv_mma<128, 32, 256><<<dim3(8, 2, 32), 256, DSM_BYTES>>>(f1ptr, wc2h, wc2l,
                                                               b2, g2, be2, m2, v2, f2ptr);

    // hi/lo fp16 im2col of CNN features
    build_bx0<<<73728, 256>>>();

    // hoisted L0 x-half GEMM for all 32 (t,b) slabs
    lstm_xgemm<<<dim3(8, 2, 32), 256, DSM_BYTES>>>();

    // Pipelined ConvLSTM: step k = L0(t=k) h-half + L1(t=k-1) full
    zero_state<<<9216, 256>>>();
    for (int k = 0; k <= 16; k++) {
        lstm_mma_pair<<<dim3(8, 4, 9), 256, DSM_BYTES>>>(k);
        lstm_gates_pair<<<1024, 256>>>(k, lb0, lb1, out);
    }

    copy_last<<<512, 256>>>(out);
}

// round 17
// speedup vs baseline: 1.9577x; 1.0032x over previous
#include <cuda_runtime.h>
#include <cuda_fp16.h>
#include <math.h>
#include <stdint.h>

// ---------------------------------------------------------------------------
//   block0: 1->64 SIMT (smem-tiled, f32x2); block1/2 + ConvLSTM convs:
//   3xFP16 mma.sync GEMM (D += Ah*Bh + Ah*Bl + Al*Bh), K=16 chunks,
//   TRIPLE buffer (1 barrier/chunk).
// ConvLSTM layers software-pipelined: step k runs L0(t=k) and L1(t=k-1).
//   - L0's x-half GEMM hoisted (Zx0; B staged on the fly from f2,
//     with slab->frame remap: zx0 slab = t*2+b, f2 frame = b*16+t)
//   - L1's x-input read directly from L0's bh buffer
//   - in-loop slots balanced: every CTA does 48 K-chunks (L0 3, L1 6)
// Dynamic smem (bytes): Ah 3x6144 @0, Al 3x6144 @18432,
//   Bh 3x4352 @36864, Bl 3x4352 @49920; total 62976.
// ---------------------------------------------------------------------------

#define CHW2 65536          // 256*16*16
#define BHS  589824         // 9*256*256
#define DSM_BYTES 62976

typedef unsigned long long ull;

// ============================ PTX helpers ==================================
__device__ __forceinline__ uint32_t smem_u32(const void* p) {
    uint32_t a;
    asm("{ .reg .u64 t; cvta.to.shared.u64 t, %1; cvt.u32.u64 %0, t; }" : "=r"(a) : "l"(p));
    return a;
}
__device__ __forceinline__ void ldm_x4(uint32_t* r, uint32_t addr) {
    asm volatile("ldmatrix.sync.aligned.m8n8.x4.shared.b16 {%0,%1,%2,%3}, [%4];"
        : "=r"(r[0]), "=r"(r[1]), "=r"(r[2]), "=r"(r[3]) : "r"(addr));
}
__device__ __forceinline__ void ldm_x4t(uint32_t* r, uint32_t addr) {
    asm volatile("ldmatrix.sync.aligned.m8n8.x4.trans.shared.b16 {%0,%1,%2,%3}, [%4];"
        : "=r"(r[0]), "=r"(r[1]), "=r"(r[2]), "=r"(r[3]) : "r"(addr));
}
__device__ __forceinline__ void mma16816(float* d, const uint32_t* a, const uint32_t* b) {
    asm volatile(
        "mma.sync.aligned.m16n8k16.row.col.f32.f16.f16.f32 "
        "{%0,%1,%2,%3}, {%4,%5,%6,%7}, {%8,%9}, {%0,%1,%2,%3};"
        : "+f"(d[0]), "+f"(d[1]), "+f"(d[2]), "+f"(d[3])
        : "r"(a[0]), "r"(a[1]), "r"(a[2]), "r"(a[3]), "r"(b[0]), "r"(b[1]));
}
__device__ __forceinline__ void cp16(uint32_t sdst, const void* gsrc) {
    asm volatile("cp.async.cg.shared.global [%0], [%1], 16;" :: "r"(sdst), "l"(gsrc));
}
__device__ __forceinline__ void cp_commit() { asm volatile("cp.async.commit_group;"); }
template <int N> __device__ __forceinline__ void cp_wait() {
    asm volatile("cp.async.wait_group %0;" :: "n"(N));
}
__device__ __forceinline__ ull pack2(float lo, float hi) {
    ull r; asm("mov.b64 %0, {%1,%2};" : "=l"(r) : "f"(lo), "f"(hi)); return r;
}
__device__ __forceinline__ void unpack2(ull v, float& lo, float& hi) {
    asm("mov.b64 {%0,%1}, %2;" : "=f"(lo), "=f"(hi) : "l"(v));
}
__device__ __forceinline__ ull fma2(ull a, ull b, ull c) {
    ull d; asm("fma.rn.f32x2 %0, %1, %2, %3;" : "=l"(d) : "l"(a), "l"(b), "l"(c));
    return d;
}
__device__ __forceinline__ float sigmoidf_(float x) { return 1.0f / (1.0f + expf(-x)); }

// ---------------------------------------------------------------------------
// Scratch
// ---------------------------------------------------------------------------
__device__ __align__(256) float  g_f0[32 * 64 * 64 * 64];
__device__ __align__(256) float  g_f1[32 * 128 * 32 * 32];
__device__ __align__(256) float  g_f2[32 * 256 * 16 * 16];
__device__ __align__(256) __half g_wc1h[36 * 128 * 16];
__device__ __align__(256) __half g_wc1l[36 * 128 * 16];
__device__ __align__(256) __half g_wc2h[72 * 256 * 16];
__device__ __align__(256) __half g_wc2l[72 * 256 * 16];
__device__ __align__(256) __half g_wph[2 * 288 * 1024 * 16];  // [layer][G][oc][16]
__device__ __align__(256) __half g_wpl[2 * 288 * 1024 * 16];
__device__ __align__(256) __half g_bhh[2 * 2 * BHS];          // h im2col [layer][b][s][c][n]
__device__ __align__(256) __half g_bhl[2 * 2 * BHS];
__device__ __align__(256) float  g_c[2 * 2 * CHW2];           // cell state [layer][b]
__device__ __align__(256) float  g_zx0[32 * 1024 * 256];      // hoisted L0 x-half GEMM
__device__ __align__(256) float  g_zp[9 * 2 * 1024 * 256];    // partials [slot][b][oc][pos]

// ---------------------------------------------------------------------------
// LSTM weight prepack (coalesced transpose): one oc per CTA, both layers.
// ---------------------------------------------------------------------------
__global__ void __launch_bounds__(256) prepack_w2(const float* __restrict__ lw0,
                                                  const float* __restrict__ lw1)
{
    __shared__ float wbuf[4608];
    int oc = blockIdx.x;
    int layer = blockIdx.y;
    const float* lw = layer ? lw1 : lw0;
    int tid = threadIdx.x;

    for (int i = tid; i < 4608; i += 256)
        wbuf[i] = lw[(size_t)oc * 4608 + i];
    __syncthreads();

    size_t base = (size_t)layer * 4718592;
    for (int k = tid; k < 4608; k += 256) {
        int s = k >> 9, c = k & 511;
        float w = wbuf[c * 9 + s];
        __half hi = __float2half(w);
        size_t o = base + ((size_t)(k >> 4) * 1024 + oc) * 16 + (k & 15);
        g_wph[o] = hi;
        g_wpl[o] = __float2half(w - __half2float(hi));
    }
}

// ---------------------------------------------------------------------------
// CNN conv weight prepack: [G][oc][16]
// ---------------------------------------------------------------------------
template <int CIN, int OCTOT>
__global__ void __launch_bounds__(256) prepack_cw(
    const float* __restrict__ w, __half* __restrict__ outh, __half* __restrict__ outl)
{
    constexpr int CPG = CIN / 16;
    int idx = blockIdx.x * 256 + threadIdx.x;
    int u  = idx & 15;
    int oc = (idx >> 4) % OCTOT;
    int G  = (idx >> 4) / OCTOT;
    int s  = G / CPG;
    int c  = (G % CPG) * 16 + u;
    float val = w[((size_t)oc * CIN + c) * 9 + s];
    __half hi = __float2half(val);
    outh[idx] = hi;
    outl[idx] = __float2half(val - __half2float(hi));
}

// ---------------------------------------------------------------------------
// Block 0 conv+BN+ReLU+pool, smem-tiled:
//   CTA = one 32x32 conv region of one frame; input tile staged once.
//   Each thread: 4 conv positions (one pooled output) x all 64 oc.
// ---------------------------------------------------------------------------
__global__ void __launch_bounds__(256) conv0_pool(
    const float* __restrict__ x, const float* __restrict__ w,
    const float* __restrict__ bias, const float* __restrict__ g,
    const float* __restrict__ be, const float* __restrict__ m,
    const float* __restrict__ v)
{
    __shared__ float tile[34][36];
    __shared__ ull   wp[9][32];
    __shared__ float ssm[64], bsm[64];

    int tid = threadIdx.x;
    int reg = blockIdx.x;                 // 16 regions (4x4 of 32x32)
    int n   = blockIdx.y;                 // frame
    int ry0 = (reg >> 2) * 32, rx0 = (reg & 3) * 32;

    const float* xi = x + (size_t)n * 16384;
    for (int i = tid; i < 1156; i += 256) {
        int r = i / 34, c = i % 34;
        int gy = ry0 - 1 + r, gx = rx0 - 1 + c;
        tile[r][c] = (gy >= 0 && gy < 128 && gx >= 0 && gx < 128)
                   ? xi[gy * 128 + gx] : 0.f;
    }
    for (int i = tid; i < 288; i += 256) {
        int k = i >> 5, p = i & 31;
        wp[k][p] = pack2(w[(2 * p) * 9 + k], w[(2 * p + 1) * 9 + k]);
    }
    if (tid < 64) {
        float s = g[tid] * rsqrtf(v[tid] + 1e-5f);
        ssm[tid] = s;
        bsm[tid] = (bias[tid] - m[tid]) * s + be[tid];
    }
    __syncthreads();

    int py = tid >> 4, px = tid & 15;
    int ly = 2 * py, lx = 2 * px;

    ull inp[4][4];
#pragma unroll
    for (int r = 0; r < 4; r++)
#pragma unroll
        for (int c = 0; c < 4; c++) {
            float vv = tile[ly + r][lx + c];
            inp[r][c] = pack2(vv, vv);
        }

    int oy = (ry0 >> 1) + py, ox = (rx0 >> 1) + px;
    float* outb = g_f0 + ((size_t)n * 64 * 4096) + (size_t)oy * 64 + ox;

#pragma unroll 2
    for (int p = 0; p < 32; p++) {
        ull a0 = 0ULL, a1 = 0ULL, a2 = 0ULL, a3 = 0ULL;
#pragma unroll
        for (int k = 0; k < 9; k++) {
            int dy = k / 3, dx = k % 3;
            ull wk = wp[k][p];
            a0 = fma2(inp[dy][dx],         wk, a0);
            a1 = fma2(inp[dy][dx + 1],     wk, a1);
            a2 = fma2(inp[dy + 1][dx],     wk, a2);
            a3 = fma2(inp[dy + 1][dx + 1], wk, a3);
        }
        float s00, s01, s10, s11, t00, t01, t10, t11;
        unpack2(a0, s00, t00); unpack2(a1, s01, t01);
        unpack2(a2, s10, t10); unpack2(a3, s11, t11);
        int oc0 = 2 * p, oc1 = 2 * p + 1;
        float sc0 = ssm[oc0], sh0 = bsm[oc0];
        float sc1 = ssm[oc1], sh1 = bsm[oc1];
        float m0_ = fmaxf(fmaxf(fmaxf(fmaf(s00, sc0, sh0), fmaf(s01, sc0, sh0)),
                                fmaf(s10, sc0, sh0)), fmaf(s11, sc0, sh0));
        float m1_ = fmaxf(fmaxf(fmaxf(fmaf(t00, sc1, sh1), fmaf(t01, sc1, sh1)),
                                fmaf(t10, sc1, sh1)), fmaf(t11, sc1, sh1));
        outb[(size_t)oc0 * 4096] = fmaxf(m0_, 0.f);
        outb[(size_t)oc1 * 4096] = fmaxf(m1_, 0.f);
    }
}

// ---------------------------------------------------------------------------
// CNN conv via 3xFP16 GEMM + fused 2x2 maxpool. Triple-buffered staging.
// ---------------------------------------------------------------------------
template <int CIN, int S, int OCTOT>
__global__ void __launch_bounds__(256, 2) conv_mma(
    const float* __restrict__ in,
    const __half* __restrict__ wph, const __half* __restrict__ wpl,
    const float* __restrict__ bias, const float* __restrict__ g,
    const float* __restrict__ be, const float* __restrict__ m,
    const float* __restrict__ v, float* __restrict__ out)
{
    constexpr int NPOS = S * S;
    constexpr int CPG  = CIN / 16;
    constexpr int NG   = 9 * CPG;
    constexpr int LOGS = (S == 64) ? 6 : 5;

    extern __shared__ __align__(16) char dsm[];
    __shared__ float ssc[128], sbi[128];

    int tid = threadIdx.x, lane = tid & 31, wid = tid >> 5;
    int wm = wid & 3, wn = wid >> 2;
    int ntile = blockIdx.x;
    int ocb   = blockIdx.y * 128;
    int frame = blockIdx.z;

    if (tid < 128) {
        int oc = ocb + tid;
        float s_ = g[oc] * rsqrtf(v[oc] + 1e-5f);
        ssc[tid] = s_;
        sbi[tid] = (bias[oc] - m[oc]) * s_ + be[oc];
    }

    uint32_t dbase = smem_u32(dsm);
    uint32_t ahb[3] = { dbase,         dbase + 6144,  dbase + 12288 };
    uint32_t alb[3] = { dbase + 18432, dbase + 24576, dbase + 30720 };
    uint32_t bhb[3] = { dbase + 36864, dbase + 41216, dbase + 45568 };
    uint32_t blb[3] = { dbase + 49920, dbase + 54272, dbase + 58624 };

    int arow = tid >> 1, au = tid & 1;
    uint32_t ao = arow * 48 + au * 16;
    size_t a_off_elem = (size_t)(ocb + arow) * 16 + au * 8;

    int bk = tid >> 4, bn = tid & 15;
    int nbase = ntile * 128 + bn * 8;
    uint32_t bo = bk * 272 + bn * 16;

    float breg[8];
    auto prefetchB = [&](int G) {
        int s = G / CPG, q = G - s * CPG;
        int dy = s / 3 - 1, dx = s % 3 - 1;
        const float* src = in + ((size_t)frame * CIN + q * 16 + bk) * NPOS;
#pragma unroll
        for (int j = 0; j < 8; j++) {
            int pos = nbase + j;
            int y = pos >> LOGS, x = pos & (S - 1);
            int iy = y + dy, ix = x + dx;
            breg[j] = (iy >= 0 && iy < S && ix >= 0 && ix < S) ? src[iy * S + ix] : 0.f;
        }
    };
    auto stsB = [&](int buf) {
        __half hv[8], lv[8];
#pragma unroll
        for (int j = 0; j < 8; j++) {
            hv[j] = __float2half(breg[j]);
            lv[j] = __float2half(breg[j] - __half2float(hv[j]));
        }
        *(uint4*)(dsm + 36864 + buf * 4352 + bo) = *(uint4*)hv;
        *(uint4*)(dsm + 49920 + buf * 4352 + bo) = *(uint4*)lv;
    };
    auto cpA = [&](int G, int buf) {
        cp16(ahb[buf] + ao, wph + (size_t)G * (OCTOT * 16) + a_off_elem);
        cp16(alb[buf] + ao, wpl + (size_t)G * (OCTOT * 16) + a_off_elem);
        cp_commit();
    };

    int quad = lane >> 3, l7 = lane & 7;
    uint32_t a_off[2], b_off[4];
    {
        int rsub = ((quad & 1) << 3) + l7;
        int ksub = (quad >> 1) << 4;
#pragma unroll
        for (int mi = 0; mi < 2; mi++)
            a_off[mi] = (uint32_t)((wm * 32 + mi * 16 + rsub) * 48 + ksub);
        int krow = ((quad & 1) << 3) + l7;
        int nsub = (quad >> 1) << 3;
#pragma unroll
        for (int ni2 = 0; ni2 < 4; ni2++)
            b_off[ni2] = (uint32_t)(krow * 272 + (wn * 64 + ni2 * 16 + nsub) * 2);
    }

    float acc[2][8][4];
#pragma unroll
    for (int mi = 0; mi < 2; mi++)
#pragma unroll
        for (int ni = 0; ni < 8; ni++)
#pragma unroll
            for (int q = 0; q < 4; q++) acc[mi][ni][q] = 0.f;

    prefetchB(0); stsB(0); cpA(0, 0);
    prefetchB(1); stsB(1); cpA(1, 1);
    if (NG > 2) prefetchB(2);

    int buf = 0;
    for (int j = 0; j < NG; j++) {
        if (j < NG - 1) cp_wait<1>(); else cp_wait<0>();
        __syncthreads();

        uint32_t ah[2][4], al[2][4];
#pragma unroll
        for (int mi = 0; mi < 2; mi++) {
            ldm_x4(ah[mi], ahb[buf] + a_off[mi]);
            ldm_x4(al[mi], alb[buf] + a_off[mi]);
        }
#pragma unroll
        for (int ni2 = 0; ni2 < 4; ni2++) {
            uint32_t bhf[4], blf[4];
            ldm_x4t(bhf, bhb[buf] + b_off[ni2]);
            ldm_x4t(blf, blb[buf] + b_off[ni2]);
#pragma unroll
            for (int mi = 0; mi < 2; mi++)
#pragma unroll
                for (int q = 0; q < 2; q++) {
                    float* a_ = acc[mi][ni2 * 2 + q];
                    mma16816(a_, ah[mi], &bhf[q * 2]);
                    mma16816(a_, ah[mi], &blf[q * 2]);
                    mma16816(a_, al[mi], &bhf[q * 2]);
                }
        }

        if (j + 2 < NG) {
            int nb = buf + 2; if (nb >= 3) nb -= 3;
            stsB(nb);
            cpA(j + 2, nb);
            if (j + 3 < NG) prefetchB(j + 3);
        }
        if (++buf == 3) buf = 0;
    }
    __syncthreads();

    // fused epilogue: BN + ReLU + 2x2 maxpool
    int gq = lane >> 2, tq = lane & 3;
    if (S == 64) {
        float* pbuf = (float*)dsm;
#pragma unroll
        for (int mi = 0; mi < 2; mi++)
#pragma unroll
            for (int h = 0; h < 2; h++) {
                int r = wm * 32 + mi * 16 + h * 8 + gq;
                float sc = ssc[r], sh = sbi[r];
#pragma unroll
                for (int ni = 0; ni < 8; ni++) {
                    float v0 = fmaxf(fmaf(acc[mi][ni][2 * h],     sc, sh), 0.f);
                    float v1 = fmaxf(fmaf(acc[mi][ni][2 * h + 1], sc, sh), 0.f);
                    pbuf[r * 64 + wn * 32 + ni * 4 + tq] = fmaxf(v0, v1);
                }
            }
        __syncthreads();
        const int HP = 32;
        for (int i = tid; i < 128 * 32; i += 256) {
            int oc = i >> 5, xh = i & 31;
            float vv = fmaxf(pbuf[oc * 64 + xh], pbuf[oc * 64 + 32 + xh]);
            out[((size_t)(frame * OCTOT + ocb + oc) * HP + ntile) * HP + xh] = vv;
        }
    } else {
        const int HP = 16;
#pragma unroll
        for (int mi = 0; mi < 2; mi++)
#pragma unroll
            for (int h = 0; h < 2; h++) {
                int r = wm * 32 + mi * 16 + h * 8 + gq;
                float sc = ssc[r], sh = sbi[r];
#pragma unroll
                for (int n4 = 0; n4 < 4; n4++) {
                    float a0 = fmaxf(fmaf(acc[mi][n4][2 * h],         sc, sh), 0.f);
                    float a1 = fmaxf(fmaf(acc[mi][n4][2 * h + 1],     sc, sh), 0.f);
                    float b0 = fmaxf(fmaf(acc[mi][n4 + 4][2 * h],     sc, sh), 0.f);
                    float b1 = fmaxf(fmaf(acc[mi][n4 + 4][2 * h + 1], sc, sh), 0.f);
                    float mx = fmaxf(fmaxf(a0, a1), fmaxf(b0, b1));
                    int yq = ntile * 2 + wn;
                    int xq = n4 * 4 + tq;
                    out[((size_t)(frame * OCTOT + ocb + r) * HP + yq) * HP + xq] = mx;
                }
            }
    }
}

// ---------------------------------------------------------------------------
// Hoisted L0 x-half GEMM: Zx0[slab] = Wx0 * im2col(f2[frame]).
// zx0 slab = t*2+b; f2 frame = b*16+t  (slab->frame remap!).
// B staged on the fly from fp32 g_f2. Triple buffer. Grid (8, 2, 32), K=144.
// ---------------------------------------------------------------------------
__global__ void __launch_bounds__(256, 2) lstm_xgemm()
{
    extern __shared__ __align__(16) char dsm[];

    int tid  = threadIdx.x;
    int lane = tid & 31;
    int wid  = tid >> 5;
    int wm = wid & 3, wn = wid >> 2;

    int mtile = blockIdx.x;
    int ntile = blockIdx.y;
    int slab  = blockIdx.z;               // zx0 slab = t*2+b
    int ocb   = mtile * 128;

    int b_ = slab & 1, t_ = slab >> 1;
    int frame = b_ * 16 + t_;             // f2 frame = b*16+t
    const float* f2base = g_f2 + (size_t)frame * 65536;

    uint32_t dbase = smem_u32(dsm);
    uint32_t ahb[3] = { dbase,         dbase + 6144,  dbase + 12288 };
    uint32_t alb[3] = { dbase + 18432, dbase + 24576, dbase + 30720 };
    uint32_t bhb[3] = { dbase + 36864, dbase + 41216, dbase + 45568 };
    uint32_t blb[3] = { dbase + 49920, dbase + 54272, dbase + 58624 };

    int arow = tid >> 1, au = tid & 1;
    uint32_t ao = arow * 48 + au * 16;
    size_t a_off_elem = (size_t)(arow + ocb) * 16 + au * 8;

    int bk = tid >> 4, bn = tid & 15;
    int nbase = ntile * 128 + bn * 8;
    uint32_t bo = bk * 272 + bn * 16;

    float breg[8];
    auto prefetchB = [&](int jx) {
        int shift = jx >> 4, c16 = jx & 15;
        int dy = shift / 3 - 1, dx = shift % 3 - 1;
        const float* src = f2base + ((size_t)(c16 * 16 + bk)) * 256;
#pragma unroll
        for (int j = 0; j < 8; j++) {
            int pos = nbase + j;
            int y = pos >> 4, x = pos & 15;
            int iy = y + dy, ix = x + dx;
            breg[j] = (iy >= 0 && iy < 16 && ix >= 0 && ix < 16) ? src[iy * 16 + ix] : 0.f;
        }
    };
    auto stsB = [&](int buf) {
        __half hv[8], lv[8];
#pragma unroll
        for (int j = 0; j < 8; j++) {
            hv[j] = __float2half(breg[j]);
            lv[j] = __float2half(breg[j] - __half2float(hv[j]));
        }
        *(uint4*)(dsm + 36864 + buf * 4352 + bo) = *(uint4*)hv;
        *(uint4*)(dsm + 49920 + buf * 4352 + bo) = *(uint4*)lv;
    };
    auto cpA = [&](int jx, int buf) {
        int G = (jx >> 4) * 32 + (jx & 15);
        cp16(ahb[buf] + ao, g_wph + (size_t)G * 16384 + a_off_elem);
        cp16(alb[buf] + ao, g_wpl + (size_t)G * 16384 + a_off_elem);
        cp_commit();
    };

    int quad = lane >> 3, l7 = lane & 7;
    uint32_t a_off[2], b_off[4];
    {
        int rsub = ((quad & 1) << 3) + l7;
        int ksub = (quad >> 1) << 4;
#pragma unroll
        for (int mi = 0; mi < 2; mi++)
            a_off[mi] = (uint32_t)((wm * 32 + mi * 16 + rsub) * 48 + ksub);
        int krow = ((quad & 1) << 3) + l7;
        int nsub = (quad >> 1) << 3;
#pragma unroll
        for (int ni2 = 0; ni2 < 4; ni2++)
            b_off[ni2] = (uint32_t)(krow * 272 + (wn * 64 + ni2 * 16 + nsub) * 2);
    }

    float acc[2][8][4];
#pragma unroll
    for (int mi = 0; mi < 2; mi++)
#pragma unroll
        for (int ni = 0; ni < 8; ni++)
#pragma unroll
            for (int q = 0; q < 4; q++) acc[mi][ni][q] = 0.f;

    prefetchB(0); stsB(0); cpA(0, 0);
    prefetchB(1); stsB(1); cpA(1, 1);
    prefetchB(2);

    int buf = 0;
    for (int j = 0; j < 144; j++) {
        if (j < 143) cp_wait<1>(); else cp_wait<0>();
        __syncthreads();

        uint32_t ah[2][4], al[2][4];
#pragma unroll
        for (int mi = 0; mi < 2; mi++) {
            ldm_x4(ah[mi], ahb[buf] + a_off[mi]);
            ldm_x4(al[mi], alb[buf] + a_off[mi]);
        }
#pragma unroll
        for (int ni2 = 0; ni2 < 4; ni2++) {
            uint32_t bhf[4], blf[4];
            ldm_x4t(bhf, bhb[buf] + b_off[ni2]);
            ldm_x4t(blf, blb[buf] + b_off[ni2]);
#pragma unroll
            for (int mi = 0; mi < 2; mi++)
#pragma unroll
                for (int q = 0; q < 2; q++) {
                    float* a_ = acc[mi][ni2 * 2 + q];
                    mma16816(a_, ah[mi], &bhf[q * 2]);
                    mma16816(a_, ah[mi], &blf[q * 2]);
                    mma16816(a_, al[mi], &bhf[q * 2]);
                }
        }

        if (j + 2 < 144) {
            int nb = buf + 2; if (nb >= 3) nb -= 3;
            stsB(nb);
            cpA(j + 2, nb);
            if (j + 3 < 144) prefetchB(j + 3);
        }
        if (++buf == 3) buf = 0;
    }

    int gq = lane >> 2, tq = lane & 3;
    float* zbase = g_zx0 + (size_t)slab * 262144;
    int row0 = ocb + wm * 32 + gq;
    int col0 = ntile * 128 + wn * 64 + 2 * tq;
#pragma unroll
    for (int mi = 0; mi < 2; mi++)
#pragma unroll
        for (int ni = 0; ni < 8; ni++) {
            int r = row0 + mi * 16;
            int cc = col0 + ni * 8;
            *(float2*)(zbase + (size_t)r * 256 + cc)       = make_float2(acc[mi][ni][0], acc[mi][ni][1]);
            *(float2*)(zbase + (size_t)(r + 8) * 256 + cc) = make_float2(acc[mi][ni][2], acc[mi][ni][3]);
        }
}

// ---------------------------------------------------------------------------
// Pipelined ConvLSTM MMA: step k runs L0(t=k) h-half and L1(t=k-1) full.
// Grid (8, 4, 9 slots). Triple buffer, 48 K-chunks per CTA.
// ---------------------------------------------------------------------------
__global__ void __launch_bounds__(256, 2) lstm_mma_pair(int k)
{
    int slot  = blockIdx.z;
    int layer = (slot >= 3);
    int t = layer ? (k - 1) : k;
    if (t < 0 || t > 15) return;

    extern __shared__ __align__(16) char dsm[];

    int tid  = threadIdx.x;
    int lane = tid & 31;
    int wid  = tid >> 5;
    int wm = wid & 3, wn = wid >> 2;

    int mtile = blockIdx.x;
    int ntile = blockIdx.y & 1;
    int b     = blockIdx.y >> 1;
    int ocb   = mtile * 128;

    const __half* bh0h = g_bhh + (size_t)b * BHS;
    const __half* bh0l = g_bhl + (size_t)b * BHS;
    const __half* bh1h = g_bhh + (size_t)(2 + b) * BHS;
    const __half* bh1l = g_bhl + (size_t)(2 + b) * BHS;
    const __half* wph = g_wph + (size_t)layer * 4718592;
    const __half* wpl = g_wpl + (size_t)layer * 4718592;

    uint32_t dbase = smem_u32(dsm);
    uint32_t ahb[3] = { dbase,         dbase + 6144,  dbase + 12288 };
    uint32_t alb[3] = { dbase + 18432, dbase + 24576, dbase + 30720 };
    uint32_t bhb[3] = { dbase + 36864, dbase + 41216, dbase + 45568 };
    uint32_t blb[3] = { dbase + 49920, dbase + 54272, dbase + 58624 };

    int arow = tid >> 1, au = tid & 1;
    uint32_t ao = arow * 48 + au * 16;
    uint32_t bo = (tid >> 4) * 272 + (tid & 15) * 16;
    size_t a_off_elem = (size_t)(arow + ocb) * 16 + au * 8;
    int b_src_off = (tid >> 4) * 256 + ntile * 128 + (tid & 15) * 8;

    int quad = lane >> 3, l7 = lane & 7;
    uint32_t a_off[2], b_off[4];
    {
        int rsub = ((quad & 1) << 3) + l7;
        int ksub = (quad >> 1) << 4;
#pragma unroll
        for (int mi = 0; mi < 2; mi++)
            a_off[mi] = (uint32_t)((wm * 32 + mi * 16 + rsub) * 48 + ksub);
        int krow = ((quad & 1) << 3) + l7;
        int nsub = (quad >> 1) << 3;
#pragma unroll
        for (int ni2 = 0; ni2 < 4; ni2++)
            b_off[ni2] = (uint32_t)(krow * 272 + (wn * 64 + ni2 * 16 + nsub) * 2);
    }

    float acc[2][8][4];
#pragma unroll
    for (int mi = 0; mi < 2; mi++)
#pragma unroll
        for (int ni = 0; ni < 8; ni++)
#pragma unroll
            for (int q = 0; q < 4; q++) acc[mi][ni][q] = 0.f;

    auto stage = [&](int j, int buf) {
        int G;
        const __half* bsh;
        const __half* bsl;
        size_t srow;
        if (slot < 3) {
            int jh = slot * 48 + j;
            int shift = jh >> 4, c16 = jh & 15;
            G = shift * 32 + 16 + c16;
            srow = ((size_t)(shift * 256 + c16 * 16)) << 8;
            bsh = bh0h; bsl = bh0l;
        } else {
            int jg = (slot - 3) * 48 + j;
            G = jg;
            int s9 = jg >> 5;
            int c0 = (jg & 31) << 4;
            bool isx = (c0 < 256);
            int cL = isx ? c0 : (c0 - 256);
            srow = ((size_t)(s9 * 256 + cL)) << 8;
            bsh = isx ? bh0h : bh1h;
            bsl = isx ? bh0l : bh1l;
        }
        cp16(ahb[buf] + ao, wph + (size_t)G * 16384 + a_off_elem);
        cp16(alb[buf] + ao, wpl + (size_t)G * 16384 + a_off_elem);
        cp16(bhb[buf] + bo, bsh + srow + b_src_off);
        cp16(blb[buf] + bo, bsl + srow + b_src_off);
        cp_commit();
    };

    stage(0, 0);
    stage(1, 1);

    int buf = 0;
    for (int j = 0; j < 48; j++) {
        if (j < 47) cp_wait<1>(); else cp_wait<0>();
        __syncthreads();

        uint32_t ah[2][4], al[2][4];
#pragma unroll
        for (int mi = 0; mi < 2; mi++) {
            ldm_x4(ah[mi], ahb[buf] + a_off[mi]);
            ldm_x4(al[mi], alb[buf] + a_off[mi]);
        }
#pragma unroll
        for (int ni2 = 0; ni2 < 4; ni2++) {
            uint32_t bhf[4], blf[4];
            ldm_x4t(bhf, bhb[buf] + b_off[ni2]);
            ldm_x4t(blf, blb[buf] + b_off[ni2]);
#pragma unroll
            for (int mi = 0; mi < 2; mi++)
#pragma unroll
                for (int q = 0; q < 2; q++) {
                    float* a_ = acc[mi][ni2 * 2 + q];
                    mma16816(a_, ah[mi], &bhf[q * 2]);
                    mma16816(a_, ah[mi], &blf[q * 2]);
                    mma16816(a_, al[mi], &bhf[q * 2]);
                }
        }

        if (j + 2 < 48) {
            int nb = buf + 2; if (nb >= 3) nb -= 3;
            stage(j + 2, nb);
        }
        if (++buf == 3) buf = 0;
    }

    int gq = lane >> 2, tq = lane & 3;
    float* zbase = g_zp + ((size_t)(slot * 2 + b) * 1024) * 256;
    int row0 = ocb + wm * 32 + gq;
    int col0 = ntile * 128 + wn * 64 + 2 * tq;
#pragma unroll
    for (int mi = 0; mi < 2; mi++)
#pragma unroll
        for (int ni = 0; ni < 8; ni++) {
            int r = row0 + mi * 16;
            int cc = col0 + ni * 8;
            *(float2*)(zbase + (size_t)r * 256 + cc)       = make_float2(acc[mi][ni][0], acc[mi][ni][1]);
            *(float2*)(zbase + (size_t)(r + 8) * 256 + cc) = make_float2(acc[mi][ni][2], acc[mi][ni][3]);
        }
}

// ---------------------------------------------------------------------------
// Pipelined gates: both layers in one launch (1024 CTAs).
// ---------------------------------------------------------------------------
__global__ void __launch_bounds__(256) lstm_gates_pair(int k,
                                                       const float* __restrict__ lb0,
                                                       const float* __restrict__ lb1,
                                                       float* __restrict__ out)
{
    int gid = blockIdx.x * 256 + threadIdx.x;
    int layer = gid >> 17;
    int idx = gid & 131071;
    int t = layer ? (k - 1) : k;
    if (t < 0 || t > 15) return;

    int inner = idx & 65535;
    int b = idx >> 16;
    int c = inner >> 8;
    int pos = inner & 255;
    const float* lb = layer ? lb1 : lb0;

    float zi = lb[c], zf = lb[c + 256], zo = lb[c + 512], zg = lb[c + 768];

    if (layer == 0) {
        const float* zx = g_zx0 + (size_t)(t * 2 + b) * 262144;
        zi += zx[(size_t)(c)       * 256 + pos];
        zf += zx[(size_t)(c + 256) * 256 + pos];
        zo += zx[(size_t)(c + 512) * 256 + pos];
        zg += zx[(size_t)(c + 768) * 256 + pos];
#pragma unroll
        for (int s = 0; s < 3; s++) {
            const float* zb = g_zp + ((size_t)(s * 2 + b)) * 1024 * 256;
            zi += zb[(size_t)(c)       * 256 + pos];
            zf += zb[(size_t)(c + 256) * 256 + pos];
            zo += zb[(size_t)(c + 512) * 256 + pos];
            zg += zb[(size_t)(c + 768) * 256 + pos];
        }
    } else {
#pragma unroll
        for (int s = 3; s < 9; s++) {
            const float* zb = g_zp + ((size_t)(s * 2 + b)) * 1024 * 256;
            zi += zb[(size_t)(c)       * 256 + pos];
            zf += zb[(size_t)(c + 256) * 256 + pos];
            zo += zb[(size_t)(c + 512) * 256 + pos];
            zg += zb[(size_t)(c + 768) * 256 + pos];
        }
    }

    size_t cidx = (size_t)layer * 131072 + idx;
    float cn = sigmoidf_(zf) * g_c[cidx] + sigmoidf_(zi) * tanhf(zg);
    float hn = sigmoidf_(zo) * tanhf(cn);
    g_c[cidx] = cn;

    __half hh = __float2half(hn);
    __half hl = __float2half(hn - __half2float(hh));
    int y = pos >> 4, x = pos & 15;
    __half* bhhp = g_bhh + (size_t)(layer * 2 + b) * BHS;
    __half* bhlp = g_bhl + (size_t)(layer * 2 + b) * BHS;
#pragma unroll
    for (int s = 0; s < 9; s++) {
        int dy = s / 3 - 1, dx = s % 3 - 1;
        int ny = y - dy, nx = x - dx;
        if (ny >= 0 && ny < 16 && nx >= 0 && nx < 16) {
            int o = ((s * 256 + c) << 8) + ny * 16 + nx;
            bhhp[o] = hh;
            bhlp[o] = hl;
        }
    }

    if (layer == 1)
        out[(size_t)b * 16 * CHW2 + (size_t)t * CHW2 + inner] = hn;
}

// zero c (both layers) and h im2col buffers (both layers)
__global__ void __launch_bounds__(256) zero_state()
{
    int idx = blockIdx.x * 256 + threadIdx.x;   // 2359296
    if (idx < 262144) g_c[idx] = 0.f;
    g_bhh[idx] = __float2half(0.f);
    g_bhl[idx] = __float2half(0.f);
}

__global__ void __launch_bounds__(256) copy_last(float* __restrict__ out)
{
    int idx = blockIdx.x * 256 + threadIdx.x;
    int inner = idx & 65535;
    int b = idx >> 16;
    out[2097152 + idx] = out[(size_t)b * 16 * CHW2 + 15 * CHW2 + inner];
}

// ---------------------------------------------------------------------------
// Launch sequence (graph-capturable)
// ---------------------------------------------------------------------------
extern "C" void kernel_launch(void* const* d_in, const int* in_sizes, int n_in,
                              void* d_out, int out_size)
{
    const float* x   = (const float*)d_in[0];
    const float* w0  = (const float*)d_in[1];
    const float* b0  = (const float*)d_in[2];
    const float* g0  = (const float*)d_in[3];
    const float* be0 = (const float*)d_in[4];
    const float* m0  = (const float*)d_in[5];
    const float* v0  = (const float*)d_in[6];
    const float* w1  = (const float*)d_in[7];
    const float* b1  = (const float*)d_in[8];
    const float* g1  = (const float*)d_in[9];
    const float* be1 = (const float*)d_in[10];
    const float* m1  = (const float*)d_in[11];
    const float* v1  = (const float*)d_in[12];
    const float* w2  = (const float*)d_in[13];
    const float* b2  = (const float*)d_in[14];
    const float* g2  = (const float*)d_in[15];
    const float* be2 = (const float*)d_in[16];
    const float* m2  = (const float*)d_in[17];
    const float* v2  = (const float*)d_in[18];
    const float* lw0 = (const float*)d_in[19];
    const float* lb0 = (const float*)d_in[20];
    const float* lw1 = (const float*)d_in[21];
    const float* lb1 = (const float*)d_in[22];
    float* out = (float*)d_out;

    static bool attr = false;
    if (!attr) {
        cudaFuncSetAttribute(lstm_mma_pair, cudaFuncAttributeMaxDynamicSharedMemorySize, DSM_BYTES);
        cudaFuncSetAttribute(lstm_xgemm, cudaFuncAttributeMaxDynamicSharedMemorySize, DSM_BYTES);
        cudaFuncSetAttribute(conv_mma<64, 64, 128>, cudaFuncAttributeMaxDynamicSharedMemorySize, DSM_BYTES);
        cudaFuncSetAttribute(conv_mma<128, 32, 256>, cudaFuncAttributeMaxDynamicSharedMemorySize, DSM_BYTES);
        attr = true;
    }

    float* f0ptr;  cudaGetSymbolAddress((void**)&f0ptr, g_f0);
    float* f1ptr;  cudaGetSymbolAddress((void**)&f1ptr, g_f1);
    float* f2ptr;  cudaGetSymbolAddress((void**)&f2ptr, g_f2);
    __half* wc1h; cudaGetSymbolAddress((void**)&wc1h, g_wc1h);
    __half* wc1l; cudaGetSymbolAddress((void**)&wc1l, g_wc1l);
    __half* wc2h; cudaGetSymbolAddress((void**)&wc2h, g_wc2h);
    __half* wc2l; cudaGetSymbolAddress((void**)&wc2l, g_wc2l);

    // weight prepacks
    prepack_w2<<<dim3(1024, 2), 256>>>(lw0, lw1);
    prepack_cw<64, 128><<<288, 256>>>(w1, wc1h, wc1l);
    prepack_cw<128, 256><<<1152, 256>>>(w2, wc2h, wc2l);

    // CNN encoder (pool fused; block0 smem-tiled)
    conv0_pool<<<dim3(16, 32), 256>>>(x, w0, b0, g0, be0, m0, v0);
    conv_mma<64, 64, 128><<<dim3(32, 1, 32), 256, DSM_BYTES>>>(f0ptr, wc1h, wc1l,
                                                               b1, g1, be1, m1, v1, f1ptr);
    conv_mma<128, 32, 256><<<dim3(8, 2, 32), 256, DSM_BYTES>>>(f1ptr, wc2h, wc2l,
                                                               b2, g2, be2, m2, v2, f2ptr);

    // hoisted L0 x-half GEMM for all 32 zx0 slabs (B staged from f2, remapped)
    lstm_xgemm<<<dim3(8, 2, 32), 256, DSM_BYTES>>>();

    // Pipelined ConvLSTM: step k = L0(t=k) h-half + L1(t=k-1) full
    zero_state<<<9216, 256>>>();
    for (int k = 0; k <= 16; k++) {
        lstm_mma_pair<<<dim3(8, 4, 9), 256, DSM_BYTES>>>(k);
        lstm_gates_pair<<<1024, 256>>>(k, lb0, lb1, out);
    }

    copy_last<<<512, 256>>>(out);
}